// round 7
// baseline (speedup 1.0000x reference)
#include <cuda_runtime.h>
#include <math.h>
#include <stdint.h>

#define NB 4
#define NT 2048
#define NH 16
#define ND 64
#define NE 1024
#define NC 64
#define NCHK 32
#define NBH (NB*NH)

// ---------------- scratch (device globals; no runtime allocation) ----------------
__device__ float g_q  [(size_t)NB*NH*NT*ND];
__device__ float g_k  [(size_t)NB*NH*NT*ND];
__device__ float g_v  [(size_t)NB*NH*NT*ND];
__device__ float g_ret[(size_t)NB*NH*NT*ND];
__device__ float g_U  [(size_t)NBH*NCHK*ND*ND];
__device__ float g_S  [(size_t)NBH*NCHK*ND*ND];
__device__ float g_kvc[(size_t)NBH*NCHK*ND*ND];
__device__ float g_W  [(size_t)NBH*NCHK*ND];
__device__ float g_Xn [(size_t)NBH*NCHK*ND];
__device__ float g_stat[(size_t)NBH*NCHK*2];
__device__ float g_norm[NB*2];
__device__ float g_xr [(size_t)NB*NT*NE];    // tf32-rounded X
__device__ float g_wr [(size_t)3*NE*NE];     // tf32-rounded Wq,Wk,Wv

__device__ __forceinline__ unsigned f2tf(float x){
    unsigned r;
    asm("cvt.rna.tf32.f32 %0, %1;" : "=r"(r) : "f"(x));
    return r;
}
__device__ __forceinline__ float tfr(float x){
    return __uint_as_float(f2tf(x));
}
__device__ __forceinline__ void mma8(float c[4], const unsigned a[4], unsigned b0, unsigned b1){
    asm volatile(
      "mma.sync.aligned.m16n8k8.row.col.f32.tf32.tf32.f32 "
      "{%0,%1,%2,%3},{%4,%5,%6,%7},{%8,%9},{%0,%1,%2,%3};"
      : "+f"(c[0]),"+f"(c[1]),"+f"(c[2]),"+f"(c[3])
      : "r"(a[0]),"r"(a[1]),"r"(a[2]),"r"(a[3]), "r"(b0),"r"(b1));
}

#define CP16(dst_u32, src) \
    asm volatile("cp.async.ca.shared.global [%0], [%1], 16;" :: "r"(dst_u32), "l"(src))

// ================= K0: pre-round X and W to tf32 =================
#define NX4 ((NB*NT*NE)/4)       // 2097152
#define NW4 ((NE*NE)/4)          // 262144
__global__ void __launch_bounds__(256) k_cvt(const float* __restrict__ X,
                                             const float* __restrict__ Wq,
                                             const float* __restrict__ Wk,
                                             const float* __restrict__ Wv)
{
    int i = blockIdx.x*256 + threadIdx.x;
    const float4* src;
    float4* dst;
    int off;
    if (i < NX4){
        src = (const float4*)X; dst = (float4*)g_xr; off = i;
    } else {
        int i2 = i - NX4;
        int sel = i2 / NW4; off = i2 - sel*NW4;
        src = (const float4*)((sel==0)?Wq:(sel==1)?Wk:Wv);
        dst = (float4*)(g_wr + (size_t)sel*NE*NE);
    }
    float4 v = src[off];
    v.x=tfr(v.x); v.y=tfr(v.y); v.z=tfr(v.z); v.w=tfr(v.w);
    dst[off] = v;
}

// ================= K1: fused QKV projection (TF32 mma, 128x128, K=32 stages) ===
#define A_STG (128*36)
#define B_STG (32*136)
#define PROJ_SMEM (3*(A_STG+B_STG)*4)
__global__ void __launch_bounds__(256) k_proj3()
{
    const int sel = blockIdx.z;
    const float* X = g_xr;
    const float* W = g_wr + (size_t)sel*NE*NE;
    float* dst = (sel==0)?g_q:(sel==1)?g_k:g_v;

    extern __shared__ float dsm[];
    float* As = dsm;              // 3 stages of 128x36
    float* Bs = dsm + 3*A_STG;    // 3 stages of 32x136

    const int tid = threadIdx.x;
    const int rowBase = blockIdx.y*128, colBase = blockIdx.x*128;
    const int warp = tid>>5, lane = tid&31;
    const int wm = warp&3, wn = warp>>2;
    const int g = lane>>2, t4 = lane&3;

    // A: 128 rows x 32 cols; 2 threads per row, 16 floats each
    const int arow = tid>>1, acol = (tid&1)*16;
    // B: 32 rows x 128 cols; 8 threads per row, 16 floats each
    const int brow = tid>>3, bcol = (tid&7)*16;

    const unsigned sA = (unsigned)__cvta_generic_to_shared(As);
    const unsigned sB = (unsigned)__cvta_generic_to_shared(Bs);
    const unsigned stA = (unsigned)A_STG*4u, stB = (unsigned)B_STG*4u;

    float acc[2][8][4];
#pragma unroll
    for (int a=0;a<2;a++)
#pragma unroll
      for (int b=0;b<8;b++)
#pragma unroll
        for (int c=0;c<4;c++) acc[a][b][c]=0.f;

    auto issue = [&](int it, int st){
        int kb = it*32;
        const float* xs = X + (size_t)(rowBase+arow)*NE + kb + acol;
        unsigned da = sA + st*stA + (unsigned)(arow*36 + acol)*4u;
#pragma unroll
        for (int u=0;u<4;u++) CP16(da + u*16u, xs + u*4);
        const float* ws = W + (size_t)(kb+brow)*NE + colBase + bcol;
        unsigned db = sB + st*stB + (unsigned)(brow*136 + bcol)*4u;
#pragma unroll
        for (int u=0;u<4;u++) CP16(db + u*16u, ws + u*4);
        asm volatile("cp.async.commit_group;" ::: "memory");
    };

    const int NIT = NE/32;   // 32
    issue(0,0); issue(1,1);
    for (int it=0; it<NIT; it++){
        const int st = it%3;
        if (it+1<NIT){
            asm volatile("cp.async.wait_group 1;" ::: "memory");
        } else {
            asm volatile("cp.async.wait_group 0;" ::: "memory");
        }
        __syncthreads();
        if (it+2<NIT) issue(it+2, (it+2)%3);
        const float* Ap = As + st*A_STG;
        const float* Bp = Bs + st*B_STG;
#pragma unroll
        for (int k0=0;k0<32;k0+=8){
            unsigned af[2][4];
#pragma unroll
            for (int mt=0;mt<2;mt++){
                int r0 = wm*32 + mt*16;
                af[mt][0] = __float_as_uint(Ap[(r0+g  )*36 + k0 + t4    ]);
                af[mt][1] = __float_as_uint(Ap[(r0+g+8)*36 + k0 + t4    ]);
                af[mt][2] = __float_as_uint(Ap[(r0+g  )*36 + k0 + t4 + 4]);
                af[mt][3] = __float_as_uint(Ap[(r0+g+8)*36 + k0 + t4 + 4]);
            }
#pragma unroll
            for (int nt=0;nt<8;nt++){
                int c0 = wn*64 + nt*8;
                unsigned b0 = __float_as_uint(Bp[(k0+t4  )*136 + c0 + g]);
                unsigned b1 = __float_as_uint(Bp[(k0+t4+4)*136 + c0 + g]);
#pragma unroll
                for (int mt=0;mt<2;mt++){
                    mma8(acc[mt][nt], af[mt], b0, b1);
                }
            }
        }
    }
#pragma unroll
    for (int mt=0;mt<2;mt++)
#pragma unroll
    for (int nt=0;nt<8;nt++){
        int row = rowBase + wm*32 + mt*16 + g;
        int col = colBase + wn*64 + nt*8 + t4*2;
        int b_ = row>>11, t_ = row&2047, h_ = col>>6, d_ = col&63;
        float* p0 = dst + (((size_t)(b_*NH+h_))*NT + t_)*ND + d_;
        *(float2*)p0 = make_float2(acc[mt][nt][0], acc[mt][nt][1]);
        int t2_ = (row+8)&2047;
        float* p1 = dst + (((size_t)(b_*NH+h_))*NT + t2_)*ND + d_;
        *(float2*)p1 = make_float2(acc[mt][nt][2], acc[mt][nt][3]);
    }
}

// ================= K2: per-chunk U_j, KV_j (tensor core, frag reuse), W_j =========
#define P1_SMEM ((4352 + 2*4608)*4)
__global__ void __launch_bounds__(256) k_pass1(const float* __restrict__ pkv)
{
    extern __shared__ float sm1[];
    float* bKT = sm1;          // 64x68 : K^T [d][i], tf32
    float* bV  = sm1 + 4352;   // 64x72 : V  [i][e], tf32 (later Q raw)
    float* bVw = sm1 + 4352 + 4608; // 64x72 : gamma^{63-i} V, tf32
    __shared__ float gp[65];
    __shared__ float red[4*64];
    __shared__ float qw[64];
    int tid=threadIdx.x, bid=blockIdx.x;
    int j=bid&31, bh=bid>>5, h=bh&15;
    size_t base = ((size_t)bh*NT + (size_t)j*NC)*ND;
    if (tid<=64){
        double gd = 1.0 - exp2(-5.0-(double)h);
        gp[tid]=(float)pow(gd,(double)tid);
    }
    __syncthreads();
#pragma unroll
    for (int l=0;l<4;l++){
        int idx = tid + l*256;
        int i=idx>>4, d4=(idx&15)*4;
        float4 k4 = *(const float4*)(g_k + base + (size_t)idx*4);
        bKT[(d4  )*68+i]=tfr(k4.x);
        bKT[(d4+1)*68+i]=tfr(k4.y);
        bKT[(d4+2)*68+i]=tfr(k4.z);
        bKT[(d4+3)*68+i]=tfr(k4.w);
        float4 v4 = *(const float4*)(g_v + base + (size_t)idx*4);
        bV[i*72+d4  ]=tfr(v4.x);
        bV[i*72+d4+1]=tfr(v4.y);
        bV[i*72+d4+2]=tfr(v4.z);
        bV[i*72+d4+3]=tfr(v4.w);
        float w = gp[63-i];
        bVw[i*72+d4  ]=tfr(v4.x*w);
        bVw[i*72+d4+1]=tfr(v4.y*w);
        bVw[i*72+d4+2]=tfr(v4.z*w);
        bVw[i*72+d4+3]=tfr(v4.w*w);
    }
    __syncthreads();
    const int warp=tid>>5, lane=tid&31;
    const int wm=warp&3, wn=warp>>2, g=lane>>2, t4=lane&3;
    const int m0=wm*16;
    const int r0=m0+g, r1=r0+8;

    unsigned ka[8][4];
#pragma unroll
    for (int k8=0;k8<8;k8++){
        int k=k8*8;
        ka[k8][0]=__float_as_uint(bKT[(m0+g  )*68 + k+t4  ]);
        ka[k8][1]=__float_as_uint(bKT[(m0+g+8)*68 + k+t4  ]);
        ka[k8][2]=__float_as_uint(bKT[(m0+g  )*68 + k+t4+4]);
        ka[k8][3]=__float_as_uint(bKT[(m0+g+8)*68 + k+t4+4]);
    }

    float accKV[4][4]={}, accU[4][4]={};
#pragma unroll
    for (int k8=0;k8<8;k8++){
#pragma unroll
        for (int nt=0;nt<4;nt++){
            int cb=wn*32+nt*8;
            unsigned b0=__float_as_uint(bV [(k8*8+t4  )*72 + cb+g]);
            unsigned b1=__float_as_uint(bV [(k8*8+t4+4)*72 + cb+g]);
            mma8(accKV[nt], ka[k8], b0, b1);
            unsigned c0=__float_as_uint(bVw[(k8*8+t4  )*72 + cb+g]);
            unsigned c1=__float_as_uint(bVw[(k8*8+t4+4)*72 + cb+g]);
            mma8(accU[nt], ka[k8], c0, c1);
        }
    }
    {
        float* Kp = g_kvc + (size_t)bid*4096;
        float* Up = g_U  + (size_t)bid*4096;
#pragma unroll
        for (int nt=0;nt<4;nt++){
            int c0=wn*32+nt*8+t4*2;
            *(float2*)(Kp + r0*64 + c0) = make_float2(accKV[nt][0],accKV[nt][1]);
            *(float2*)(Kp + r1*64 + c0) = make_float2(accKV[nt][2],accKV[nt][3]);
            *(float2*)(Up + r0*64 + c0) = make_float2(accU[nt][0],accU[nt][1]);
            *(float2*)(Up + r1*64 + c0) = make_float2(accU[nt][2],accU[nt][3]);
        }
    }
    __syncthreads();
#pragma unroll
    for (int l=0;l<4;l++){
        int idx=tid+l*256;
        *(float4*)(bV + (idx>>4)*72 + (idx&15)*4) =
            *(const float4*)(g_q + base + (size_t)idx*4);
    }
    __syncthreads();
    int rr = tid>>6, d = tid&63;
    float s = 0.f;
#pragma unroll
    for (int i=rr*16;i<rr*16+16;i++) s += gp[i]*bV[i*72 + d];
    red[rr*64 + d] = s;
    __syncthreads();
    if (tid<64) qw[tid] = red[tid] + red[64+tid] + red[128+tid] + red[192+tid];
    __syncthreads();
    const float* A = pkv + (size_t)h*4096;
    float s2 = 0.f;
#pragma unroll
    for (int dd=rr*16; dd<rr*16+16; dd++) s2 += qw[dd]*A[dd*64 + d];
    red[rr*64 + d] = s2;
    __syncthreads();
    if (tid<64) g_W[(size_t)bid*64 + tid] = red[tid] + red[64+tid] + red[128+tid] + red[192+tid];
}

// ================= K3: chunk scans (wide grid, prefetched) =========
__global__ void __launch_bounds__(256) k_scan()
{
    int bh = blockIdx.x, part = blockIdx.y, tid = threadIdx.x;
    int h = bh&15;
    double gd = 1.0 - exp2(-5.0-(double)h);
    float g64 = (float)pow(gd,64.0);
    int idx = part*256 + tid;               // 0..4095
    size_t o = (size_t)bh*NCHK*4096 + idx;
    float S = 0.f;
    float u = g_U[o];
    for (int j=0;j<NCHK;j++){
        float un = (j+1<NCHK) ? g_U[o + (size_t)(j+1)*4096] : 0.f;
        g_S[o + (size_t)j*4096] = S;
        S = g64*S + u;
        u = un;
    }
    if (part==0 && tid<64){
        float X=0.f;
        size_t ob = (size_t)bh*NCHK*64 + tid;
        float w = g_W[ob + (size_t)(NCHK-1)*64];
        for (int j=NCHK-1;j>=0;--j){
            float wn = (j>0) ? g_W[ob + (size_t)(j-1)*64] : 0.f;
            g_Xn[ob + (size_t)j*64] = X;
            X = g64*X + w;
            w = wn;
        }
    }
}

// ================= K4: per-chunk finalize (tensor core, frag reuse) =================
#define P3_SMEM ((4352 + 4*4608)*4)
__global__ void __launch_bounds__(256) k_pass3(const float* __restrict__ pkv)
{
    extern __shared__ float sm3[];
    float* bQ = sm3;                  // 64x68 : Q [i][d] tf32 -> P tf32
    float* bK = sm3 + 4352;           // 64x72 : K^T [d][s] tf32 -> scan buffer
    float* bS = sm3 + 4352 + 4608;    // 64x72 : S raw fp32
    float* bA = sm3 + 4352 + 2*4608;  // 64x72 : past_kv raw
    float* bV = sm3 + 4352 + 3*4608;  // 64x72 : V raw
    __shared__ float gp[65];
    __shared__ float Xs[64];
    __shared__ float carry[4*64];
    __shared__ float redS[8], redQ[8];
    int tid=threadIdx.x, bid=blockIdx.x;
    int j=bid&31, bh=bid>>5, h=bh&15;
    size_t base=((size_t)bh*NT+(size_t)j*NC)*ND;

    {
        const unsigned sb = (unsigned)__cvta_generic_to_shared(sm3);
        const float* Ssrc = g_S + ((size_t)bh*NCHK+j)*4096;
        const float* Asrc = pkv + (size_t)h*4096;
        const float* Vsrc = g_v + base;
#pragma unroll
        for (int l=0;l<4;l++){
            int idx=tid+l*256;
            unsigned o = (unsigned)((idx>>4)*72 + (idx&15)*4)*4u;
            CP16(sb + (4352u+  4608u)*4u + o, Ssrc + (size_t)idx*4);
            CP16(sb + (4352u+2*4608u)*4u + o, Asrc + (size_t)idx*4);
            CP16(sb + (4352u+3*4608u)*4u + o, Vsrc + (size_t)idx*4);
        }
        asm volatile("cp.async.commit_group;" ::: "memory");
    }
    if (tid<=64){
        double gd = 1.0 - exp2(-5.0-(double)h);
        gp[tid]=(float)pow(gd,(double)tid);
    }
    if (tid<64) Xs[tid] = g_Xn[((size_t)bh*NCHK+j)*64 + tid];
#pragma unroll
    for (int l=0;l<4;l++){
        int idx=tid+l*256;
        int i=idx>>4, d4=(idx&15)*4;
        float4 q4 = *(const float4*)(g_q + base + (size_t)idx*4);
        bQ[i*68+d4  ]=tfr(q4.x);
        bQ[i*68+d4+1]=tfr(q4.y);
        bQ[i*68+d4+2]=tfr(q4.z);
        bQ[i*68+d4+3]=tfr(q4.w);
        float4 k4 = *(const float4*)(g_k + base + (size_t)idx*4);
        bK[(d4  )*72+i]=tfr(k4.x);
        bK[(d4+1)*72+i]=tfr(k4.y);
        bK[(d4+2)*72+i]=tfr(k4.z);
        bK[(d4+3)*72+i]=tfr(k4.w);
    }
    __syncthreads();
    const int warp=tid>>5, lane=tid&31;
    const int wm=warp&3, wn=warp>>2, g=lane>>2, t4=lane&3;
    const int m0=wm*16;
    const int r0=m0+g, r1=r0+8;

    unsigned qa[8][4];
#pragma unroll
    for (int k8=0;k8<8;k8++){
        int k=k8*8;
        qa[k8][0]=__float_as_uint(bQ[(m0+g  )*68 + k+t4  ]);
        qa[k8][1]=__float_as_uint(bQ[(m0+g+8)*68 + k+t4  ]);
        qa[k8][2]=__float_as_uint(bQ[(m0+g  )*68 + k+t4+4]);
        qa[k8][3]=__float_as_uint(bQ[(m0+g+8)*68 + k+t4+4]);
    }
    float accP[4][4]={};
#pragma unroll
    for (int k8=0;k8<8;k8++){
#pragma unroll
        for (int nt=0;nt<4;nt++){
            int cb=wn*32+nt*8;
            unsigned b0=__float_as_uint(bK[(k8*8+t4  )*72 + cb+g]);
            unsigned b1=__float_as_uint(bK[(k8*8+t4+4)*72 + cb+g]);
            mma8(accP[nt], qa[k8], b0, b1);
        }
    }
    asm volatile("cp.async.wait_group 0;" ::: "memory");
    __syncthreads();
    float accQ[4][4]={}, accPP[4][4]={};
#pragma unroll
    for (int k8=0;k8<8;k8++){
#pragma unroll
        for (int nt=0;nt<4;nt++){
            int cb=wn*32+nt*8;
            unsigned b0=f2tf(bS[(k8*8+t4  )*72 + cb+g]);
            unsigned b1=f2tf(bS[(k8*8+t4+4)*72 + cb+g]);
            mma8(accQ[nt], qa[k8], b0, b1);
            unsigned c0=f2tf(bA[(k8*8+t4  )*72 + cb+g]);
            unsigned c1=f2tf(bA[(k8*8+t4+4)*72 + cb+g]);
            mma8(accPP[nt], qa[k8], c0, c1);
        }
    }
#pragma unroll
    for (int nt=0;nt<4;nt++){
        int c0=wn*32+nt*8+t4*2;
        int d00=r0-c0, d01=d00-1, d10=r1-c0, d11=d10-1;
        float p00 = (d00>=0)? accP[nt][0]*gp[d00] : 0.f;
        float p01 = (d01>=0)? accP[nt][1]*gp[d01] : 0.f;
        float p10 = (d10>=0)? accP[nt][2]*gp[d10] : 0.f;
        float p11 = (d11>=0)? accP[nt][3]*gp[d11] : 0.f;
        bQ[r0*68+c0  ]=tfr(p00);
        bQ[r0*68+c0+1]=tfr(p01);
        bQ[r1*68+c0  ]=tfr(p10);
        bQ[r1*68+c0+1]=tfr(p11);
        *(float2*)(bK + r0*72 + c0) = make_float2(accPP[nt][0],accPP[nt][1]);
        *(float2*)(bK + r1*72 + c0) = make_float2(accPP[nt][2],accPP[nt][3]);
        float gq0=gp[r0+1], gq1=gp[r1+1];
        accQ[nt][0]*=gq0; accQ[nt][1]*=gq0;
        accQ[nt][2]*=gq1; accQ[nt][3]*=gq1;
    }
    __syncthreads();
#pragma unroll
    for (int k8=0;k8<8;k8++){
        int k=k8*8;
        unsigned pa[4];
        pa[0]=__float_as_uint(bQ[(m0+g  )*68 + k+t4  ]);
        pa[1]=__float_as_uint(bQ[(m0+g+8)*68 + k+t4  ]);
        pa[2]=__float_as_uint(bQ[(m0+g  )*68 + k+t4+4]);
        pa[3]=__float_as_uint(bQ[(m0+g+8)*68 + k+t4+4]);
#pragma unroll
        for (int nt=0;nt<4;nt++){
            int cb=wn*32+nt*8;
            unsigned b0=f2tf(bV[(k+t4  )*72 + cb+g]);
            unsigned b1=f2tf(bV[(k+t4+4)*72 + cb+g]);
            mma8(accQ[nt], pa, b0, b1);
        }
    }
    {
        int e = tid&63, q = tid>>6;
        float g1 = gp[1];
        float loc[16];
        float c = 0.f;
#pragma unroll
        for (int i=15;i>=0;--i){
            c = bK[(q*16+i)*72 + e] + g1*c;
            loc[i] = c;
        }
        carry[q*64+e] = loc[0];
        __syncthreads();
        float F = 0.f;
        if (q<3) F  = carry[(q+1)*64+e];
        if (q<2) F += gp[16]*carry[(q+2)*64+e];
        if (q<1) F += gp[32]*carry[(q+3)*64+e];
#pragma unroll
        for (int i=0;i<16;i++){
            bK[(q*16+i)*72 + e] = loc[i] + gp[16-i]*F;
        }
    }
    __syncthreads();
    float s1=0.f, s2=0.f;
    float gx0=gp[64-r0], gx1=gp[64-r1];
#pragma unroll
    for (int nt=0;nt<4;nt++){
        int c0=wn*32+nt*8+t4*2;
        float v00 = accQ[nt][0] + bK[r0*72+c0  ] + gx0*Xs[c0  ];
        float v01 = accQ[nt][1] + bK[r0*72+c0+1] + gx0*Xs[c0+1];
        float v10 = accQ[nt][2] + bK[r1*72+c0  ] + gx1*Xs[c0  ];
        float v11 = accQ[nt][3] + bK[r1*72+c0+1] + gx1*Xs[c0+1];
        s1 += v00+v01+v10+v11;
        s2 += v00*v00+v01*v01+v10*v10+v11*v11;
        *(float2*)(g_ret + base + (size_t)r0*64 + c0) = make_float2(v00,v01);
        *(float2*)(g_ret + base + (size_t)r1*64 + c0) = make_float2(v10,v11);
    }
#pragma unroll
    for (int o=16;o>0;o>>=1){
        s1 += __shfl_down_sync(0xffffffffu, s1, o);
        s2 += __shfl_down_sync(0xffffffffu, s2, o);
    }
    if (lane==0){ redS[warp]=s1; redQ[warp]=s2; }
    __syncthreads();
    if (tid==0){
        float a=0.f,bq=0.f;
#pragma unroll
        for (int w=0;w<8;w++){ a+=redS[w]; bq+=redQ[w]; }
        g_stat[(size_t)bid*2  ]=a;
        g_stat[(size_t)bid*2+1]=bq;
    }
}

// ================= K5: per-batch GroupNorm stats =================
__global__ void __launch_bounds__(512) k_stats()
{
    __shared__ float r1[512], r2[512];
    int b=blockIdx.x, tid=threadIdx.x;
    r1[tid]=g_stat[(size_t)(b*512+tid)*2];
    r2[tid]=g_stat[(size_t)(b*512+tid)*2+1];
    __syncthreads();
    for (int o=256;o>0;o>>=1){
        if (tid<o){ r1[tid]+=r1[tid+o]; r2[tid]+=r2[tid+o]; }
        __syncthreads();
    }
    if (tid==0){
        const float N = (float)((size_t)NH*NT*ND);
        float mu = r1[0]/N;
        float var = r2[0]/N - mu*mu;
        g_norm[b*2]=mu;
        g_norm[b*2+1]=rsqrtf(var+1e-5f);
    }
}

// ================= K6: normalize + layout to [B,T,NE] =================
__global__ void __launch_bounds__(256) k_out(const float* __restrict__ gnw,
                                             const float* __restrict__ gnb,
                                             float* __restrict__ out)
{
    int bid=blockIdx.x;
    int b=bid>>11, t=bid&2047;
    int tid=threadIdx.x;
    int h=tid>>4, d4=(tid&15)*4;
    float mu=g_norm[b*2], rs=g_norm[b*2+1];
    float w = gnw[h]*rs;
    float bb = gnb[h] - mu*w;
    float4 xv = *(const float4*)(g_ret + (((size_t)(b*NH+h))*NT + t)*ND + d4);
    float4 yv = make_float4(xv.x*w+bb, xv.y*w+bb, xv.z*w+bb, xv.w*w+bb);
    *(float4*)(out + (size_t)bid*NE + h*ND + d4) = yv;
}

// ================= K7: kv reduce + decay =================
__global__ void __launch_bounds__(256) k_kvout(const float* __restrict__ pkv,
                                               float* __restrict__ out_kv)
{
    int h=blockIdx.x;
    int idx=blockIdx.y*256+threadIdx.x;
    float s=0.f;
    for (int b=0;b<NB;b++){
        size_t bh=((size_t)(b*NH+h))*NCHK;
        for (int j2=0;j2<NCHK;j2++) s += g_kvc[(bh+j2)*4096 + idx];
    }
    double gd = 1.0 - exp2(-5.0-(double)h);
    out_kv[(size_t)h*4096 + idx] = (float)gd*pkv[(size_t)h*4096 + idx] + 0.25f*s;
}

extern "C" void kernel_launch(void* const* d_in, const int* in_sizes, int n_in,
                              void* d_out, int out_size)
{
    const float* x   = (const float*)d_in[0];
    const float* pkv = (const float*)d_in[1];
    const float* Wq  = (const float*)d_in[2];
    const float* Wk  = (const float*)d_in[3];
    const float* Wv  = (const float*)d_in[4];
    const float* gnw = (const float*)d_in[5];
    const float* gnb = (const float*)d_in[6];
    float* out = (float*)d_out;

    cudaFuncSetAttribute(k_proj3, cudaFuncAttributeMaxDynamicSharedMemorySize, PROJ_SMEM);
    cudaFuncSetAttribute(k_pass1, cudaFuncAttributeMaxDynamicSharedMemorySize, P1_SMEM);
    cudaFuncSetAttribute(k_pass3, cudaFuncAttributeMaxDynamicSharedMemorySize, P3_SMEM);

    k_cvt<<<(NX4 + 3*NW4)/256, 256>>>(x, Wq, Wk, Wv);
    dim3 gproj(8, 64, 3);
    k_proj3<<<gproj, 256, PROJ_SMEM>>>();
    k_pass1<<<NBH*NCHK, 256, P1_SMEM>>>(pkv);
    dim3 gscan(NBH, 16);
    k_scan<<<gscan, 256>>>();
    k_pass3<<<NBH*NCHK, 256, P3_SMEM>>>(pkv);
    k_stats<<<NB, 512>>>();
    k_out<<<NB*NT, 256>>>(gnw, gnb, out);
    dim3 gkv(NH, 16);
    k_kvout<<<gkv, 256>>>(pkv, out + (size_t)NB*NT*NE);
}

// round 8
// speedup vs baseline: 1.2376x; 1.2376x over previous
#include <cuda_runtime.h>
#include <math.h>
#include <stdint.h>

#define NB 4
#define NT 2048
#define NH 16
#define ND 64
#define NE 1024
#define NC 64
#define NCHK 32
#define NBH (NB*NH)

// ---------------- scratch (device globals; no runtime allocation) ----------------
__device__ float g_q  [(size_t)NB*NH*NT*ND];
__device__ float g_k  [(size_t)NB*NH*NT*ND];
__device__ float g_v  [(size_t)NB*NH*NT*ND];
__device__ float g_ret[(size_t)NB*NH*NT*ND];
__device__ float g_U  [(size_t)NBH*NCHK*ND*ND];
__device__ float g_S  [(size_t)NBH*NCHK*ND*ND];
__device__ float g_kvc[(size_t)NBH*NCHK*ND*ND];
__device__ float g_W  [(size_t)NBH*NCHK*ND];
__device__ float g_Xn [(size_t)NBH*NCHK*ND];
__device__ float g_stat[(size_t)NBH*NCHK*2];
__device__ float g_norm[NB*2];
__device__ float g_xr [(size_t)NB*NT*NE];    // tf32-rounded X
__device__ float g_wr [(size_t)3*NE*NE];     // tf32-rounded Wq,Wk,Wv

__device__ __forceinline__ unsigned f2tf(float x){
    unsigned r;
    asm("cvt.rna.tf32.f32 %0, %1;" : "=r"(r) : "f"(x));
    return r;
}
__device__ __forceinline__ float tfr(float x){
    return __uint_as_float(f2tf(x));
}
__device__ __forceinline__ void mma8(float c[4], const unsigned a[4], unsigned b0, unsigned b1){
    asm volatile(
      "mma.sync.aligned.m16n8k8.row.col.f32.tf32.tf32.f32 "
      "{%0,%1,%2,%3},{%4,%5,%6,%7},{%8,%9},{%0,%1,%2,%3};"
      : "+f"(c[0]),"+f"(c[1]),"+f"(c[2]),"+f"(c[3])
      : "r"(a[0]),"r"(a[1]),"r"(a[2]),"r"(a[3]), "r"(b0),"r"(b1));
}

#define CP16(dst_u32, src) \
    asm volatile("cp.async.ca.shared.global [%0], [%1], 16;" :: "r"(dst_u32), "l"(src))

// ================= K0: pre-round X and W to tf32 =================
#define NX4 ((NB*NT*NE)/4)       // 2097152
#define NW4 ((NE*NE)/4)          // 262144
__global__ void __launch_bounds__(256) k_cvt(const float* __restrict__ X,
                                             const float* __restrict__ Wq,
                                             const float* __restrict__ Wk,
                                             const float* __restrict__ Wv)
{
    int i = blockIdx.x*256 + threadIdx.x;
    const float4* src;
    float4* dst;
    int off;
    if (i < NX4){
        src = (const float4*)X; dst = (float4*)g_xr; off = i;
    } else {
        int i2 = i - NX4;
        int sel = i2 / NW4; off = i2 - sel*NW4;
        src = (const float4*)((sel==0)?Wq:(sel==1)?Wk:Wv);
        dst = (float4*)(g_wr + (size_t)sel*NE*NE);
    }
    float4 v = src[off];
    v.x=tfr(v.x); v.y=tfr(v.y); v.z=tfr(v.z); v.w=tfr(v.w);
    dst[off] = v;
}

// ================= K1: fused QKV projection (TF32 mma, 128x128, 3-stage) ===
#define PROJ_SMEM (3*(2560+2176)*4)
__global__ void __launch_bounds__(256) k_proj3()
{
    const int sel = blockIdx.z;
    const float* X = g_xr;
    const float* W = g_wr + (size_t)sel*NE*NE;
    float* dst = (sel==0)?g_q:(sel==1)?g_k:g_v;

    extern __shared__ float dsm[];
    float* As = dsm;            // 3 stages of 128*20
    float* Bs = dsm + 3*2560;   // 3 stages of 16*136

    const int tid = threadIdx.x;
    const int rowBase = blockIdx.y*128, colBase = blockIdx.x*128;
    const int warp = tid>>5, lane = tid&31;
    const int wm = warp&3, wn = warp>>2;
    const int g = lane>>2, t4 = lane&3;

    const int ar0 = tid>>2, ac0 = (tid&3)*4;
    const int br0 = tid>>5, bc0 = (tid&31)*4;

    const unsigned sA = (unsigned)__cvta_generic_to_shared(As);
    const unsigned sB = (unsigned)__cvta_generic_to_shared(Bs);
    const unsigned stA = 2560u*4u, stB = 2176u*4u;

    float acc[2][8][4];
#pragma unroll
    for (int a=0;a<2;a++)
#pragma unroll
      for (int b=0;b<8;b++)
#pragma unroll
        for (int c=0;c<4;c++) acc[a][b][c]=0.f;

    auto issue = [&](int it, int st){
        int kb = it*16;
        const float* xs = X + (size_t)rowBase*NE + kb;
        CP16(sA + st*stA + (unsigned)((ar0    )*20 + ac0)*4u, xs + (size_t)(ar0    )*NE + ac0);
        CP16(sA + st*stA + (unsigned)((ar0+64 )*20 + ac0)*4u, xs + (size_t)(ar0+64 )*NE + ac0);
        const float* ws = W + (size_t)kb*NE + colBase;
        CP16(sB + st*stB + (unsigned)((br0   )*136 + bc0)*4u, ws + (size_t)(br0   )*NE + bc0);
        CP16(sB + st*stB + (unsigned)((br0+8 )*136 + bc0)*4u, ws + (size_t)(br0+8 )*NE + bc0);
        asm volatile("cp.async.commit_group;" ::: "memory");
    };

    const int NIT = NE/16;
    issue(0,0); issue(1,1);
    for (int it=0; it<NIT; it++){
        const int st = it%3;
        if (it+2<NIT){
            issue(it+2, (it+2)%3);
            asm volatile("cp.async.wait_group 2;" ::: "memory");
        } else if (it+1<NIT){
            asm volatile("cp.async.wait_group 1;" ::: "memory");
        } else {
            asm volatile("cp.async.wait_group 0;" ::: "memory");
        }
        __syncthreads();
        const float* Ap = As + st*2560;
        const float* Bp = Bs + st*2176;
#pragma unroll
        for (int k0=0;k0<16;k0+=8){
            unsigned af[2][4];
#pragma unroll
            for (int mt=0;mt<2;mt++){
                int r0 = wm*32 + mt*16;
                af[mt][0] = __float_as_uint(Ap[(r0+g  )*20 + k0 + t4    ]);
                af[mt][1] = __float_as_uint(Ap[(r0+g+8)*20 + k0 + t4    ]);
                af[mt][2] = __float_as_uint(Ap[(r0+g  )*20 + k0 + t4 + 4]);
                af[mt][3] = __float_as_uint(Ap[(r0+g+8)*20 + k0 + t4 + 4]);
            }
#pragma unroll
            for (int nt=0;nt<8;nt++){
                int c0 = wn*64 + nt*8;
                unsigned b0 = __float_as_uint(Bp[(k0+t4  )*136 + c0 + g]);
                unsigned b1 = __float_as_uint(Bp[(k0+t4+4)*136 + c0 + g]);
#pragma unroll
                for (int mt=0;mt<2;mt++){
                    mma8(acc[mt][nt], af[mt], b0, b1);
                }
            }
        }
        __syncthreads();
    }
#pragma unroll
    for (int mt=0;mt<2;mt++)
#pragma unroll
    for (int nt=0;nt<8;nt++){
        int row = rowBase + wm*32 + mt*16 + g;
        int col = colBase + wn*64 + nt*8 + t4*2;
        int b_ = row>>11, t_ = row&2047, h_ = col>>6, d_ = col&63;
        float* p0 = dst + (((size_t)(b_*NH+h_))*NT + t_)*ND + d_;
        *(float2*)p0 = make_float2(acc[mt][nt][0], acc[mt][nt][1]);
        int t2_ = (row+8)&2047;
        float* p1 = dst + (((size_t)(b_*NH+h_))*NT + t2_)*ND + d_;
        *(float2*)p1 = make_float2(acc[mt][nt][2], acc[mt][nt][3]);
    }
}

// ================= K2: per-chunk U_j, KV_j (tensor core, frag reuse), W_j =========
#define P1_SMEM ((4352 + 2*4608)*4)
__global__ void __launch_bounds__(256) k_pass1(const float* __restrict__ pkv)
{
    extern __shared__ float sm1[];
    float* bKT = sm1;          // 64x68 : K^T [d][i], tf32
    float* bV  = sm1 + 4352;   // 64x72 : V  [i][e], tf32 (later Q raw)
    float* bVw = sm1 + 4352 + 4608; // 64x72 : gamma^{63-i} V, tf32
    __shared__ float gp[65];
    __shared__ float red[4*64];
    __shared__ float qw[64];
    int tid=threadIdx.x, bid=blockIdx.x;
    int j=bid&31, bh=bid>>5, h=bh&15;
    size_t base = ((size_t)bh*NT + (size_t)j*NC)*ND;
    if (tid<=64){
        double gd = 1.0 - exp2(-5.0-(double)h);
        gp[tid]=(float)pow(gd,(double)tid);
    }
    __syncthreads();
#pragma unroll
    for (int l=0;l<4;l++){
        int idx = tid + l*256;
        int i=idx>>4, d4=(idx&15)*4;
        float4 k4 = *(const float4*)(g_k + base + (size_t)idx*4);
        bKT[(d4  )*68+i]=tfr(k4.x);
        bKT[(d4+1)*68+i]=tfr(k4.y);
        bKT[(d4+2)*68+i]=tfr(k4.z);
        bKT[(d4+3)*68+i]=tfr(k4.w);
        float4 v4 = *(const float4*)(g_v + base + (size_t)idx*4);
        bV[i*72+d4  ]=tfr(v4.x);
        bV[i*72+d4+1]=tfr(v4.y);
        bV[i*72+d4+2]=tfr(v4.z);
        bV[i*72+d4+3]=tfr(v4.w);
        float w = gp[63-i];
        bVw[i*72+d4  ]=tfr(v4.x*w);
        bVw[i*72+d4+1]=tfr(v4.y*w);
        bVw[i*72+d4+2]=tfr(v4.z*w);
        bVw[i*72+d4+3]=tfr(v4.w*w);
    }
    __syncthreads();
    const int warp=tid>>5, lane=tid&31;
    const int wm=warp&3, wn=warp>>2, g=lane>>2, t4=lane&3;
    const int m0=wm*16;
    const int r0=m0+g, r1=r0+8;

    unsigned ka[8][4];
#pragma unroll
    for (int k8=0;k8<8;k8++){
        int k=k8*8;
        ka[k8][0]=__float_as_uint(bKT[(m0+g  )*68 + k+t4  ]);
        ka[k8][1]=__float_as_uint(bKT[(m0+g+8)*68 + k+t4  ]);
        ka[k8][2]=__float_as_uint(bKT[(m0+g  )*68 + k+t4+4]);
        ka[k8][3]=__float_as_uint(bKT[(m0+g+8)*68 + k+t4+4]);
    }

    float accKV[4][4]={}, accU[4][4]={};
#pragma unroll
    for (int k8=0;k8<8;k8++){
#pragma unroll
        for (int nt=0;nt<4;nt++){
            int cb=wn*32+nt*8;
            unsigned b0=__float_as_uint(bV [(k8*8+t4  )*72 + cb+g]);
            unsigned b1=__float_as_uint(bV [(k8*8+t4+4)*72 + cb+g]);
            mma8(accKV[nt], ka[k8], b0, b1);
            unsigned c0=__float_as_uint(bVw[(k8*8+t4  )*72 + cb+g]);
            unsigned c1=__float_as_uint(bVw[(k8*8+t4+4)*72 + cb+g]);
            mma8(accU[nt], ka[k8], c0, c1);
        }
    }
    {
        float* Kp = g_kvc + (size_t)bid*4096;
        float* Up = g_U  + (size_t)bid*4096;
#pragma unroll
        for (int nt=0;nt<4;nt++){
            int c0=wn*32+nt*8+t4*2;
            *(float2*)(Kp + r0*64 + c0) = make_float2(accKV[nt][0],accKV[nt][1]);
            *(float2*)(Kp + r1*64 + c0) = make_float2(accKV[nt][2],accKV[nt][3]);
            *(float2*)(Up + r0*64 + c0) = make_float2(accU[nt][0],accU[nt][1]);
            *(float2*)(Up + r1*64 + c0) = make_float2(accU[nt][2],accU[nt][3]);
        }
    }
    __syncthreads();
#pragma unroll
    for (int l=0;l<4;l++){
        int idx=tid+l*256;
        *(float4*)(bV + (idx>>4)*72 + (idx&15)*4) =
            *(const float4*)(g_q + base + (size_t)idx*4);
    }
    __syncthreads();
    int rr = tid>>6, d = tid&63;
    float s = 0.f;
#pragma unroll
    for (int i=rr*16;i<rr*16+16;i++) s += gp[i]*bV[i*72 + d];
    red[rr*64 + d] = s;
    __syncthreads();
    if (tid<64) qw[tid] = red[tid] + red[64+tid] + red[128+tid] + red[192+tid];
    __syncthreads();
    const float* A = pkv + (size_t)h*4096;
    float s2 = 0.f;
#pragma unroll
    for (int dd=rr*16; dd<rr*16+16; dd++) s2 += qw[dd]*A[dd*64 + d];
    red[rr*64 + d] = s2;
    __syncthreads();
    if (tid<64) g_W[(size_t)bid*64 + tid] = red[tid] + red[64+tid] + red[128+tid] + red[192+tid];
}

// ================= K3: chunk scans (all-register, MLP=32) =========
__global__ void __launch_bounds__(256) k_scan()
{
    int bh = blockIdx.x, part = blockIdx.y, tid = threadIdx.x;
    int h = bh&15;
    double gd = 1.0 - exp2(-5.0-(double)h);
    float g64 = (float)pow(gd,64.0);
    int idx = part*256 + tid;               // 0..4095
    size_t o = (size_t)bh*NCHK*4096 + idx;
    float u[NCHK];
#pragma unroll
    for (int j=0;j<NCHK;j++) u[j] = g_U[o + (size_t)j*4096];
    float S = 0.f;
#pragma unroll
    for (int j=0;j<NCHK;j++){
        g_S[o + (size_t)j*4096] = S;
        S = g64*S + u[j];
    }
    if (part==0 && tid<64){
        size_t ob = (size_t)bh*NCHK*64 + tid;
        float w[NCHK];
#pragma unroll
        for (int j=0;j<NCHK;j++) w[j] = g_W[ob + (size_t)j*64];
        float X=0.f;
#pragma unroll
        for (int j=NCHK-1;j>=0;--j){
            g_Xn[ob + (size_t)j*64] = X;
            X = g64*X + w[j];
        }
    }
}

// ================= K4: per-chunk finalize (tensor core, frag reuse) =================
#define P3_SMEM ((4352 + 4*4608)*4)
__global__ void __launch_bounds__(256) k_pass3(const float* __restrict__ pkv)
{
    extern __shared__ float sm3[];
    float* bQ = sm3;                  // 64x68 : Q [i][d] tf32 -> P tf32
    float* bK = sm3 + 4352;           // 64x72 : K^T [d][s] tf32 -> scan buffer
    float* bS = sm3 + 4352 + 4608;    // 64x72 : S raw fp32
    float* bA = sm3 + 4352 + 2*4608;  // 64x72 : past_kv raw
    float* bV = sm3 + 4352 + 3*4608;  // 64x72 : V raw
    __shared__ float gp[65];
    __shared__ float Xs[64];
    __shared__ float carry[4*64];
    __shared__ float redS[8], redQ[8];
    int tid=threadIdx.x, bid=blockIdx.x;
    int j=bid&31, bh=bid>>5, h=bh&15;
    size_t base=((size_t)bh*NT+(size_t)j*NC)*ND;

    {
        const unsigned sb = (unsigned)__cvta_generic_to_shared(sm3);
        const float* Ssrc = g_S + ((size_t)bh*NCHK+j)*4096;
        const float* Asrc = pkv + (size_t)h*4096;
        const float* Vsrc = g_v + base;
#pragma unroll
        for (int l=0;l<4;l++){
            int idx=tid+l*256;
            unsigned o = (unsigned)((idx>>4)*72 + (idx&15)*4)*4u;
            CP16(sb + (4352u+  4608u)*4u + o, Ssrc + (size_t)idx*4);
            CP16(sb + (4352u+2*4608u)*4u + o, Asrc + (size_t)idx*4);
            CP16(sb + (4352u+3*4608u)*4u + o, Vsrc + (size_t)idx*4);
        }
        asm volatile("cp.async.commit_group;" ::: "memory");
    }
    if (tid<=64){
        double gd = 1.0 - exp2(-5.0-(double)h);
        gp[tid]=(float)pow(gd,(double)tid);
    }
    if (tid<64) Xs[tid] = g_Xn[((size_t)bh*NCHK+j)*64 + tid];
#pragma unroll
    for (int l=0;l<4;l++){
        int idx=tid+l*256;
        int i=idx>>4, d4=(idx&15)*4;
        float4 q4 = *(const float4*)(g_q + base + (size_t)idx*4);
        bQ[i*68+d4  ]=tfr(q4.x);
        bQ[i*68+d4+1]=tfr(q4.y);
        bQ[i*68+d4+2]=tfr(q4.z);
        bQ[i*68+d4+3]=tfr(q4.w);
        float4 k4 = *(const float4*)(g_k + base + (size_t)idx*4);
        bK[(d4  )*72+i]=tfr(k4.x);
        bK[(d4+1)*72+i]=tfr(k4.y);
        bK[(d4+2)*72+i]=tfr(k4.z);
        bK[(d4+3)*72+i]=tfr(k4.w);
    }
    __syncthreads();
    const int warp=tid>>5, lane=tid&31;
    const int wm=warp&3, wn=warp>>2, g=lane>>2, t4=lane&3;
    const int m0=wm*16;
    const int r0=m0+g, r1=r0+8;

    unsigned qa[8][4];
#pragma unroll
    for (int k8=0;k8<8;k8++){
        int k=k8*8;
        qa[k8][0]=__float_as_uint(bQ[(m0+g  )*68 + k+t4  ]);
        qa[k8][1]=__float_as_uint(bQ[(m0+g+8)*68 + k+t4  ]);
        qa[k8][2]=__float_as_uint(bQ[(m0+g  )*68 + k+t4+4]);
        qa[k8][3]=__float_as_uint(bQ[(m0+g+8)*68 + k+t4+4]);
    }
    float accP[4][4]={};
#pragma unroll
    for (int k8=0;k8<8;k8++){
#pragma unroll
        for (int nt=0;nt<4;nt++){
            int cb=wn*32+nt*8;
            unsigned b0=__float_as_uint(bK[(k8*8+t4  )*72 + cb+g]);
            unsigned b1=__float_as_uint(bK[(k8*8+t4+4)*72 + cb+g]);
            mma8(accP[nt], qa[k8], b0, b1);
        }
    }
    asm volatile("cp.async.wait_group 0;" ::: "memory");
    __syncthreads();
    float accQ[4][4]={}, accPP[4][4]={};
#pragma unroll
    for (int k8=0;k8<8;k8++){
#pragma unroll
        for (int nt=0;nt<4;nt++){
            int cb=wn*32+nt*8;
            unsigned b0=f2tf(bS[(k8*8+t4  )*72 + cb+g]);
            unsigned b1=f2tf(bS[(k8*8+t4+4)*72 + cb+g]);
            mma8(accQ[nt], qa[k8], b0, b1);
            unsigned c0=f2tf(bA[(k8*8+t4  )*72 + cb+g]);
            unsigned c1=f2tf(bA[(k8*8+t4+4)*72 + cb+g]);
            mma8(accPP[nt], qa[k8], c0, c1);
        }
    }
#pragma unroll
    for (int nt=0;nt<4;nt++){
        int c0=wn*32+nt*8+t4*2;
        int d00=r0-c0, d01=d00-1, d10=r1-c0, d11=d10-1;
        float p00 = (d00>=0)? accP[nt][0]*gp[d00] : 0.f;
        float p01 = (d01>=0)? accP[nt][1]*gp[d01] : 0.f;
        float p10 = (d10>=0)? accP[nt][2]*gp[d10] : 0.f;
        float p11 = (d11>=0)? accP[nt][3]*gp[d11] : 0.f;
        bQ[r0*68+c0  ]=tfr(p00);
        bQ[r0*68+c0+1]=tfr(p01);
        bQ[r1*68+c0  ]=tfr(p10);
        bQ[r1*68+c0+1]=tfr(p11);
        *(float2*)(bK + r0*72 + c0) = make_float2(accPP[nt][0],accPP[nt][1]);
        *(float2*)(bK + r1*72 + c0) = make_float2(accPP[nt][2],accPP[nt][3]);
        float gq0=gp[r0+1], gq1=gp[r1+1];
        accQ[nt][0]*=gq0; accQ[nt][1]*=gq0;
        accQ[nt][2]*=gq1; accQ[nt][3]*=gq1;
    }
    __syncthreads();
#pragma unroll
    for (int k8=0;k8<8;k8++){
        int k=k8*8;
        unsigned pa[4];
        pa[0]=__float_as_uint(bQ[(m0+g  )*68 + k+t4  ]);
        pa[1]=__float_as_uint(bQ[(m0+g+8)*68 + k+t4  ]);
        pa[2]=__float_as_uint(bQ[(m0+g  )*68 + k+t4+4]);
        pa[3]=__float_as_uint(bQ[(m0+g+8)*68 + k+t4+4]);
#pragma unroll
        for (int nt=0;nt<4;nt++){
            int cb=wn*32+nt*8;
            unsigned b0=f2tf(bV[(k+t4  )*72 + cb+g]);
            unsigned b1=f2tf(bV[(k+t4+4)*72 + cb+g]);
            mma8(accQ[nt], pa, b0, b1);
        }
    }
    {
        int e = tid&63, q = tid>>6;
        float g1 = gp[1];
        float loc[16];
        float c = 0.f;
#pragma unroll
        for (int i=15;i>=0;--i){
            c = bK[(q*16+i)*72 + e] + g1*c;
            loc[i] = c;
        }
        carry[q*64+e] = loc[0];
        __syncthreads();
        float F = 0.f;
        if (q<3) F  = carry[(q+1)*64+e];
        if (q<2) F += gp[16]*carry[(q+2)*64+e];
        if (q<1) F += gp[32]*carry[(q+3)*64+e];
#pragma unroll
        for (int i=0;i<16;i++){
            bK[(q*16+i)*72 + e] = loc[i] + gp[16-i]*F;
        }
    }
    __syncthreads();
    float s1=0.f, s2=0.f;
    float gx0=gp[64-r0], gx1=gp[64-r1];
#pragma unroll
    for (int nt=0;nt<4;nt++){
        int c0=wn*32+nt*8+t4*2;
        float v00 = accQ[nt][0] + bK[r0*72+c0  ] + gx0*Xs[c0  ];
        float v01 = accQ[nt][1] + bK[r0*72+c0+1] + gx0*Xs[c0+1];
        float v10 = accQ[nt][2] + bK[r1*72+c0  ] + gx1*Xs[c0  ];
        float v11 = accQ[nt][3] + bK[r1*72+c0+1] + gx1*Xs[c0+1];
        s1 += v00+v01+v10+v11;
        s2 += v00*v00+v01*v01+v10*v10+v11*v11;
        *(float2*)(g_ret + base + (size_t)r0*64 + c0) = make_float2(v00,v01);
        *(float2*)(g_ret + base + (size_t)r1*64 + c0) = make_float2(v10,v11);
    }
#pragma unroll
    for (int o=16;o>0;o>>=1){
        s1 += __shfl_down_sync(0xffffffffu, s1, o);
        s2 += __shfl_down_sync(0xffffffffu, s2, o);
    }
    if (lane==0){ redS[warp]=s1; redQ[warp]=s2; }
    __syncthreads();
    if (tid==0){
        float a=0.f,bq=0.f;
#pragma unroll
        for (int w=0;w<8;w++){ a+=redS[w]; bq+=redQ[w]; }
        g_stat[(size_t)bid*2  ]=a;
        g_stat[(size_t)bid*2+1]=bq;
    }
}

// ================= K5: per-batch GroupNorm stats =================
__global__ void __launch_bounds__(512) k_stats()
{
    __shared__ float r1[512], r2[512];
    int b=blockIdx.x, tid=threadIdx.x;
    r1[tid]=g_stat[(size_t)(b*512+tid)*2];
    r2[tid]=g_stat[(size_t)(b*512+tid)*2+1];
    __syncthreads();
    for (int o=256;o>0;o>>=1){
        if (tid<o){ r1[tid]+=r1[tid+o]; r2[tid]+=r2[tid+o]; }
        __syncthreads();
    }
    if (tid==0){
        const float N = (float)((size_t)NH*NT*ND);
        float mu = r1[0]/N;
        float var = r2[0]/N - mu*mu;
        g_norm[b*2]=mu;
        g_norm[b*2+1]=rsqrtf(var+1e-5f);
    }
}

// ================= K6: normalize + layout to [B,T,NE] =================
__global__ void __launch_bounds__(256) k_out(const float* __restrict__ gnw,
                                             const float* __restrict__ gnb,
                                             float* __restrict__ out)
{
    int bid=blockIdx.x;
    int b=bid>>11, t=bid&2047;
    int tid=threadIdx.x;
    int h=tid>>4, d4=(tid&15)*4;
    float mu=g_norm[b*2], rs=g_norm[b*2+1];
    float w = gnw[h]*rs;
    float bb = gnb[h] - mu*w;
    float4 xv = *(const float4*)(g_ret + (((size_t)(b*NH+h))*NT + t)*ND + d4);
    float4 yv = make_float4(xv.x*w+bb, xv.y*w+bb, xv.z*w+bb, xv.w*w+bb);
    *(float4*)(out + (size_t)bid*NE + h*ND + d4) = yv;
}

// ================= K7: kv reduce + decay =================
__global__ void __launch_bounds__(256) k_kvout(const float* __restrict__ pkv,
                                               float* __restrict__ out_kv)
{
    int h=blockIdx.x;
    int idx=blockIdx.y*256+threadIdx.x;
    float s=0.f;
    for (int b=0;b<NB;b++){
        size_t bh=((size_t)(b*NH+h))*NCHK;
        for (int j2=0;j2<NCHK;j2++) s += g_kvc[(bh+j2)*4096 + idx];
    }
    double gd = 1.0 - exp2(-5.0-(double)h);
    out_kv[(size_t)h*4096 + idx] = (float)gd*pkv[(size_t)h*4096 + idx] + 0.25f*s;
}

extern "C" void kernel_launch(void* const* d_in, const int* in_sizes, int n_in,
                              void* d_out, int out_size)
{
    const float* x   = (const float*)d_in[0];
    const float* pkv = (const float*)d_in[1];
    const float* Wq  = (const float*)d_in[2];
    const float* Wk  = (const float*)d_in[3];
    const float* Wv  = (const float*)d_in[4];
    const float* gnw = (const float*)d_in[5];
    const float* gnb = (const float*)d_in[6];
    float* out = (float*)d_out;

    cudaFuncSetAttribute(k_proj3, cudaFuncAttributeMaxDynamicSharedMemorySize, PROJ_SMEM);
    cudaFuncSetAttribute(k_pass1, cudaFuncAttributeMaxDynamicSharedMemorySize, P1_SMEM);
    cudaFuncSetAttribute(k_pass3, cudaFuncAttributeMaxDynamicSharedMemorySize, P3_SMEM);

    k_cvt<<<(NX4 + 3*NW4)/256, 256>>>(x, Wq, Wk, Wv);
    dim3 gproj(8, 64, 3);
    k_proj3<<<gproj, 256, PROJ_SMEM>>>();
    k_pass1<<<NBH*NCHK, 256, P1_SMEM>>>(pkv);
    dim3 gscan(NBH, 16);
    k_scan<<<gscan, 256>>>();
    k_pass3<<<NBH*NCHK, 256, P3_SMEM>>>(pkv);
    k_stats<<<NB, 512>>>();
    k_out<<<NB*NT, 256>>>(gnw, gnb, out);
    dim3 gkv(NH, 16);
    k_kvout<<<gkv, 256>>>(pkv, out + (size_t)NB*NT*NE);
}

// round 9
// speedup vs baseline: 1.2543x; 1.0135x over previous
#include <cuda_runtime.h>
#include <math.h>
#include <stdint.h>

#define NB 4
#define NT 2048
#define NH 16
#define ND 64
#define NE 1024
#define NC 64
#define NCHK 32
#define NBH (NB*NH)

// ---------------- scratch (device globals; no runtime allocation) ----------------
__device__ float g_q  [(size_t)NB*NH*NT*ND];
__device__ float g_k  [(size_t)NB*NH*NT*ND];
__device__ float g_v  [(size_t)NB*NH*NT*ND];
__device__ float g_ret[(size_t)NB*NH*NT*ND];
__device__ float g_U  [(size_t)NBH*NCHK*ND*ND];
__device__ float g_S  [(size_t)NBH*NCHK*ND*ND];
__device__ float g_kvc[(size_t)NBH*NCHK*ND*ND];
__device__ float g_W  [(size_t)NBH*NCHK*ND];
__device__ float g_Xn [(size_t)NBH*NCHK*ND];
__device__ float g_stat[(size_t)NBH*NCHK*2];
__device__ float g_norm[NB*2];
__device__ float g_xr [(size_t)NB*NT*NE];    // tf32-rounded X
__device__ float g_wr [(size_t)3*NE*NE];     // tf32-rounded Wq,Wk,Wv
__device__ float g_ar [(size_t)NH*ND*ND];    // tf32-rounded past_kv

__device__ __forceinline__ unsigned f2tf(float x){
    unsigned r;
    asm("cvt.rna.tf32.f32 %0, %1;" : "=r"(r) : "f"(x));
    return r;
}
__device__ __forceinline__ float tfr(float x){
    return __uint_as_float(f2tf(x));
}
__device__ __forceinline__ void mma8(float c[4], const unsigned a[4], unsigned b0, unsigned b1){
    asm volatile(
      "mma.sync.aligned.m16n8k8.row.col.f32.tf32.tf32.f32 "
      "{%0,%1,%2,%3},{%4,%5,%6,%7},{%8,%9},{%0,%1,%2,%3};"
      : "+f"(c[0]),"+f"(c[1]),"+f"(c[2]),"+f"(c[3])
      : "r"(a[0]),"r"(a[1]),"r"(a[2]),"r"(a[3]), "r"(b0),"r"(b1));
}

#define CP16(dst_u32, src) \
    asm volatile("cp.async.ca.shared.global [%0], [%1], 16;" :: "r"(dst_u32), "l"(src))

// ================= K0: pre-round X, W, past_kv to tf32 =================
#define NX4 ((NB*NT*NE)/4)       // 2097152
#define NW4 ((NE*NE)/4)          // 262144
#define NA4 ((NH*ND*ND)/4)       // 16384
__global__ void __launch_bounds__(256) k_cvt(const float* __restrict__ X,
                                             const float* __restrict__ Wq,
                                             const float* __restrict__ Wk,
                                             const float* __restrict__ Wv,
                                             const float* __restrict__ pkv)
{
    int i = blockIdx.x*256 + threadIdx.x;
    const float4* src;
    float4* dst;
    int off;
    if (i < NX4){
        src = (const float4*)X; dst = (float4*)g_xr; off = i;
    } else if (i < NX4 + 3*NW4){
        int i2 = i - NX4;
        int sel = i2 / NW4; off = i2 - sel*NW4;
        src = (const float4*)((sel==0)?Wq:(sel==1)?Wk:Wv);
        dst = (float4*)(g_wr + (size_t)sel*NE*NE);
    } else {
        off = i - NX4 - 3*NW4;
        if (off >= NA4) return;
        src = (const float4*)pkv; dst = (float4*)g_ar;
    }
    float4 v = src[off];
    v.x=tfr(v.x); v.y=tfr(v.y); v.z=tfr(v.z); v.w=tfr(v.w);
    dst[off] = v;
}

// ================= K1: fused QKV projection (TF32 mma, 128x128, 3-stage) ===
#define PROJ_SMEM (3*(2560+2176)*4)
__global__ void __launch_bounds__(256) k_proj3()
{
    const int sel = blockIdx.z;
    const float* X = g_xr;
    const float* W = g_wr + (size_t)sel*NE*NE;
    float* dst = (sel==0)?g_q:(sel==1)?g_k:g_v;

    extern __shared__ float dsm[];
    float* As = dsm;            // 3 stages of 128*20
    float* Bs = dsm + 3*2560;   // 3 stages of 16*136

    const int tid = threadIdx.x;
    const int rowBase = blockIdx.y*128, colBase = blockIdx.x*128;
    const int warp = tid>>5, lane = tid&31;
    const int wm = warp&3, wn = warp>>2;
    const int g = lane>>2, t4 = lane&3;

    const int ar0 = tid>>2, ac0 = (tid&3)*4;
    const int br0 = tid>>5, bc0 = (tid&31)*4;

    const unsigned sA = (unsigned)__cvta_generic_to_shared(As);
    const unsigned sB = (unsigned)__cvta_generic_to_shared(Bs);
    const unsigned stA = 2560u*4u, stB = 2176u*4u;

    float acc[2][8][4];
#pragma unroll
    for (int a=0;a<2;a++)
#pragma unroll
      for (int b=0;b<8;b++)
#pragma unroll
        for (int c=0;c<4;c++) acc[a][b][c]=0.f;

    auto issue = [&](int it, int st){
        int kb = it*16;
        const float* xs = X + (size_t)rowBase*NE + kb;
        CP16(sA + st*stA + (unsigned)((ar0    )*20 + ac0)*4u, xs + (size_t)(ar0    )*NE + ac0);
        CP16(sA + st*stA + (unsigned)((ar0+64 )*20 + ac0)*4u, xs + (size_t)(ar0+64 )*NE + ac0);
        const float* ws = W + (size_t)kb*NE + colBase;
        CP16(sB + st*stB + (unsigned)((br0   )*136 + bc0)*4u, ws + (size_t)(br0   )*NE + bc0);
        CP16(sB + st*stB + (unsigned)((br0+8 )*136 + bc0)*4u, ws + (size_t)(br0+8 )*NE + bc0);
        asm volatile("cp.async.commit_group;" ::: "memory");
    };

    const int NIT = NE/16;
    issue(0,0); issue(1,1);
    for (int it=0; it<NIT; it++){
        const int st = it%3;
        if (it+2<NIT){
            issue(it+2, (it+2)%3);
            asm volatile("cp.async.wait_group 2;" ::: "memory");
        } else if (it+1<NIT){
            asm volatile("cp.async.wait_group 1;" ::: "memory");
        } else {
            asm volatile("cp.async.wait_group 0;" ::: "memory");
        }
        __syncthreads();
        const float* Ap = As + st*2560;
        const float* Bp = Bs + st*2176;
#pragma unroll
        for (int k0=0;k0<16;k0+=8){
            unsigned af[2][4];
#pragma unroll
            for (int mt=0;mt<2;mt++){
                int r0 = wm*32 + mt*16;
                af[mt][0] = __float_as_uint(Ap[(r0+g  )*20 + k0 + t4    ]);
                af[mt][1] = __float_as_uint(Ap[(r0+g+8)*20 + k0 + t4    ]);
                af[mt][2] = __float_as_uint(Ap[(r0+g  )*20 + k0 + t4 + 4]);
                af[mt][3] = __float_as_uint(Ap[(r0+g+8)*20 + k0 + t4 + 4]);
            }
#pragma unroll
            for (int nt=0;nt<8;nt++){
                int c0 = wn*64 + nt*8;
                unsigned b0 = __float_as_uint(Bp[(k0+t4  )*136 + c0 + g]);
                unsigned b1 = __float_as_uint(Bp[(k0+t4+4)*136 + c0 + g]);
#pragma unroll
                for (int mt=0;mt<2;mt++){
                    mma8(acc[mt][nt], af[mt], b0, b1);
                }
            }
        }
        __syncthreads();
    }
    // epilogue: store q/k/v pre-rounded to tf32 (consumers feed them to mma anyway)
#pragma unroll
    for (int mt=0;mt<2;mt++)
#pragma unroll
    for (int nt=0;nt<8;nt++){
        int row = rowBase + wm*32 + mt*16 + g;
        int col = colBase + wn*64 + nt*8 + t4*2;
        int b_ = row>>11, t_ = row&2047, h_ = col>>6, d_ = col&63;
        float* p0 = dst + (((size_t)(b_*NH+h_))*NT + t_)*ND + d_;
        *(float2*)p0 = make_float2(tfr(acc[mt][nt][0]), tfr(acc[mt][nt][1]));
        int t2_ = (row+8)&2047;
        float* p1 = dst + (((size_t)(b_*NH+h_))*NT + t2_)*ND + d_;
        *(float2*)p1 = make_float2(tfr(acc[mt][nt][2]), tfr(acc[mt][nt][3]));
    }
}

// ================= K2: per-chunk U_j, KV_j (tensor core, frag reuse), W_j =========
#define P1_SMEM ((4352 + 2*4608)*4)
__global__ void __launch_bounds__(256) k_pass1(const float* __restrict__ pkv)
{
    extern __shared__ float sm1[];
    float* bKT = sm1;          // 64x68 : K^T [d][i] (already tf32)
    float* bV  = sm1 + 4352;   // 64x72 : V  [i][e] (already tf32; later Q)
    float* bVw = sm1 + 4352 + 4608; // 64x72 : gamma^{63-i} V, tf32
    __shared__ float gp[65];
    __shared__ float red[4*64];
    __shared__ float qw[64];
    int tid=threadIdx.x, bid=blockIdx.x;
    int j=bid&31, bh=bid>>5, h=bh&15;
    size_t base = ((size_t)bh*NT + (size_t)j*NC)*ND;
    if (tid<=64){
        double gd = 1.0 - exp2(-5.0-(double)h);
        gp[tid]=(float)pow(gd,(double)tid);
    }
    __syncthreads();
#pragma unroll
    for (int l=0;l<4;l++){
        int idx = tid + l*256;
        int i=idx>>4, d4=(idx&15)*4;
        float4 k4 = *(const float4*)(g_k + base + (size_t)idx*4);
        bKT[(d4  )*68+i]=k4.x;
        bKT[(d4+1)*68+i]=k4.y;
        bKT[(d4+2)*68+i]=k4.z;
        bKT[(d4+3)*68+i]=k4.w;
        float4 v4 = *(const float4*)(g_v + base + (size_t)idx*4);
        *(float4*)(bV + i*72 + d4) = v4;
        float w = gp[63-i];
        bVw[i*72+d4  ]=tfr(v4.x*w);
        bVw[i*72+d4+1]=tfr(v4.y*w);
        bVw[i*72+d4+2]=tfr(v4.z*w);
        bVw[i*72+d4+3]=tfr(v4.w*w);
    }
    __syncthreads();
    const int warp=tid>>5, lane=tid&31;
    const int wm=warp&3, wn=warp>>2, g=lane>>2, t4=lane&3;
    const int m0=wm*16;
    const int r0=m0+g, r1=r0+8;

    unsigned ka[8][4];
#pragma unroll
    for (int k8=0;k8<8;k8++){
        int k=k8*8;
        ka[k8][0]=__float_as_uint(bKT[(m0+g  )*68 + k+t4  ]);
        ka[k8][1]=__float_as_uint(bKT[(m0+g+8)*68 + k+t4  ]);
        ka[k8][2]=__float_as_uint(bKT[(m0+g  )*68 + k+t4+4]);
        ka[k8][3]=__float_as_uint(bKT[(m0+g+8)*68 + k+t4+4]);
    }

    float accKV[4][4]={}, accU[4][4]={};
#pragma unroll
    for (int k8=0;k8<8;k8++){
#pragma unroll
        for (int nt=0;nt<4;nt++){
            int cb=wn*32+nt*8;
            unsigned b0=__float_as_uint(bV [(k8*8+t4  )*72 + cb+g]);
            unsigned b1=__float_as_uint(bV [(k8*8+t4+4)*72 + cb+g]);
            mma8(accKV[nt], ka[k8], b0, b1);
            unsigned c0=__float_as_uint(bVw[(k8*8+t4  )*72 + cb+g]);
            unsigned c1=__float_as_uint(bVw[(k8*8+t4+4)*72 + cb+g]);
            mma8(accU[nt], ka[k8], c0, c1);
        }
    }
    {
        float* Kp = g_kvc + (size_t)bid*4096;
        float* Up = g_U  + (size_t)bid*4096;
#pragma unroll
        for (int nt=0;nt<4;nt++){
            int c0=wn*32+nt*8+t4*2;
            *(float2*)(Kp + r0*64 + c0) = make_float2(accKV[nt][0],accKV[nt][1]);
            *(float2*)(Kp + r1*64 + c0) = make_float2(accKV[nt][2],accKV[nt][3]);
            *(float2*)(Up + r0*64 + c0) = make_float2(accU[nt][0],accU[nt][1]);
            *(float2*)(Up + r1*64 + c0) = make_float2(accU[nt][2],accU[nt][3]);
        }
    }
    __syncthreads();
#pragma unroll
    for (int l=0;l<4;l++){
        int idx=tid+l*256;
        *(float4*)(bV + (idx>>4)*72 + (idx&15)*4) =
            *(const float4*)(g_q + base + (size_t)idx*4);
    }
    __syncthreads();
    int rr = tid>>6, d = tid&63;
    float s = 0.f;
#pragma unroll
    for (int i=rr*16;i<rr*16+16;i++) s += gp[i]*bV[i*72 + d];
    red[rr*64 + d] = s;
    __syncthreads();
    if (tid<64) qw[tid] = red[tid] + red[64+tid] + red[128+tid] + red[192+tid];
    __syncthreads();
    const float* A = pkv + (size_t)h*4096;
    float s2 = 0.f;
#pragma unroll
    for (int dd=rr*16; dd<rr*16+16; dd++) s2 += qw[dd]*A[dd*64 + d];
    red[rr*64 + d] = s2;
    __syncthreads();
    if (tid<64) g_W[(size_t)bid*64 + tid] = red[tid] + red[64+tid] + red[128+tid] + red[192+tid];
}

// ================= K3: chunk scans (round-6 structure; S stored tf32) =========
__global__ void __launch_bounds__(256) k_scan()
{
    int bh = blockIdx.x, part = blockIdx.y, tid = threadIdx.x;
    int h = bh&15;
    double gd = 1.0 - exp2(-5.0-(double)h);
    float g64 = (float)pow(gd,64.0);
    float S[4] = {0.f,0.f,0.f,0.f};
    int off = part*1024;
    for (int j=0;j<NCHK;j++){
        size_t o = ((size_t)bh*NCHK+j)*4096 + off;
#pragma unroll
        for (int r=0;r<4;r++){
            int idx = tid + r*256;
            g_S[o+idx] = tfr(S[r]);
            S[r] = g64*S[r] + g_U[o+idx];
        }
    }
    if (part==0 && tid<64){
        float X=0.f;
        for (int j=NCHK-1;j>=0;--j){
            size_t o2 = ((size_t)bh*NCHK+j)*64;
            g_Xn[o2+tid] = X;
            X = g64*X + g_W[o2+tid];
        }
    }
}

// ================= K4: per-chunk finalize (tensor core, all operands pre-tf32) ======
#define P3_SMEM ((4352 + 4*4608)*4)
__global__ void __launch_bounds__(256) k_pass3()
{
    extern __shared__ float sm3[];
    float* bQ = sm3;                  // 64x68 : Q [i][d] tf32 -> P tf32
    float* bK = sm3 + 4352;           // 64x72 : K^T [d][s] tf32 -> scan buffer
    float* bS = sm3 + 4352 + 4608;    // 64x72 : S (tf32)
    float* bA = sm3 + 4352 + 2*4608;  // 64x72 : past_kv (tf32)
    float* bV = sm3 + 4352 + 3*4608;  // 64x72 : V (tf32)
    __shared__ float gp[65];
    __shared__ float Xs[64];
    __shared__ float carry[4*64];
    __shared__ float redS[8], redQ[8];
    int tid=threadIdx.x, bid=blockIdx.x;
    int j=bid&31, bh=bid>>5, h=bh&15;
    size_t base=((size_t)bh*NT+(size_t)j*NC)*ND;

    {
        const unsigned sb = (unsigned)__cvta_generic_to_shared(sm3);
        const float* Ssrc = g_S + ((size_t)bh*NCHK+j)*4096;
        const float* Asrc = g_ar + (size_t)h*4096;
        const float* Vsrc = g_v + base;
#pragma unroll
        for (int l=0;l<4;l++){
            int idx=tid+l*256;
            unsigned o = (unsigned)((idx>>4)*72 + (idx&15)*4)*4u;
            CP16(sb + (4352u+  4608u)*4u + o, Ssrc + (size_t)idx*4);
            CP16(sb + (4352u+2*4608u)*4u + o, Asrc + (size_t)idx*4);
            CP16(sb + (4352u+3*4608u)*4u + o, Vsrc + (size_t)idx*4);
        }
        asm volatile("cp.async.commit_group;" ::: "memory");
    }
    if (tid<=64){
        double gd = 1.0 - exp2(-5.0-(double)h);
        gp[tid]=(float)pow(gd,(double)tid);
    }
    if (tid<64) Xs[tid] = g_Xn[((size_t)bh*NCHK+j)*64 + tid];
#pragma unroll
    for (int l=0;l<4;l++){
        int idx=tid+l*256;
        int i=idx>>4, d4=(idx&15)*4;
        float4 q4 = *(const float4*)(g_q + base + (size_t)idx*4);
        *(float4*)(bQ + i*68 + d4) = q4;
        float4 k4 = *(const float4*)(g_k + base + (size_t)idx*4);
        bK[(d4  )*72+i]=k4.x;
        bK[(d4+1)*72+i]=k4.y;
        bK[(d4+2)*72+i]=k4.z;
        bK[(d4+3)*72+i]=k4.w;
    }
    __syncthreads();
    const int warp=tid>>5, lane=tid&31;
    const int wm=warp&3, wn=warp>>2, g=lane>>2, t4=lane&3;
    const int m0=wm*16;
    const int r0=m0+g, r1=r0+8;

    unsigned qa[8][4];
#pragma unroll
    for (int k8=0;k8<8;k8++){
        int k=k8*8;
        qa[k8][0]=__float_as_uint(bQ[(m0+g  )*68 + k+t4  ]);
        qa[k8][1]=__float_as_uint(bQ[(m0+g+8)*68 + k+t4  ]);
        qa[k8][2]=__float_as_uint(bQ[(m0+g  )*68 + k+t4+4]);
        qa[k8][3]=__float_as_uint(bQ[(m0+g+8)*68 + k+t4+4]);
    }
    float accP[4][4]={};
#pragma unroll
    for (int k8=0;k8<8;k8++){
#pragma unroll
        for (int nt=0;nt<4;nt++){
            int cb=wn*32+nt*8;
            unsigned b0=__float_as_uint(bK[(k8*8+t4  )*72 + cb+g]);
            unsigned b1=__float_as_uint(bK[(k8*8+t4+4)*72 + cb+g]);
            mma8(accP[nt], qa[k8], b0, b1);
        }
    }
    asm volatile("cp.async.wait_group 0;" ::: "memory");
    __syncthreads();
    float accQ[4][4]={}, accPP[4][4]={};
#pragma unroll
    for (int k8=0;k8<8;k8++){
#pragma unroll
        for (int nt=0;nt<4;nt++){
            int cb=wn*32+nt*8;
            unsigned b0=__float_as_uint(bS[(k8*8+t4  )*72 + cb+g]);
            unsigned b1=__float_as_uint(bS[(k8*8+t4+4)*72 + cb+g]);
            mma8(accQ[nt], qa[k8], b0, b1);
            unsigned c0=__float_as_uint(bA[(k8*8+t4  )*72 + cb+g]);
            unsigned c1=__float_as_uint(bA[(k8*8+t4+4)*72 + cb+g]);
            mma8(accPP[nt], qa[k8], c0, c1);
        }
    }
#pragma unroll
    for (int nt=0;nt<4;nt++){
        int c0=wn*32+nt*8+t4*2;
        int d00=r0-c0, d01=d00-1, d10=r1-c0, d11=d10-1;
        float p00 = (d00>=0)? accP[nt][0]*gp[d00] : 0.f;
        float p01 = (d01>=0)? accP[nt][1]*gp[d01] : 0.f;
        float p10 = (d10>=0)? accP[nt][2]*gp[d10] : 0.f;
        float p11 = (d11>=0)? accP[nt][3]*gp[d11] : 0.f;
        bQ[r0*68+c0  ]=tfr(p00);
        bQ[r0*68+c0+1]=tfr(p01);
        bQ[r1*68+c0  ]=tfr(p10);
        bQ[r1*68+c0+1]=tfr(p11);
        *(float2*)(bK + r0*72 + c0) = make_float2(accPP[nt][0],accPP[nt][1]);
        *(float2*)(bK + r1*72 + c0) = make_float2(accPP[nt][2],accPP[nt][3]);
        float gq0=gp[r0+1], gq1=gp[r1+1];
        accQ[nt][0]*=gq0; accQ[nt][1]*=gq0;
        accQ[nt][2]*=gq1; accQ[nt][3]*=gq1;
    }
    __syncthreads();
#pragma unroll
    for (int k8=0;k8<8;k8++){
        int k=k8*8;
        unsigned pa[4];
        pa[0]=__float_as_uint(bQ[(m0+g  )*68 + k+t4  ]);
        pa[1]=__float_as_uint(bQ[(m0+g+8)*68 + k+t4  ]);
        pa[2]=__float_as_uint(bQ[(m0+g  )*68 + k+t4+4]);
        pa[3]=__float_as_uint(bQ[(m0+g+8)*68 + k+t4+4]);
#pragma unroll
        for (int nt=0;nt<4;nt++){
            int cb=wn*32+nt*8;
            unsigned b0=__float_as_uint(bV[(k+t4  )*72 + cb+g]);
            unsigned b1=__float_as_uint(bV[(k+t4+4)*72 + cb+g]);
            mma8(accQ[nt], pa, b0, b1);
        }
    }
    {
        int e = tid&63, q = tid>>6;
        float g1 = gp[1];
        float loc[16];
        float c = 0.f;
#pragma unroll
        for (int i=15;i>=0;--i){
            c = bK[(q*16+i)*72 + e] + g1*c;
            loc[i] = c;
        }
        carry[q*64+e] = loc[0];
        __syncthreads();
        float F = 0.f;
        if (q<3) F  = carry[(q+1)*64+e];
        if (q<2) F += gp[16]*carry[(q+2)*64+e];
        if (q<1) F += gp[32]*carry[(q+3)*64+e];
#pragma unroll
        for (int i=0;i<16;i++){
            bK[(q*16+i)*72 + e] = loc[i] + gp[16-i]*F;
        }
    }
    __syncthreads();
    float s1=0.f, s2=0.f;
    float gx0=gp[64-r0], gx1=gp[64-r1];
#pragma unroll
    for (int nt=0;nt<4;nt++){
        int c0=wn*32+nt*8+t4*2;
        float v00 = accQ[nt][0] + bK[r0*72+c0  ] + gx0*Xs[c0  ];
        float v01 = accQ[nt][1] + bK[r0*72+c0+1] + gx0*Xs[c0+1];
        float v10 = accQ[nt][2] + bK[r1*72+c0  ] + gx1*Xs[c0  ];
        float v11 = accQ[nt][3] + bK[r1*72+c0+1] + gx1*Xs[c0+1];
        s1 += v00+v01+v10+v11;
        s2 += v00*v00+v01*v01+v10*v10+v11*v11;
        *(float2*)(g_ret + base + (size_t)r0*64 + c0) = make_float2(v00,v01);
        *(float2*)(g_ret + base + (size_t)r1*64 + c0) = make_float2(v10,v11);
    }
#pragma unroll
    for (int o=16;o>0;o>>=1){
        s1 += __shfl_down_sync(0xffffffffu, s1, o);
        s2 += __shfl_down_sync(0xffffffffu, s2, o);
    }
    if (lane==0){ redS[warp]=s1; redQ[warp]=s2; }
    __syncthreads();
    if (tid==0){
        float a=0.f,bq=0.f;
#pragma unroll
        for (int w=0;w<8;w++){ a+=redS[w]; bq+=redQ[w]; }
        g_stat[(size_t)bid*2  ]=a;
        g_stat[(size_t)bid*2+1]=bq;
    }
}

// ================= K5: per-batch GroupNorm stats =================
__global__ void __launch_bounds__(512) k_stats()
{
    __shared__ float r1[512], r2[512];
    int b=blockIdx.x, tid=threadIdx.x;
    r1[tid]=g_stat[(size_t)(b*512+tid)*2];
    r2[tid]=g_stat[(size_t)(b*512+tid)*2+1];
    __syncthreads();
    for (int o=256;o>0;o>>=1){
        if (tid<o){ r1[tid]+=r1[tid+o]; r2[tid]+=r2[tid+o]; }
        __syncthreads();
    }
    if (tid==0){
        const float N = (float)((size_t)NH*NT*ND);
        float mu = r1[0]/N;
        float var = r2[0]/N - mu*mu;
        g_norm[b*2]=mu;
        g_norm[b*2+1]=rsqrtf(var+1e-5f);
    }
}

// ================= K6: normalize + layout to [B,T,NE] =================
__global__ void __launch_bounds__(256) k_out(const float* __restrict__ gnw,
                                             const float* __restrict__ gnb,
                                             float* __restrict__ out)
{
    int bid=blockIdx.x;
    int b=bid>>11, t=bid&2047;
    int tid=threadIdx.x;
    int h=tid>>4, d4=(tid&15)*4;
    float mu=g_norm[b*2], rs=g_norm[b*2+1];
    float w = gnw[h]*rs;
    float bb = gnb[h] - mu*w;
    float4 xv = *(const float4*)(g_ret + (((size_t)(b*NH+h))*NT + t)*ND + d4);
    float4 yv = make_float4(xv.x*w+bb, xv.y*w+bb, xv.z*w+bb, xv.w*w+bb);
    *(float4*)(out + (size_t)bid*NE + h*ND + d4) = yv;
}

// ================= K7: kv reduce + decay =================
__global__ void __launch_bounds__(256) k_kvout(const float* __restrict__ pkv,
                                               float* __restrict__ out_kv)
{
    int h=blockIdx.x;
    int idx=blockIdx.y*256+threadIdx.x;
    float s=0.f;
    for (int b=0;b<NB;b++){
        size_t bh=((size_t)(b*NH+h))*NCHK;
        for (int j2=0;j2<NCHK;j2++) s += g_kvc[(bh+j2)*4096 + idx];
    }
    double gd = 1.0 - exp2(-5.0-(double)h);
    out_kv[(size_t)h*4096 + idx] = (float)gd*pkv[(size_t)h*4096 + idx] + 0.25f*s;
}

extern "C" void kernel_launch(void* const* d_in, const int* in_sizes, int n_in,
                              void* d_out, int out_size)
{
    const float* x   = (const float*)d_in[0];
    const float* pkv = (const float*)d_in[1];
    const float* Wq  = (const float*)d_in[2];
    const float* Wk  = (const float*)d_in[3];
    const float* Wv  = (const float*)d_in[4];
    const float* gnw = (const float*)d_in[5];
    const float* gnb = (const float*)d_in[6];
    float* out = (float*)d_out;

    cudaFuncSetAttribute(k_proj3, cudaFuncAttributeMaxDynamicSharedMemorySize, PROJ_SMEM);
    cudaFuncSetAttribute(k_pass1, cudaFuncAttributeMaxDynamicSharedMemorySize, P1_SMEM);
    cudaFuncSetAttribute(k_pass3, cudaFuncAttributeMaxDynamicSharedMemorySize, P3_SMEM);

    k_cvt<<<(NX4 + 3*NW4 + NA4 + 255)/256, 256>>>(x, Wq, Wk, Wv, pkv);
    dim3 gproj(8, 64, 3);
    k_proj3<<<gproj, 256, PROJ_SMEM>>>();
    k_pass1<<<NBH*NCHK, 256, P1_SMEM>>>(pkv);
    dim3 gscan(NBH, 4);
    k_scan<<<gscan, 256>>>();
    k_pass3<<<NBH*NCHK, 256, P3_SMEM>>>();
    k_stats<<<NB, 512>>>();
    k_out<<<NB*NT, 256>>>(gnw, gnb, out);
    dim3 gkv(NH, 16);
    k_kvout<<<gkv, 256>>>(pkv, out + (size_t)NB*NT*NE);
}

// round 10
// speedup vs baseline: 1.2986x; 1.0353x over previous
#include <cuda_runtime.h>
#include <math.h>
#include <stdint.h>

#define NB 4
#define NT 2048
#define NH 16
#define ND 64
#define NE 1024
#define NC 64
#define NCHK 32
#define NBH (NB*NH)

// ---------------- scratch (device globals; no runtime allocation) ----------------
__device__ float g_q  [(size_t)NB*NH*NT*ND];
__device__ float g_k  [(size_t)NB*NH*NT*ND];
__device__ float g_v  [(size_t)NB*NH*NT*ND];
__device__ float g_ret[(size_t)NB*NH*NT*ND];
__device__ float g_U  [(size_t)NBH*NCHK*ND*ND];
__device__ float g_S  [(size_t)NBH*NCHK*ND*ND];
__device__ float g_kvc[(size_t)NBH*NCHK*ND*ND];
__device__ float g_W  [(size_t)NBH*NCHK*ND];
__device__ float g_Xn [(size_t)NBH*NCHK*ND];
__device__ float g_stat[(size_t)NBH*NCHK*2];
__device__ float g_norm[NB*2];
__device__ float g_xr [(size_t)NB*NT*NE];    // tf32-rounded X
__device__ float g_wr [(size_t)3*NE*NE];     // tf32-rounded Wq,Wk,Wv
__device__ float g_ar [(size_t)NH*ND*ND];    // tf32-rounded past_kv

__device__ __forceinline__ unsigned f2tf(float x){
    unsigned r;
    asm("cvt.rna.tf32.f32 %0, %1;" : "=r"(r) : "f"(x));
    return r;
}
__device__ __forceinline__ float tfr(float x){
    return __uint_as_float(f2tf(x));
}
__device__ __forceinline__ void mma8(float c[4], const unsigned a[4], unsigned b0, unsigned b1){
    asm volatile(
      "mma.sync.aligned.m16n8k8.row.col.f32.tf32.tf32.f32 "
      "{%0,%1,%2,%3},{%4,%5,%6,%7},{%8,%9},{%0,%1,%2,%3};"
      : "+f"(c[0]),"+f"(c[1]),"+f"(c[2]),"+f"(c[3])
      : "r"(a[0]),"r"(a[1]),"r"(a[2]),"r"(a[3]), "r"(b0),"r"(b1));
}

#define CP16(dst_u32, src) \
    asm volatile("cp.async.ca.shared.global [%0], [%1], 16;" :: "r"(dst_u32), "l"(src))

// ================= K0: pre-round X, W, past_kv to tf32 =================
#define NX4 ((NB*NT*NE)/4)       // 2097152
#define NW4 ((NE*NE)/4)          // 262144
#define NA4 ((NH*ND*ND)/4)       // 16384
__global__ void __launch_bounds__(256) k_cvt(const float* __restrict__ X,
                                             const float* __restrict__ Wq,
                                             const float* __restrict__ Wk,
                                             const float* __restrict__ Wv,
                                             const float* __restrict__ pkv)
{
    int i = blockIdx.x*256 + threadIdx.x;
    const float4* src;
    float4* dst;
    int off;
    if (i < NX4){
        src = (const float4*)X; dst = (float4*)g_xr; off = i;
    } else if (i < NX4 + 3*NW4){
        int i2 = i - NX4;
        int sel = i2 / NW4; off = i2 - sel*NW4;
        src = (const float4*)((sel==0)?Wq:(sel==1)?Wk:Wv);
        dst = (float4*)(g_wr + (size_t)sel*NE*NE);
    } else {
        off = i - NX4 - 3*NW4;
        if (off >= NA4) return;
        src = (const float4*)pkv; dst = (float4*)g_ar;
    }
    float4 v = src[off];
    v.x=tfr(v.x); v.y=tfr(v.y); v.z=tfr(v.z); v.w=tfr(v.w);
    dst[off] = v;
}

// ================= K1: fused QKV projection (TF32 mma, 128x128, 3-stage) ===
#define PROJ_SMEM (3*(2560+2176)*4)
__global__ void __launch_bounds__(256) k_proj3()
{
    const int sel = blockIdx.z;
    const float* X = g_xr;
    const float* W = g_wr + (size_t)sel*NE*NE;
    float* dst = (sel==0)?g_q:(sel==1)?g_k:g_v;

    extern __shared__ float dsm[];
    float* As = dsm;            // 3 stages of 128*20
    float* Bs = dsm + 3*2560;   // 3 stages of 16*136

    const int tid = threadIdx.x;
    const int rowBase = blockIdx.y*128, colBase = blockIdx.x*128;
    const int warp = tid>>5, lane = tid&31;
    const int wm = warp&3, wn = warp>>2;
    const int g = lane>>2, t4 = lane&3;

    const int ar0 = tid>>2, ac0 = (tid&3)*4;
    const int br0 = tid>>5, bc0 = (tid&31)*4;

    const unsigned sA = (unsigned)__cvta_generic_to_shared(As);
    const unsigned sB = (unsigned)__cvta_generic_to_shared(Bs);
    const unsigned stA = 2560u*4u, stB = 2176u*4u;

    float acc[2][8][4];
#pragma unroll
    for (int a=0;a<2;a++)
#pragma unroll
      for (int b=0;b<8;b++)
#pragma unroll
        for (int c=0;c<4;c++) acc[a][b][c]=0.f;

    auto issue = [&](int it, int st){
        int kb = it*16;
        const float* xs = X + (size_t)rowBase*NE + kb;
        CP16(sA + st*stA + (unsigned)((ar0    )*20 + ac0)*4u, xs + (size_t)(ar0    )*NE + ac0);
        CP16(sA + st*stA + (unsigned)((ar0+64 )*20 + ac0)*4u, xs + (size_t)(ar0+64 )*NE + ac0);
        const float* ws = W + (size_t)kb*NE + colBase;
        CP16(sB + st*stB + (unsigned)((br0   )*136 + bc0)*4u, ws + (size_t)(br0   )*NE + bc0);
        CP16(sB + st*stB + (unsigned)((br0+8 )*136 + bc0)*4u, ws + (size_t)(br0+8 )*NE + bc0);
        asm volatile("cp.async.commit_group;" ::: "memory");
    };

    const int NIT = NE/16;
    issue(0,0); issue(1,1);
    for (int it=0; it<NIT; it++){
        const int st = it%3;
        if (it+2<NIT){
            issue(it+2, (it+2)%3);
            asm volatile("cp.async.wait_group 2;" ::: "memory");
        } else if (it+1<NIT){
            asm volatile("cp.async.wait_group 1;" ::: "memory");
        } else {
            asm volatile("cp.async.wait_group 0;" ::: "memory");
        }
        __syncthreads();
        const float* Ap = As + st*2560;
        const float* Bp = Bs + st*2176;
#pragma unroll
        for (int k0=0;k0<16;k0+=8){
            unsigned af[2][4];
#pragma unroll
            for (int mt=0;mt<2;mt++){
                int r0 = wm*32 + mt*16;
                af[mt][0] = __float_as_uint(Ap[(r0+g  )*20 + k0 + t4    ]);
                af[mt][1] = __float_as_uint(Ap[(r0+g+8)*20 + k0 + t4    ]);
                af[mt][2] = __float_as_uint(Ap[(r0+g  )*20 + k0 + t4 + 4]);
                af[mt][3] = __float_as_uint(Ap[(r0+g+8)*20 + k0 + t4 + 4]);
            }
#pragma unroll
            for (int nt=0;nt<8;nt++){
                int c0 = wn*64 + nt*8;
                unsigned b0 = __float_as_uint(Bp[(k0+t4  )*136 + c0 + g]);
                unsigned b1 = __float_as_uint(Bp[(k0+t4+4)*136 + c0 + g]);
#pragma unroll
                for (int mt=0;mt<2;mt++){
                    mma8(acc[mt][nt], af[mt], b0, b1);
                }
            }
        }
        __syncthreads();
    }
    // epilogue: store q/k/v pre-rounded to tf32
#pragma unroll
    for (int mt=0;mt<2;mt++)
#pragma unroll
    for (int nt=0;nt<8;nt++){
        int row = rowBase + wm*32 + mt*16 + g;
        int col = colBase + wn*64 + nt*8 + t4*2;
        int b_ = row>>11, t_ = row&2047, h_ = col>>6, d_ = col&63;
        float* p0 = dst + (((size_t)(b_*NH+h_))*NT + t_)*ND + d_;
        *(float2*)p0 = make_float2(tfr(acc[mt][nt][0]), tfr(acc[mt][nt][1]));
        int t2_ = (row+8)&2047;
        float* p1 = dst + (((size_t)(b_*NH+h_))*NT + t2_)*ND + d_;
        *(float2*)p1 = make_float2(tfr(acc[mt][nt][2]), tfr(acc[mt][nt][3]));
    }
}

// ================= K2: per-chunk U_j, KV_j (tensor core, frag reuse), W_j =========
#define P1_SMEM ((4352 + 2*4608)*4)
__global__ void __launch_bounds__(256) k_pass1(const float* __restrict__ pkv)
{
    extern __shared__ float sm1[];
    float* bKT = sm1;          // 64x68 : K^T [d][i] (already tf32)
    float* bV  = sm1 + 4352;   // 64x72 : V  [i][e] (already tf32; later Q)
    float* bVw = sm1 + 4352 + 4608; // 64x72 : gamma^{63-i} V, tf32
    __shared__ float gp[65];
    __shared__ float red[4*64];
    __shared__ float qw[64];
    int tid=threadIdx.x, bid=blockIdx.x;
    int j=bid&31, bh=bid>>5, h=bh&15;
    size_t base = ((size_t)bh*NT + (size_t)j*NC)*ND;
    if (tid<=64){
        double gd = 1.0 - exp2(-5.0-(double)h);
        gp[tid]=(float)pow(gd,(double)tid);
    }
    __syncthreads();
#pragma unroll
    for (int l=0;l<4;l++){
        int idx = tid + l*256;
        int i=idx>>4, d4=(idx&15)*4;
        float4 k4 = *(const float4*)(g_k + base + (size_t)idx*4);
        bKT[(d4  )*68+i]=k4.x;
        bKT[(d4+1)*68+i]=k4.y;
        bKT[(d4+2)*68+i]=k4.z;
        bKT[(d4+3)*68+i]=k4.w;
        float4 v4 = *(const float4*)(g_v + base + (size_t)idx*4);
        *(float4*)(bV + i*72 + d4) = v4;
        float w = gp[63-i];
        bVw[i*72+d4  ]=tfr(v4.x*w);
        bVw[i*72+d4+1]=tfr(v4.y*w);
        bVw[i*72+d4+2]=tfr(v4.z*w);
        bVw[i*72+d4+3]=tfr(v4.w*w);
    }
    __syncthreads();
    const int warp=tid>>5, lane=tid&31;
    const int wm=warp&3, wn=warp>>2, g=lane>>2, t4=lane&3;
    const int m0=wm*16;
    const int r0=m0+g, r1=r0+8;

    unsigned ka[8][4];
#pragma unroll
    for (int k8=0;k8<8;k8++){
        int k=k8*8;
        ka[k8][0]=__float_as_uint(bKT[(m0+g  )*68 + k+t4  ]);
        ka[k8][1]=__float_as_uint(bKT[(m0+g+8)*68 + k+t4  ]);
        ka[k8][2]=__float_as_uint(bKT[(m0+g  )*68 + k+t4+4]);
        ka[k8][3]=__float_as_uint(bKT[(m0+g+8)*68 + k+t4+4]);
    }

    float accKV[4][4]={}, accU[4][4]={};
#pragma unroll
    for (int k8=0;k8<8;k8++){
#pragma unroll
        for (int nt=0;nt<4;nt++){
            int cb=wn*32+nt*8;
            unsigned b0=__float_as_uint(bV [(k8*8+t4  )*72 + cb+g]);
            unsigned b1=__float_as_uint(bV [(k8*8+t4+4)*72 + cb+g]);
            mma8(accKV[nt], ka[k8], b0, b1);
            unsigned c0=__float_as_uint(bVw[(k8*8+t4  )*72 + cb+g]);
            unsigned c1=__float_as_uint(bVw[(k8*8+t4+4)*72 + cb+g]);
            mma8(accU[nt], ka[k8], c0, c1);
        }
    }
    {
        float* Kp = g_kvc + (size_t)bid*4096;
        float* Up = g_U  + (size_t)bid*4096;
#pragma unroll
        for (int nt=0;nt<4;nt++){
            int c0=wn*32+nt*8+t4*2;
            *(float2*)(Kp + r0*64 + c0) = make_float2(accKV[nt][0],accKV[nt][1]);
            *(float2*)(Kp + r1*64 + c0) = make_float2(accKV[nt][2],accKV[nt][3]);
            *(float2*)(Up + r0*64 + c0) = make_float2(accU[nt][0],accU[nt][1]);
            *(float2*)(Up + r1*64 + c0) = make_float2(accU[nt][2],accU[nt][3]);
        }
    }
    __syncthreads();
#pragma unroll
    for (int l=0;l<4;l++){
        int idx=tid+l*256;
        *(float4*)(bV + (idx>>4)*72 + (idx&15)*4) =
            *(const float4*)(g_q + base + (size_t)idx*4);
    }
    __syncthreads();
    int rr = tid>>6, d = tid&63;
    float s = 0.f;
#pragma unroll
    for (int i=rr*16;i<rr*16+16;i++) s += gp[i]*bV[i*72 + d];
    red[rr*64 + d] = s;
    __syncthreads();
    if (tid<64) qw[tid] = red[tid] + red[64+tid] + red[128+tid] + red[192+tid];
    __syncthreads();
    const float* A = pkv + (size_t)h*4096;
    float s2 = 0.f;
#pragma unroll
    for (int dd=rr*16; dd<rr*16+16; dd++) s2 += qw[dd]*A[dd*64 + d];
    red[rr*64 + d] = s2;
    __syncthreads();
    if (tid<64) g_W[(size_t)bid*64 + tid] = red[tid] + red[64+tid] + red[128+tid] + red[192+tid];
}

// ================= K3: chunk scans (4 chains/thread, 4-iter batched loads) ========
__global__ void __launch_bounds__(256) k_scan()
{
    int bh = blockIdx.x, part = blockIdx.y, tid = threadIdx.x;
    int h = bh&15;
    double gd = 1.0 - exp2(-5.0-(double)h);
    float g64 = (float)pow(gd,64.0);
    if (part < 4){
        // forward state scan: 4 chains per thread, load 16 values per burst
        size_t ob = (size_t)bh*NCHK*4096 + (size_t)part*1024 + tid;
        float S[4] = {0.f,0.f,0.f,0.f};
        for (int j=0;j<NCHK;j+=4){
            float u[4][4];
#pragma unroll
            for (int jj=0;jj<4;jj++)
#pragma unroll
                for (int r=0;r<4;r++)
                    u[jj][r] = g_U[ob + (size_t)(j+jj)*4096 + r*256];
#pragma unroll
            for (int jj=0;jj<4;jj++){
#pragma unroll
                for (int r=0;r<4;r++){
                    g_S[ob + (size_t)(j+jj)*4096 + r*256] = tfr(S[r]);
                    S[r] = g64*S[r] + u[jj][r];
                }
            }
        }
    } else {
        // backward suffix carry: dedicated block, batched by 8
        if (tid < 64){
            size_t ob2 = (size_t)bh*NCHK*64 + tid;
            float X = 0.f;
            for (int j=NCHK-8; j>=0; j-=8){
                float w[8];
#pragma unroll
                for (int jj=0;jj<8;jj++) w[jj] = g_W[ob2 + (size_t)(j+jj)*64];
#pragma unroll
                for (int jj=7;jj>=0;jj--){
                    g_Xn[ob2 + (size_t)(j+jj)*64] = X;
                    X = g64*X + w[jj];
                }
            }
        }
    }
}

// ================= K4: per-chunk finalize (tensor core, all operands pre-tf32) ======
#define P3_SMEM ((4352 + 4*4608)*4)
__global__ void __launch_bounds__(256) k_pass3()
{
    extern __shared__ float sm3[];
    float* bQ = sm3;                  // 64x68 : Q [i][d] tf32 -> P tf32
    float* bK = sm3 + 4352;           // 64x72 : K^T [d][s] tf32 -> scan buffer
    float* bS = sm3 + 4352 + 4608;    // 64x72 : S (tf32)
    float* bA = sm3 + 4352 + 2*4608;  // 64x72 : past_kv (tf32)
    float* bV = sm3 + 4352 + 3*4608;  // 64x72 : V (tf32)
    __shared__ float gp[65];
    __shared__ float Xs[64];
    __shared__ float carry[4*64];
    __shared__ float redS[8], redQ[8];
    int tid=threadIdx.x, bid=blockIdx.x;
    int j=bid&31, bh=bid>>5, h=bh&15;
    size_t base=((size_t)bh*NT+(size_t)j*NC)*ND;

    {
        const unsigned sb = (unsigned)__cvta_generic_to_shared(sm3);
        const float* Ssrc = g_S + ((size_t)bh*NCHK+j)*4096;
        const float* Asrc = g_ar + (size_t)h*4096;
        const float* Vsrc = g_v + base;
#pragma unroll
        for (int l=0;l<4;l++){
            int idx=tid+l*256;
            unsigned o = (unsigned)((idx>>4)*72 + (idx&15)*4)*4u;
            CP16(sb + (4352u+  4608u)*4u + o, Ssrc + (size_t)idx*4);
            CP16(sb + (4352u+2*4608u)*4u + o, Asrc + (size_t)idx*4);
            CP16(sb + (4352u+3*4608u)*4u + o, Vsrc + (size_t)idx*4);
        }
        asm volatile("cp.async.commit_group;" ::: "memory");
    }
    if (tid<=64){
        double gd = 1.0 - exp2(-5.0-(double)h);
        gp[tid]=(float)pow(gd,(double)tid);
    }
    if (tid<64) Xs[tid] = g_Xn[((size_t)bh*NCHK+j)*64 + tid];
#pragma unroll
    for (int l=0;l<4;l++){
        int idx=tid+l*256;
        int i=idx>>4, d4=(idx&15)*4;
        float4 q4 = *(const float4*)(g_q + base + (size_t)idx*4);
        *(float4*)(bQ + i*68 + d4) = q4;
        float4 k4 = *(const float4*)(g_k + base + (size_t)idx*4);
        bK[(d4  )*72+i]=k4.x;
        bK[(d4+1)*72+i]=k4.y;
        bK[(d4+2)*72+i]=k4.z;
        bK[(d4+3)*72+i]=k4.w;
    }
    __syncthreads();
    const int warp=tid>>5, lane=tid&31;
    const int wm=warp&3, wn=warp>>2, g=lane>>2, t4=lane&3;
    const int m0=wm*16;
    const int r0=m0+g, r1=r0+8;

    unsigned qa[8][4];
#pragma unroll
    for (int k8=0;k8<8;k8++){
        int k=k8*8;
        qa[k8][0]=__float_as_uint(bQ[(m0+g  )*68 + k+t4  ]);
        qa[k8][1]=__float_as_uint(bQ[(m0+g+8)*68 + k+t4  ]);
        qa[k8][2]=__float_as_uint(bQ[(m0+g  )*68 + k+t4+4]);
        qa[k8][3]=__float_as_uint(bQ[(m0+g+8)*68 + k+t4+4]);
    }
    float accP[4][4]={};
#pragma unroll
    for (int k8=0;k8<8;k8++){
#pragma unroll
        for (int nt=0;nt<4;nt++){
            int cb=wn*32+nt*8;
            unsigned b0=__float_as_uint(bK[(k8*8+t4  )*72 + cb+g]);
            unsigned b1=__float_as_uint(bK[(k8*8+t4+4)*72 + cb+g]);
            mma8(accP[nt], qa[k8], b0, b1);
        }
    }
    asm volatile("cp.async.wait_group 0;" ::: "memory");
    __syncthreads();
    float accQ[4][4]={}, accPP[4][4]={};
#pragma unroll
    for (int k8=0;k8<8;k8++){
#pragma unroll
        for (int nt=0;nt<4;nt++){
            int cb=wn*32+nt*8;
            unsigned b0=__float_as_uint(bS[(k8*8+t4  )*72 + cb+g]);
            unsigned b1=__float_as_uint(bS[(k8*8+t4+4)*72 + cb+g]);
            mma8(accQ[nt], qa[k8], b0, b1);
            unsigned c0=__float_as_uint(bA[(k8*8+t4  )*72 + cb+g]);
            unsigned c1=__float_as_uint(bA[(k8*8+t4+4)*72 + cb+g]);
            mma8(accPP[nt], qa[k8], c0, c1);
        }
    }
#pragma unroll
    for (int nt=0;nt<4;nt++){
        int c0=wn*32+nt*8+t4*2;
        int d00=r0-c0, d01=d00-1, d10=r1-c0, d11=d10-1;
        float p00 = (d00>=0)? accP[nt][0]*gp[d00] : 0.f;
        float p01 = (d01>=0)? accP[nt][1]*gp[d01] : 0.f;
        float p10 = (d10>=0)? accP[nt][2]*gp[d10] : 0.f;
        float p11 = (d11>=0)? accP[nt][3]*gp[d11] : 0.f;
        bQ[r0*68+c0  ]=tfr(p00);
        bQ[r0*68+c0+1]=tfr(p01);
        bQ[r1*68+c0  ]=tfr(p10);
        bQ[r1*68+c0+1]=tfr(p11);
        *(float2*)(bK + r0*72 + c0) = make_float2(accPP[nt][0],accPP[nt][1]);
        *(float2*)(bK + r1*72 + c0) = make_float2(accPP[nt][2],accPP[nt][3]);
        float gq0=gp[r0+1], gq1=gp[r1+1];
        accQ[nt][0]*=gq0; accQ[nt][1]*=gq0;
        accQ[nt][2]*=gq1; accQ[nt][3]*=gq1;
    }
    __syncthreads();
#pragma unroll
    for (int k8=0;k8<8;k8++){
        int k=k8*8;
        unsigned pa[4];
        pa[0]=__float_as_uint(bQ[(m0+g  )*68 + k+t4  ]);
        pa[1]=__float_as_uint(bQ[(m0+g+8)*68 + k+t4  ]);
        pa[2]=__float_as_uint(bQ[(m0+g  )*68 + k+t4+4]);
        pa[3]=__float_as_uint(bQ[(m0+g+8)*68 + k+t4+4]);
#pragma unroll
        for (int nt=0;nt<4;nt++){
            int cb=wn*32+nt*8;
            unsigned b0=__float_as_uint(bV[(k+t4  )*72 + cb+g]);
            unsigned b1=__float_as_uint(bV[(k+t4+4)*72 + cb+g]);
            mma8(accQ[nt], pa, b0, b1);
        }
    }
    {
        int e = tid&63, q = tid>>6;
        float g1 = gp[1];
        float loc[16];
        float c = 0.f;
#pragma unroll
        for (int i=15;i>=0;--i){
            c = bK[(q*16+i)*72 + e] + g1*c;
            loc[i] = c;
        }
        carry[q*64+e] = loc[0];
        __syncthreads();
        float F = 0.f;
        if (q<3) F  = carry[(q+1)*64+e];
        if (q<2) F += gp[16]*carry[(q+2)*64+e];
        if (q<1) F += gp[32]*carry[(q+3)*64+e];
#pragma unroll
        for (int i=0;i<16;i++){
            bK[(q*16+i)*72 + e] = loc[i] + gp[16-i]*F;
        }
    }
    __syncthreads();
    float s1=0.f, s2=0.f;
    float gx0=gp[64-r0], gx1=gp[64-r1];
#pragma unroll
    for (int nt=0;nt<4;nt++){
        int c0=wn*32+nt*8+t4*2;
        float v00 = accQ[nt][0] + bK[r0*72+c0  ] + gx0*Xs[c0  ];
        float v01 = accQ[nt][1] + bK[r0*72+c0+1] + gx0*Xs[c0+1];
        float v10 = accQ[nt][2] + bK[r1*72+c0  ] + gx1*Xs[c0  ];
        float v11 = accQ[nt][3] + bK[r1*72+c0+1] + gx1*Xs[c0+1];
        s1 += v00+v01+v10+v11;
        s2 += v00*v00+v01*v01+v10*v10+v11*v11;
        *(float2*)(g_ret + base + (size_t)r0*64 + c0) = make_float2(v00,v01);
        *(float2*)(g_ret + base + (size_t)r1*64 + c0) = make_float2(v10,v11);
    }
#pragma unroll
    for (int o=16;o>0;o>>=1){
        s1 += __shfl_down_sync(0xffffffffu, s1, o);
        s2 += __shfl_down_sync(0xffffffffu, s2, o);
    }
    if (lane==0){ redS[warp]=s1; redQ[warp]=s2; }
    __syncthreads();
    if (tid==0){
        float a=0.f,bq=0.f;
#pragma unroll
        for (int w=0;w<8;w++){ a+=redS[w]; bq+=redQ[w]; }
        g_stat[(size_t)bid*2  ]=a;
        g_stat[(size_t)bid*2+1]=bq;
    }
}

// ================= K5: per-batch GroupNorm stats =================
__global__ void __launch_bounds__(512) k_stats()
{
    __shared__ float r1[512], r2[512];
    int b=blockIdx.x, tid=threadIdx.x;
    r1[tid]=g_stat[(size_t)(b*512+tid)*2];
    r2[tid]=g_stat[(size_t)(b*512+tid)*2+1];
    __syncthreads();
    for (int o=256;o>0;o>>=1){
        if (tid<o){ r1[tid]+=r1[tid+o]; r2[tid]+=r2[tid+o]; }
        __syncthreads();
    }
    if (tid==0){
        const float N = (float)((size_t)NH*NT*ND);
        float mu = r1[0]/N;
        float var = r2[0]/N - mu*mu;
        g_norm[b*2]=mu;
        g_norm[b*2+1]=rsqrtf(var+1e-5f);
    }
}

// ================= K6: normalize + layout to [B,T,NE] =================
__global__ void __launch_bounds__(256) k_out(const float* __restrict__ gnw,
                                             const float* __restrict__ gnb,
                                             float* __restrict__ out)
{
    int bid=blockIdx.x;
    int b=bid>>11, t=bid&2047;
    int tid=threadIdx.x;
    int h=tid>>4, d4=(tid&15)*4;
    float mu=g_norm[b*2], rs=g_norm[b*2+1];
    float w = gnw[h]*rs;
    float bb = gnb[h] - mu*w;
    float4 xv = *(const float4*)(g_ret + (((size_t)(b*NH+h))*NT + t)*ND + d4);
    float4 yv = make_float4(xv.x*w+bb, xv.y*w+bb, xv.z*w+bb, xv.w*w+bb);
    *(float4*)(out + (size_t)bid*NE + h*ND + d4) = yv;
}

// ================= K7: kv reduce + decay =================
__global__ void __launch_bounds__(256) k_kvout(const float* __restrict__ pkv,
                                               float* __restrict__ out_kv)
{
    int h=blockIdx.x;
    int idx=blockIdx.y*256+threadIdx.x;
    float s=0.f;
    for (int b=0;b<NB;b++){
        size_t bh=((size_t)(b*NH+h))*NCHK;
        for (int j2=0;j2<NCHK;j2++) s += g_kvc[(bh+j2)*4096 + idx];
    }
    double gd = 1.0 - exp2(-5.0-(double)h);
    out_kv[(size_t)h*4096 + idx] = (float)gd*pkv[(size_t)h*4096 + idx] + 0.25f*s;
}

extern "C" void kernel_launch(void* const* d_in, const int* in_sizes, int n_in,
                              void* d_out, int out_size)
{
    const float* x   = (const float*)d_in[0];
    const float* pkv = (const float*)d_in[1];
    const float* Wq  = (const float*)d_in[2];
    const float* Wk  = (const float*)d_in[3];
    const float* Wv  = (const float*)d_in[4];
    const float* gnw = (const float*)d_in[5];
    const float* gnb = (const float*)d_in[6];
    float* out = (float*)d_out;

    cudaFuncSetAttribute(k_proj3, cudaFuncAttributeMaxDynamicSharedMemorySize, PROJ_SMEM);
    cudaFuncSetAttribute(k_pass1, cudaFuncAttributeMaxDynamicSharedMemorySize, P1_SMEM);
    cudaFuncSetAttribute(k_pass3, cudaFuncAttributeMaxDynamicSharedMemorySize, P3_SMEM);

    k_cvt<<<(NX4 + 3*NW4 + NA4 + 255)/256, 256>>>(x, Wq, Wk, Wv, pkv);
    dim3 gproj(8, 64, 3);
    k_proj3<<<gproj, 256, PROJ_SMEM>>>();
    k_pass1<<<NBH*NCHK, 256, P1_SMEM>>>(pkv);
    dim3 gscan(NBH, 5);
    k_scan<<<gscan, 256>>>();
    k_pass3<<<NBH*NCHK, 256, P3_SMEM>>>();
    k_stats<<<NB, 512>>>();
    k_out<<<NB*NT, 256>>>(gnw, gnb, out);
    dim3 gkv(NH, 16);
    k_kvout<<<gkv, 256>>>(pkv, out + (size_t)NB*NT*NE);
}

// round 11
// speedup vs baseline: 1.3055x; 1.0053x over previous
#include <cuda_runtime.h>
#include <math.h>
#include <stdint.h>

#define NB 4
#define NT 2048
#define NH 16
#define ND 64
#define NE 1024
#define NC 64
#define NCHK 32
#define NBH (NB*NH)

// ---------------- scratch (device globals; no runtime allocation) ----------------
__device__ float g_q  [(size_t)NB*NH*NT*ND];
__device__ float g_k  [(size_t)NB*NH*NT*ND];
__device__ float g_v  [(size_t)NB*NH*NT*ND];
__device__ float g_ret[(size_t)NB*NH*NT*ND];
__device__ float g_U  [(size_t)NBH*NCHK*ND*ND];
__device__ float g_S  [(size_t)NBH*NCHK*ND*ND];
__device__ float g_kvc[(size_t)NBH*NCHK*ND*ND];
__device__ float g_W  [(size_t)NBH*NCHK*ND];
__device__ float g_Xn [(size_t)NBH*NCHK*ND];
__device__ float g_stat[(size_t)NBH*NCHK*2];
__device__ float g_norm[NB*2];
__device__ float g_xr [(size_t)NB*NT*NE];    // tf32-rounded X
__device__ float g_wr [(size_t)3*NE*NE];     // tf32-rounded Wq,Wk,Wv
__device__ float g_ar [(size_t)NH*ND*ND];    // tf32-rounded past_kv

__device__ __forceinline__ unsigned f2tf(float x){
    unsigned r;
    asm("cvt.rna.tf32.f32 %0, %1;" : "=r"(r) : "f"(x));
    return r;
}
__device__ __forceinline__ float tfr(float x){
    return __uint_as_float(f2tf(x));
}
__device__ __forceinline__ void mma8(float c[4], const unsigned a[4], unsigned b0, unsigned b1){
    asm volatile(
      "mma.sync.aligned.m16n8k8.row.col.f32.tf32.tf32.f32 "
      "{%0,%1,%2,%3},{%4,%5,%6,%7},{%8,%9},{%0,%1,%2,%3};"
      : "+f"(c[0]),"+f"(c[1]),"+f"(c[2]),"+f"(c[3])
      : "r"(a[0]),"r"(a[1]),"r"(a[2]),"r"(a[3]), "r"(b0),"r"(b1));
}

#define CP16(dst_u32, src) \
    asm volatile("cp.async.ca.shared.global [%0], [%1], 16;" :: "r"(dst_u32), "l"(src))

// ================= K0: pre-round X, W, past_kv to tf32 =================
#define NX4 ((NB*NT*NE)/4)       // 2097152
#define NW4 ((NE*NE)/4)          // 262144
#define NA4 ((NH*ND*ND)/4)       // 16384
__global__ void __launch_bounds__(256) k_cvt(const float* __restrict__ X,
                                             const float* __restrict__ Wq,
                                             const float* __restrict__ Wk,
                                             const float* __restrict__ Wv,
                                             const float* __restrict__ pkv)
{
    int i = blockIdx.x*256 + threadIdx.x;
    const float4* src;
    float4* dst;
    int off;
    if (i < NX4){
        src = (const float4*)X; dst = (float4*)g_xr; off = i;
    } else if (i < NX4 + 3*NW4){
        int i2 = i - NX4;
        int sel = i2 / NW4; off = i2 - sel*NW4;
        src = (const float4*)((sel==0)?Wq:(sel==1)?Wk:Wv);
        dst = (float4*)(g_wr + (size_t)sel*NE*NE);
    } else {
        off = i - NX4 - 3*NW4;
        if (off >= NA4) return;
        src = (const float4*)pkv; dst = (float4*)g_ar;
    }
    float4 v = src[off];
    v.x=tfr(v.x); v.y=tfr(v.y); v.z=tfr(v.z); v.w=tfr(v.w);
    dst[off] = v;
}

// ================= K1: fused QKV projection (TF32 mma, 128x128, 3-stage, 1 barrier/iter) ===
#define PROJ_SMEM (3*(2560+2176)*4)
__global__ void __launch_bounds__(256) k_proj3()
{
    const int sel = blockIdx.z;
    const float* X = g_xr;
    const float* W = g_wr + (size_t)sel*NE*NE;
    float* dst = (sel==0)?g_q:(sel==1)?g_k:g_v;

    extern __shared__ float dsm[];
    float* As = dsm;            // 3 stages of 128*20
    float* Bs = dsm + 3*2560;   // 3 stages of 16*136

    const int tid = threadIdx.x;
    const int rowBase = blockIdx.y*128, colBase = blockIdx.x*128;
    const int warp = tid>>5, lane = tid&31;
    const int wm = warp&3, wn = warp>>2;
    const int g = lane>>2, t4 = lane&3;

    const int ar0 = tid>>2, ac0 = (tid&3)*4;
    const int br0 = tid>>5, bc0 = (tid&31)*4;

    const unsigned sA = (unsigned)__cvta_generic_to_shared(As);
    const unsigned sB = (unsigned)__cvta_generic_to_shared(Bs);
    const unsigned stA = 2560u*4u, stB = 2176u*4u;

    float acc[2][8][4];
#pragma unroll
    for (int a=0;a<2;a++)
#pragma unroll
      for (int b=0;b<8;b++)
#pragma unroll
        for (int c=0;c<4;c++) acc[a][b][c]=0.f;

    auto issue = [&](int it, int st){
        int kb = it*16;
        const float* xs = X + (size_t)rowBase*NE + kb;
        CP16(sA + st*stA + (unsigned)((ar0    )*20 + ac0)*4u, xs + (size_t)(ar0    )*NE + ac0);
        CP16(sA + st*stA + (unsigned)((ar0+64 )*20 + ac0)*4u, xs + (size_t)(ar0+64 )*NE + ac0);
        const float* ws = W + (size_t)kb*NE + colBase;
        CP16(sB + st*stB + (unsigned)((br0   )*136 + bc0)*4u, ws + (size_t)(br0   )*NE + bc0);
        CP16(sB + st*stB + (unsigned)((br0+8 )*136 + bc0)*4u, ws + (size_t)(br0+8 )*NE + bc0);
        asm volatile("cp.async.commit_group;" ::: "memory");
    };

    const int NIT = NE/16;
    issue(0,0); issue(1,1);
    for (int it=0; it<NIT; it++){
        const int st = it%3;
        if (it+1<NIT){
            asm volatile("cp.async.wait_group 1;" ::: "memory");
        } else {
            asm volatile("cp.async.wait_group 0;" ::: "memory");
        }
        __syncthreads();
        // barrier above ordered all reads of stage (it-1) == (it+2)%3; safe to refill
        if (it+2<NIT) issue(it+2, (it+2)%3);
        const float* Ap = As + st*2560;
        const float* Bp = Bs + st*2176;
#pragma unroll
        for (int k0=0;k0<16;k0+=8){
            unsigned af[2][4];
#pragma unroll
            for (int mt=0;mt<2;mt++){
                int r0 = wm*32 + mt*16;
                af[mt][0] = __float_as_uint(Ap[(r0+g  )*20 + k0 + t4    ]);
                af[mt][1] = __float_as_uint(Ap[(r0+g+8)*20 + k0 + t4    ]);
                af[mt][2] = __float_as_uint(Ap[(r0+g  )*20 + k0 + t4 + 4]);
                af[mt][3] = __float_as_uint(Ap[(r0+g+8)*20 + k0 + t4 + 4]);
            }
#pragma unroll
            for (int nt=0;nt<8;nt++){
                int c0 = wn*64 + nt*8;
                unsigned b0 = __float_as_uint(Bp[(k0+t4  )*136 + c0 + g]);
                unsigned b1 = __float_as_uint(Bp[(k0+t4+4)*136 + c0 + g]);
#pragma unroll
                for (int mt=0;mt<2;mt++){
                    mma8(acc[mt][nt], af[mt], b0, b1);
                }
            }
        }
    }
    // epilogue: store q/k/v pre-rounded to tf32
#pragma unroll
    for (int mt=0;mt<2;mt++)
#pragma unroll
    for (int nt=0;nt<8;nt++){
        int row = rowBase + wm*32 + mt*16 + g;
        int col = colBase + wn*64 + nt*8 + t4*2;
        int b_ = row>>11, t_ = row&2047, h_ = col>>6, d_ = col&63;
        float* p0 = dst + (((size_t)(b_*NH+h_))*NT + t_)*ND + d_;
        *(float2*)p0 = make_float2(tfr(acc[mt][nt][0]), tfr(acc[mt][nt][1]));
        int t2_ = (row+8)&2047;
        float* p1 = dst + (((size_t)(b_*NH+h_))*NT + t2_)*ND + d_;
        *(float2*)p1 = make_float2(tfr(acc[mt][nt][2]), tfr(acc[mt][nt][3]));
    }
}

// ================= K2: per-chunk U_j, KV_j (tensor core, frag reuse), W_j =========
#define P1_SMEM ((4352 + 2*4608)*4)
__global__ void __launch_bounds__(256) k_pass1(const float* __restrict__ pkv)
{
    extern __shared__ float sm1[];
    float* bKT = sm1;          // 64x68 : K^T [d][i] (already tf32)
    float* bV  = sm1 + 4352;   // 64x72 : V  [i][e] (already tf32; later Q)
    float* bVw = sm1 + 4352 + 4608; // 64x72 : gamma^{63-i} V, tf32
    __shared__ float gp[65];
    __shared__ float red[4*64];
    __shared__ float qw[64];
    int tid=threadIdx.x, bid=blockIdx.x;
    int j=bid&31, bh=bid>>5, h=bh&15;
    size_t base = ((size_t)bh*NT + (size_t)j*NC)*ND;
    if (tid<=64){
        double gd = 1.0 - exp2(-5.0-(double)h);
        gp[tid]=(float)pow(gd,(double)tid);
    }
    __syncthreads();
#pragma unroll
    for (int l=0;l<4;l++){
        int idx = tid + l*256;
        int i=idx>>4, d4=(idx&15)*4;
        float4 k4 = *(const float4*)(g_k + base + (size_t)idx*4);
        bKT[(d4  )*68+i]=k4.x;
        bKT[(d4+1)*68+i]=k4.y;
        bKT[(d4+2)*68+i]=k4.z;
        bKT[(d4+3)*68+i]=k4.w;
        float4 v4 = *(const float4*)(g_v + base + (size_t)idx*4);
        *(float4*)(bV + i*72 + d4) = v4;
        float w = gp[63-i];
        bVw[i*72+d4  ]=tfr(v4.x*w);
        bVw[i*72+d4+1]=tfr(v4.y*w);
        bVw[i*72+d4+2]=tfr(v4.z*w);
        bVw[i*72+d4+3]=tfr(v4.w*w);
    }
    __syncthreads();
    const int warp=tid>>5, lane=tid&31;
    const int wm=warp&3, wn=warp>>2, g=lane>>2, t4=lane&3;
    const int m0=wm*16;
    const int r0=m0+g, r1=r0+8;

    unsigned ka[8][4];
#pragma unroll
    for (int k8=0;k8<8;k8++){
        int k=k8*8;
        ka[k8][0]=__float_as_uint(bKT[(m0+g  )*68 + k+t4  ]);
        ka[k8][1]=__float_as_uint(bKT[(m0+g+8)*68 + k+t4  ]);
        ka[k8][2]=__float_as_uint(bKT[(m0+g  )*68 + k+t4+4]);
        ka[k8][3]=__float_as_uint(bKT[(m0+g+8)*68 + k+t4+4]);
    }

    float accKV[4][4]={}, accU[4][4]={};
#pragma unroll
    for (int k8=0;k8<8;k8++){
#pragma unroll
        for (int nt=0;nt<4;nt++){
            int cb=wn*32+nt*8;
            unsigned b0=__float_as_uint(bV [(k8*8+t4  )*72 + cb+g]);
            unsigned b1=__float_as_uint(bV [(k8*8+t4+4)*72 + cb+g]);
            mma8(accKV[nt], ka[k8], b0, b1);
            unsigned c0=__float_as_uint(bVw[(k8*8+t4  )*72 + cb+g]);
            unsigned c1=__float_as_uint(bVw[(k8*8+t4+4)*72 + cb+g]);
            mma8(accU[nt], ka[k8], c0, c1);
        }
    }
    {
        float* Kp = g_kvc + (size_t)bid*4096;
        float* Up = g_U  + (size_t)bid*4096;
#pragma unroll
        for (int nt=0;nt<4;nt++){
            int c0=wn*32+nt*8+t4*2;
            *(float2*)(Kp + r0*64 + c0) = make_float2(accKV[nt][0],accKV[nt][1]);
            *(float2*)(Kp + r1*64 + c0) = make_float2(accKV[nt][2],accKV[nt][3]);
            *(float2*)(Up + r0*64 + c0) = make_float2(accU[nt][0],accU[nt][1]);
            *(float2*)(Up + r1*64 + c0) = make_float2(accU[nt][2],accU[nt][3]);
        }
    }
    __syncthreads();
#pragma unroll
    for (int l=0;l<4;l++){
        int idx=tid+l*256;
        *(float4*)(bV + (idx>>4)*72 + (idx&15)*4) =
            *(const float4*)(g_q + base + (size_t)idx*4);
    }
    __syncthreads();
    int rr = tid>>6, d = tid&63;
    float s = 0.f;
#pragma unroll
    for (int i=rr*16;i<rr*16+16;i++) s += gp[i]*bV[i*72 + d];
    red[rr*64 + d] = s;
    __syncthreads();
    if (tid<64) qw[tid] = red[tid] + red[64+tid] + red[128+tid] + red[192+tid];
    __syncthreads();
    const float* A = pkv + (size_t)h*4096;
    float s2 = 0.f;
#pragma unroll
    for (int dd=rr*16; dd<rr*16+16; dd++) s2 += qw[dd]*A[dd*64 + d];
    red[rr*64 + d] = s2;
    __syncthreads();
    if (tid<64) g_W[(size_t)bid*64 + tid] = red[tid] + red[64+tid] + red[128+tid] + red[192+tid];
}

// ================= K3: chunk scans (4 chains/thread, 8-iter batched loads) ========
__global__ void __launch_bounds__(256) k_scan()
{
    int bh = blockIdx.x, part = blockIdx.y, tid = threadIdx.x;
    int h = bh&15;
    double gd = 1.0 - exp2(-5.0-(double)h);
    float g64 = (float)pow(gd,64.0);
    if (part < 4){
        // forward state scan: 4 chains per thread, 32 loads in flight per burst
        size_t ob = (size_t)bh*NCHK*4096 + (size_t)part*1024 + tid;
        float S[4] = {0.f,0.f,0.f,0.f};
        for (int j=0;j<NCHK;j+=8){
            float u[8][4];
#pragma unroll
            for (int jj=0;jj<8;jj++)
#pragma unroll
                for (int r=0;r<4;r++)
                    u[jj][r] = g_U[ob + (size_t)(j+jj)*4096 + r*256];
#pragma unroll
            for (int jj=0;jj<8;jj++){
#pragma unroll
                for (int r=0;r<4;r++){
                    g_S[ob + (size_t)(j+jj)*4096 + r*256] = tfr(S[r]);
                    S[r] = g64*S[r] + u[jj][r];
                }
            }
        }
    } else {
        // backward suffix carry: dedicated block, batched by 8
        if (tid < 64){
            size_t ob2 = (size_t)bh*NCHK*64 + tid;
            float X = 0.f;
            for (int j=NCHK-8; j>=0; j-=8){
                float w[8];
#pragma unroll
                for (int jj=0;jj<8;jj++) w[jj] = g_W[ob2 + (size_t)(j+jj)*64];
#pragma unroll
                for (int jj=7;jj>=0;jj--){
                    g_Xn[ob2 + (size_t)(j+jj)*64] = X;
                    X = g64*X + w[jj];
                }
            }
        }
    }
}

// ================= K4: per-chunk finalize (tensor core, all operands pre-tf32) ======
#define P3_SMEM ((4352 + 4*4608)*4)
__global__ void __launch_bounds__(256) k_pass3()
{
    extern __shared__ float sm3[];
    float* bQ = sm3;                  // 64x68 : Q [i][d] tf32 -> P tf32
    float* bK = sm3 + 4352;           // 64x72 : K^T [d][s] tf32 -> scan buffer
    float* bS = sm3 + 4352 + 4608;    // 64x72 : S (tf32)
    float* bA = sm3 + 4352 + 2*4608;  // 64x72 : past_kv (tf32)
    float* bV = sm3 + 4352 + 3*4608;  // 64x72 : V (tf32)
    __shared__ float gp[65];
    __shared__ float Xs[64];
    __shared__ float carry[4*64];
    __shared__ float redS[8], redQ[8];
    int tid=threadIdx.x, bid=blockIdx.x;
    int j=bid&31, bh=bid>>5, h=bh&15;
    size_t base=((size_t)bh*NT+(size_t)j*NC)*ND;

    {
        const unsigned sb = (unsigned)__cvta_generic_to_shared(sm3);
        const float* Ssrc = g_S + ((size_t)bh*NCHK+j)*4096;
        const float* Asrc = g_ar + (size_t)h*4096;
        const float* Vsrc = g_v + base;
#pragma unroll
        for (int l=0;l<4;l++){
            int idx=tid+l*256;
            unsigned o = (unsigned)((idx>>4)*72 + (idx&15)*4)*4u;
            CP16(sb + (4352u+  4608u)*4u + o, Ssrc + (size_t)idx*4);
            CP16(sb + (4352u+2*4608u)*4u + o, Asrc + (size_t)idx*4);
            CP16(sb + (4352u+3*4608u)*4u + o, Vsrc + (size_t)idx*4);
        }
        asm volatile("cp.async.commit_group;" ::: "memory");
    }
    if (tid<=64){
        double gd = 1.0 - exp2(-5.0-(double)h);
        gp[tid]=(float)pow(gd,(double)tid);
    }
    if (tid<64) Xs[tid] = g_Xn[((size_t)bh*NCHK+j)*64 + tid];
#pragma unroll
    for (int l=0;l<4;l++){
        int idx=tid+l*256;
        int i=idx>>4, d4=(idx&15)*4;
        float4 q4 = *(const float4*)(g_q + base + (size_t)idx*4);
        *(float4*)(bQ + i*68 + d4) = q4;
        float4 k4 = *(const float4*)(g_k + base + (size_t)idx*4);
        bK[(d4  )*72+i]=k4.x;
        bK[(d4+1)*72+i]=k4.y;
        bK[(d4+2)*72+i]=k4.z;
        bK[(d4+3)*72+i]=k4.w;
    }
    __syncthreads();
    const int warp=tid>>5, lane=tid&31;
    const int wm=warp&3, wn=warp>>2, g=lane>>2, t4=lane&3;
    const int m0=wm*16;
    const int r0=m0+g, r1=r0+8;

    unsigned qa[8][4];
#pragma unroll
    for (int k8=0;k8<8;k8++){
        int k=k8*8;
        qa[k8][0]=__float_as_uint(bQ[(m0+g  )*68 + k+t4  ]);
        qa[k8][1]=__float_as_uint(bQ[(m0+g+8)*68 + k+t4  ]);
        qa[k8][2]=__float_as_uint(bQ[(m0+g  )*68 + k+t4+4]);
        qa[k8][3]=__float_as_uint(bQ[(m0+g+8)*68 + k+t4+4]);
    }
    float accP[4][4]={};
#pragma unroll
    for (int k8=0;k8<8;k8++){
#pragma unroll
        for (int nt=0;nt<4;nt++){
            int cb=wn*32+nt*8;
            unsigned b0=__float_as_uint(bK[(k8*8+t4  )*72 + cb+g]);
            unsigned b1=__float_as_uint(bK[(k8*8+t4+4)*72 + cb+g]);
            mma8(accP[nt], qa[k8], b0, b1);
        }
    }
    asm volatile("cp.async.wait_group 0;" ::: "memory");
    __syncthreads();
    float accQ[4][4]={}, accPP[4][4]={};
#pragma unroll
    for (int k8=0;k8<8;k8++){
#pragma unroll
        for (int nt=0;nt<4;nt++){
            int cb=wn*32+nt*8;
            unsigned b0=__float_as_uint(bS[(k8*8+t4  )*72 + cb+g]);
            unsigned b1=__float_as_uint(bS[(k8*8+t4+4)*72 + cb+g]);
            mma8(accQ[nt], qa[k8], b0, b1);
            unsigned c0=__float_as_uint(bA[(k8*8+t4  )*72 + cb+g]);
            unsigned c1=__float_as_uint(bA[(k8*8+t4+4)*72 + cb+g]);
            mma8(accPP[nt], qa[k8], c0, c1);
        }
    }
#pragma unroll
    for (int nt=0;nt<4;nt++){
        int c0=wn*32+nt*8+t4*2;
        int d00=r0-c0, d01=d00-1, d10=r1-c0, d11=d10-1;
        float p00 = (d00>=0)? accP[nt][0]*gp[d00] : 0.f;
        float p01 = (d01>=0)? accP[nt][1]*gp[d01] : 0.f;
        float p10 = (d10>=0)? accP[nt][2]*gp[d10] : 0.f;
        float p11 = (d11>=0)? accP[nt][3]*gp[d11] : 0.f;
        bQ[r0*68+c0  ]=tfr(p00);
        bQ[r0*68+c0+1]=tfr(p01);
        bQ[r1*68+c0  ]=tfr(p10);
        bQ[r1*68+c0+1]=tfr(p11);
        *(float2*)(bK + r0*72 + c0) = make_float2(accPP[nt][0],accPP[nt][1]);
        *(float2*)(bK + r1*72 + c0) = make_float2(accPP[nt][2],accPP[nt][3]);
        float gq0=gp[r0+1], gq1=gp[r1+1];
        accQ[nt][0]*=gq0; accQ[nt][1]*=gq0;
        accQ[nt][2]*=gq1; accQ[nt][3]*=gq1;
    }
    __syncthreads();
#pragma unroll
    for (int k8=0;k8<8;k8++){
        int k=k8*8;
        unsigned pa[4];
        pa[0]=__float_as_uint(bQ[(m0+g  )*68 + k+t4  ]);
        pa[1]=__float_as_uint(bQ[(m0+g+8)*68 + k+t4  ]);
        pa[2]=__float_as_uint(bQ[(m0+g  )*68 + k+t4+4]);
        pa[3]=__float_as_uint(bQ[(m0+g+8)*68 + k+t4+4]);
#pragma unroll
        for (int nt=0;nt<4;nt++){
            int cb=wn*32+nt*8;
            unsigned b0=__float_as_uint(bV[(k+t4  )*72 + cb+g]);
            unsigned b1=__float_as_uint(bV[(k+t4+4)*72 + cb+g]);
            mma8(accQ[nt], pa, b0, b1);
        }
    }
    {
        int e = tid&63, q = tid>>6;
        float g1 = gp[1];
        float loc[16];
        float c = 0.f;
#pragma unroll
        for (int i=15;i>=0;--i){
            c = bK[(q*16+i)*72 + e] + g1*c;
            loc[i] = c;
        }
        carry[q*64+e] = loc[0];
        __syncthreads();
        float F = 0.f;
        if (q<3) F  = carry[(q+1)*64+e];
        if (q<2) F += gp[16]*carry[(q+2)*64+e];
        if (q<1) F += gp[32]*carry[(q+3)*64+e];
#pragma unroll
        for (int i=0;i<16;i++){
            bK[(q*16+i)*72 + e] = loc[i] + gp[16-i]*F;
        }
    }
    __syncthreads();
    float s1=0.f, s2=0.f;
    float gx0=gp[64-r0], gx1=gp[64-r1];
#pragma unroll
    for (int nt=0;nt<4;nt++){
        int c0=wn*32+nt*8+t4*2;
        float v00 = accQ[nt][0] + bK[r0*72+c0  ] + gx0*Xs[c0  ];
        float v01 = accQ[nt][1] + bK[r0*72+c0+1] + gx0*Xs[c0+1];
        float v10 = accQ[nt][2] + bK[r1*72+c0  ] + gx1*Xs[c0  ];
        float v11 = accQ[nt][3] + bK[r1*72+c0+1] + gx1*Xs[c0+1];
        s1 += v00+v01+v10+v11;
        s2 += v00*v00+v01*v01+v10*v10+v11*v11;
        *(float2*)(g_ret + base + (size_t)r0*64 + c0) = make_float2(v00,v01);
        *(float2*)(g_ret + base + (size_t)r1*64 + c0) = make_float2(v10,v11);
    }
#pragma unroll
    for (int o=16;o>0;o>>=1){
        s1 += __shfl_down_sync(0xffffffffu, s1, o);
        s2 += __shfl_down_sync(0xffffffffu, s2, o);
    }
    if (lane==0){ redS[warp]=s1; redQ[warp]=s2; }
    __syncthreads();
    if (tid==0){
        float a=0.f,bq=0.f;
#pragma unroll
        for (int w=0;w<8;w++){ a+=redS[w]; bq+=redQ[w]; }
        g_stat[(size_t)bid*2  ]=a;
        g_stat[(size_t)bid*2+1]=bq;
    }
}

// ================= K5: per-batch GroupNorm stats =================
__global__ void __launch_bounds__(512) k_stats()
{
    __shared__ float r1[512], r2[512];
    int b=blockIdx.x, tid=threadIdx.x;
    r1[tid]=g_stat[(size_t)(b*512+tid)*2];
    r2[tid]=g_stat[(size_t)(b*512+tid)*2+1];
    __syncthreads();
    for (int o=256;o>0;o>>=1){
        if (tid<o){ r1[tid]+=r1[tid+o]; r2[tid]+=r2[tid+o]; }
        __syncthreads();
    }
    if (tid==0){
        const float N = (float)((size_t)NH*NT*ND);
        float mu = r1[0]/N;
        float var = r2[0]/N - mu*mu;
        g_norm[b*2]=mu;
        g_norm[b*2+1]=rsqrtf(var+1e-5f);
    }
}

// ================= K6: normalize + layout to [B,T,NE] =================
__global__ void __launch_bounds__(256) k_out(const float* __restrict__ gnw,
                                             const float* __restrict__ gnb,
                                             float* __restrict__ out)
{
    int bid=blockIdx.x;
    int b=bid>>11, t=bid&2047;
    int tid=threadIdx.x;
    int h=tid>>4, d4=(tid&15)*4;
    float mu=g_norm[b*2], rs=g_norm[b*2+1];
    float w = gnw[h]*rs;
    float bb = gnb[h] - mu*w;
    float4 xv = *(const float4*)(g_ret + (((size_t)(b*NH+h))*NT + t)*ND + d4);
    float4 yv = make_float4(xv.x*w+bb, xv.y*w+bb, xv.z*w+bb, xv.w*w+bb);
    *(float4*)(out + (size_t)bid*NE + h*ND + d4) = yv;
}

// ================= K7: kv reduce + decay =================
__global__ void __launch_bounds__(256) k_kvout(const float* __restrict__ pkv,
                                               float* __restrict__ out_kv)
{
    int h=blockIdx.x;
    int idx=blockIdx.y*256+threadIdx.x;
    float s=0.f;
    for (int b=0;b<NB;b++){
        size_t bh=((size_t)(b*NH+h))*NCHK;
        for (int j2=0;j2<NCHK;j2++) s += g_kvc[(bh+j2)*4096 + idx];
    }
    double gd = 1.0 - exp2(-5.0-(double)h);
    out_kv[(size_t)h*4096 + idx] = (float)gd*pkv[(size_t)h*4096 + idx] + 0.25f*s;
}

extern "C" void kernel_launch(void* const* d_in, const int* in_sizes, int n_in,
                              void* d_out, int out_size)
{
    const float* x   = (const float*)d_in[0];
    const float* pkv = (const float*)d_in[1];
    const float* Wq  = (const float*)d_in[2];
    const float* Wk  = (const float*)d_in[3];
    const float* Wv  = (const float*)d_in[4];
    const float* gnw = (const float*)d_in[5];
    const float* gnb = (const float*)d_in[6];
    float* out = (float*)d_out;

    cudaFuncSetAttribute(k_proj3, cudaFuncAttributeMaxDynamicSharedMemorySize, PROJ_SMEM);
    cudaFuncSetAttribute(k_pass1, cudaFuncAttributeMaxDynamicSharedMemorySize, P1_SMEM);
    cudaFuncSetAttribute(k_pass3, cudaFuncAttributeMaxDynamicSharedMemorySize, P3_SMEM);

    k_cvt<<<(NX4 + 3*NW4 + NA4 + 255)/256, 256>>>(x, Wq, Wk, Wv, pkv);
    dim3 gproj(8, 64, 3);
    k_proj3<<<gproj, 256, PROJ_SMEM>>>();
    k_pass1<<<NBH*NCHK, 256, P1_SMEM>>>(pkv);
    dim3 gscan(NBH, 5);
    k_scan<<<gscan, 256>>>();
    k_pass3<<<NBH*NCHK, 256, P3_SMEM>>>();
    k_stats<<<NB, 512>>>();
    k_out<<<NB*NT, 256>>>(gnw, gnb, out);
    dim3 gkv(NH, 16);
    k_kvout<<<gkv, 256>>>(pkv, out + (size_t)NB*NT*NE);
}

// round 12
// speedup vs baseline: 1.5504x; 1.1876x over previous
#include <cuda_runtime.h>
#include <cuda_fp16.h>
#include <math.h>
#include <stdint.h>

#define NB 4
#define NT 2048
#define NH 16
#define ND 64
#define NE 1024
#define NC 64
#define NCHK 32
#define NBH (NB*NH)

// ---------------- scratch (device globals; no runtime allocation) ----------------
__device__ float g_q  [(size_t)NB*NH*NT*ND];
__device__ float g_k  [(size_t)NB*NH*NT*ND];
__device__ float g_v  [(size_t)NB*NH*NT*ND];
__device__ float g_ret[(size_t)NB*NH*NT*ND];
__device__ float g_U  [(size_t)NBH*NCHK*ND*ND];
__device__ float g_S  [(size_t)NBH*NCHK*ND*ND];
__device__ float g_kvc[(size_t)NBH*NCHK*ND*ND];
__device__ float g_W  [(size_t)NBH*NCHK*ND];
__device__ float g_Xn [(size_t)NBH*NCHK*ND];
__device__ float g_stat[(size_t)NBH*NCHK*2];
__device__ float g_norm[NB*2];
__device__ __half g_xh [(size_t)NB*NT*NE];    // fp16 X
__device__ __half g_wh [(size_t)3*NE*NE];     // fp16 W^T (layout [n][k])
__device__ float  g_ar [(size_t)NH*ND*ND];    // tf32-rounded past_kv

__device__ __forceinline__ unsigned f2tf(float x){
    unsigned r;
    asm("cvt.rna.tf32.f32 %0, %1;" : "=r"(r) : "f"(x));
    return r;
}
__device__ __forceinline__ float tfr(float x){
    return __uint_as_float(f2tf(x));
}
__device__ __forceinline__ void mma8(float c[4], const unsigned a[4], unsigned b0, unsigned b1){
    asm volatile(
      "mma.sync.aligned.m16n8k8.row.col.f32.tf32.tf32.f32 "
      "{%0,%1,%2,%3},{%4,%5,%6,%7},{%8,%9},{%0,%1,%2,%3};"
      : "+f"(c[0]),"+f"(c[1]),"+f"(c[2]),"+f"(c[3])
      : "r"(a[0]),"r"(a[1]),"r"(a[2]),"r"(a[3]), "r"(b0),"r"(b1));
}
__device__ __forceinline__ void mma16(float c[4], const unsigned a[4], unsigned b0, unsigned b1){
    asm volatile(
      "mma.sync.aligned.m16n8k16.row.col.f32.f16.f16.f32 "
      "{%0,%1,%2,%3},{%4,%5,%6,%7},{%8,%9},{%0,%1,%2,%3};"
      : "+f"(c[0]),"+f"(c[1]),"+f"(c[2]),"+f"(c[3])
      : "r"(a[0]),"r"(a[1]),"r"(a[2]),"r"(a[3]), "r"(b0),"r"(b1));
}

#define CP16(dst_u32, src) \
    asm volatile("cp.async.ca.shared.global [%0], [%1], 16;" :: "r"(dst_u32), "l"(src))

// ================= K0a: X -> fp16, past_kv -> tf32 =================
#define NX4 ((NB*NT*NE)/4)       // 2097152
#define NA4 ((NH*ND*ND)/4)       // 16384
__global__ void __launch_bounds__(256) k_cvtx(const float* __restrict__ X,
                                              const float* __restrict__ pkv)
{
    int i = blockIdx.x*256 + threadIdx.x;
    if (i < NX4){
        float4 v = ((const float4*)X)[i];
        __half2 h0 = __floats2half2_rn(v.x, v.y);
        __half2 h1 = __floats2half2_rn(v.z, v.w);
        uint2 o;
        o.x = *(unsigned*)&h0;
        o.y = *(unsigned*)&h1;
        *(uint2*)&g_xh[(size_t)i*4] = o;
    } else {
        int off = i - NX4;
        if (off >= NA4) return;
        float4 v = ((const float4*)pkv)[off];
        v.x=tfr(v.x); v.y=tfr(v.y); v.z=tfr(v.z); v.w=tfr(v.w);
        ((float4*)g_ar)[off] = v;
    }
}

// ================= K0b: W -> fp16, transposed to [n][k] =================
__global__ void __launch_bounds__(256) k_cvtw(const float* __restrict__ Wq,
                                              const float* __restrict__ Wk,
                                              const float* __restrict__ Wv)
{
    __shared__ float sm[64*65];
    int sel = blockIdx.z;
    const float* W = (sel==0)?Wq:(sel==1)?Wk:Wv;
    __half* dst = g_wh + (size_t)sel*NE*NE;
    int k0 = blockIdx.x*64, n0 = blockIdx.y*64;
    int tid = threadIdx.x;
#pragma unroll
    for (int l=0;l<16;l++){
        int idx = tid + l*256;
        int r = idx>>6, c = idx&63;
        sm[c*65 + r] = W[(size_t)(k0+r)*NE + n0 + c];
    }
    __syncthreads();
#pragma unroll
    for (int l=0;l<8;l++){
        int idx = tid + l*256;
        int r = idx>>5, cp = idx&31;
        __half2 h = __floats2half2_rn(sm[(2*cp)*65 + r] * 0.f + sm[r*65 + 2*cp],
                                      sm[r*65 + 2*cp + 1]);
        // sm[r*65+c] holds W[k0+c][n0+r] (transposed at load); write [n][k] contiguous in k
        *(__half2*)&dst[(size_t)(n0+r)*NE + k0 + 2*cp] = h;
    }
}

// ================= K1: fused QKV projection (FP16 mma, 128x128, 3-stage) ===
#define A_STGH (128*24)
#define B_STGH (128*24)
#define PROJ_SMEM (3*(A_STGH+B_STGH)*2)
__global__ void __launch_bounds__(256) k_proj3()
{
    const int sel = blockIdx.z;
    const __half* Xh = g_xh;
    const __half* Wh = g_wh + (size_t)sel*NE*NE;
    float* dst = (sel==0)?g_q:(sel==1)?g_k:g_v;

    extern __shared__ __half hsm[];
    __half* As = hsm;               // 3 stages of 128x24 (16 used + pad)
    __half* Bs = hsm + 3*A_STGH;    // 3 stages of 128x24 (W^T rows)

    const int tid = threadIdx.x;
    const int rowBase = blockIdx.y*128, colBase = blockIdx.x*128;
    const int warp = tid>>5, lane = tid&31;
    const int wm = warp&3, wn = warp>>2;
    const int g = lane>>2, t4 = lane&3;

    const int srow = tid>>1, shc = (tid&1)*8;

    const unsigned sA = (unsigned)__cvta_generic_to_shared(As);
    const unsigned sB = (unsigned)__cvta_generic_to_shared(Bs);
    const unsigned stA = (unsigned)A_STGH*2u, stB = (unsigned)B_STGH*2u;

    float acc[2][8][4];
#pragma unroll
    for (int a=0;a<2;a++)
#pragma unroll
      for (int b=0;b<8;b++)
#pragma unroll
        for (int c=0;c<4;c++) acc[a][b][c]=0.f;

    auto issue = [&](int it, int st){
        int kb = it*16;
        const __half* xs = Xh + (size_t)(rowBase+srow)*NE + kb + shc;
        CP16(sA + st*stA + (unsigned)(srow*24 + shc)*2u, xs);
        const __half* ws = Wh + (size_t)(colBase+srow)*NE + kb + shc;
        CP16(sB + st*stB + (unsigned)(srow*24 + shc)*2u, ws);
        asm volatile("cp.async.commit_group;" ::: "memory");
    };

    const int NIT = NE/16;
    issue(0,0); issue(1,1);
    for (int it=0; it<NIT; it++){
        const int st = it%3;
        if (it+1<NIT){
            asm volatile("cp.async.wait_group 1;" ::: "memory");
        } else {
            asm volatile("cp.async.wait_group 0;" ::: "memory");
        }
        __syncthreads();
        if (it+2<NIT) issue(it+2, (it+2)%3);
        const __half* Ap = As + st*A_STGH;
        const __half* Bp = Bs + st*B_STGH;
        unsigned af[2][4];
#pragma unroll
        for (int mt=0;mt<2;mt++){
            int rr = wm*32 + mt*16 + g;
            af[mt][0] = *(const unsigned*)(Ap + rr*24     + 2*t4);
            af[mt][1] = *(const unsigned*)(Ap + (rr+8)*24 + 2*t4);
            af[mt][2] = *(const unsigned*)(Ap + rr*24     + 8 + 2*t4);
            af[mt][3] = *(const unsigned*)(Ap + (rr+8)*24 + 8 + 2*t4);
        }
#pragma unroll
        for (int nt=0;nt<8;nt++){
            int nr = wn*64 + nt*8 + g;
            unsigned b0 = *(const unsigned*)(Bp + nr*24 + 2*t4);
            unsigned b1 = *(const unsigned*)(Bp + nr*24 + 8 + 2*t4);
#pragma unroll
            for (int mt=0;mt<2;mt++){
                mma16(acc[mt][nt], af[mt], b0, b1);
            }
        }
    }
    // epilogue: store q/k/v pre-rounded to tf32
#pragma unroll
    for (int mt=0;mt<2;mt++)
#pragma unroll
    for (int nt=0;nt<8;nt++){
        int row = rowBase + wm*32 + mt*16 + g;
        int col = colBase + wn*64 + nt*8 + t4*2;
        int b_ = row>>11, t_ = row&2047, h_ = col>>6, d_ = col&63;
        float* p0 = dst + (((size_t)(b_*NH+h_))*NT + t_)*ND + d_;
        *(float2*)p0 = make_float2(tfr(acc[mt][nt][0]), tfr(acc[mt][nt][1]));
        int t2_ = (row+8)&2047;
        float* p1 = dst + (((size_t)(b_*NH+h_))*NT + t2_)*ND + d_;
        *(float2*)p1 = make_float2(tfr(acc[mt][nt][2]), tfr(acc[mt][nt][3]));
    }
}

// ================= K2: per-chunk U_j, KV_j (tensor core, frag reuse), W_j =========
#define P1_SMEM ((4352 + 2*4608)*4)
__global__ void __launch_bounds__(256) k_pass1(const float* __restrict__ pkv)
{
    extern __shared__ float sm1[];
    float* bKT = sm1;          // 64x68 : K^T [d][i] (already tf32)
    float* bV  = sm1 + 4352;   // 64x72 : V  [i][e] (already tf32; later Q)
    float* bVw = sm1 + 4352 + 4608; // 64x72 : gamma^{63-i} V, tf32
    __shared__ float gp[65];
    __shared__ float red[4*64];
    __shared__ float qw[64];
    int tid=threadIdx.x, bid=blockIdx.x;
    int j=bid&31, bh=bid>>5, h=bh&15;
    size_t base = ((size_t)bh*NT + (size_t)j*NC)*ND;
    if (tid<=64){
        double gd = 1.0 - exp2(-5.0-(double)h);
        gp[tid]=(float)pow(gd,(double)tid);
    }
    __syncthreads();
#pragma unroll
    for (int l=0;l<4;l++){
        int idx = tid + l*256;
        int i=idx>>4, d4=(idx&15)*4;
        float4 k4 = *(const float4*)(g_k + base + (size_t)idx*4);
        bKT[(d4  )*68+i]=k4.x;
        bKT[(d4+1)*68+i]=k4.y;
        bKT[(d4+2)*68+i]=k4.z;
        bKT[(d4+3)*68+i]=k4.w;
        float4 v4 = *(const float4*)(g_v + base + (size_t)idx*4);
        *(float4*)(bV + i*72 + d4) = v4;
        float w = gp[63-i];
        bVw[i*72+d4  ]=tfr(v4.x*w);
        bVw[i*72+d4+1]=tfr(v4.y*w);
        bVw[i*72+d4+2]=tfr(v4.z*w);
        bVw[i*72+d4+3]=tfr(v4.w*w);
    }
    __syncthreads();
    const int warp=tid>>5, lane=tid&31;
    const int wm=warp&3, wn=warp>>2, g=lane>>2, t4=lane&3;
    const int m0=wm*16;
    const int r0=m0+g, r1=r0+8;

    unsigned ka[8][4];
#pragma unroll
    for (int k8=0;k8<8;k8++){
        int k=k8*8;
        ka[k8][0]=__float_as_uint(bKT[(m0+g  )*68 + k+t4  ]);
        ka[k8][1]=__float_as_uint(bKT[(m0+g+8)*68 + k+t4  ]);
        ka[k8][2]=__float_as_uint(bKT[(m0+g  )*68 + k+t4+4]);
        ka[k8][3]=__float_as_uint(bKT[(m0+g+8)*68 + k+t4+4]);
    }

    float accKV[4][4]={}, accU[4][4]={};
#pragma unroll
    for (int k8=0;k8<8;k8++){
#pragma unroll
        for (int nt=0;nt<4;nt++){
            int cb=wn*32+nt*8;
            unsigned b0=__float_as_uint(bV [(k8*8+t4  )*72 + cb+g]);
            unsigned b1=__float_as_uint(bV [(k8*8+t4+4)*72 + cb+g]);
            mma8(accKV[nt], ka[k8], b0, b1);
            unsigned c0=__float_as_uint(bVw[(k8*8+t4  )*72 + cb+g]);
            unsigned c1=__float_as_uint(bVw[(k8*8+t4+4)*72 + cb+g]);
            mma8(accU[nt], ka[k8], c0, c1);
        }
    }
    {
        float* Kp = g_kvc + (size_t)bid*4096;
        float* Up = g_U  + (size_t)bid*4096;
#pragma unroll
        for (int nt=0;nt<4;nt++){
            int c0=wn*32+nt*8+t4*2;
            *(float2*)(Kp + r0*64 + c0) = make_float2(accKV[nt][0],accKV[nt][1]);
            *(float2*)(Kp + r1*64 + c0) = make_float2(accKV[nt][2],accKV[nt][3]);
            *(float2*)(Up + r0*64 + c0) = make_float2(accU[nt][0],accU[nt][1]);
            *(float2*)(Up + r1*64 + c0) = make_float2(accU[nt][2],accU[nt][3]);
        }
    }
    __syncthreads();
#pragma unroll
    for (int l=0;l<4;l++){
        int idx=tid+l*256;
        *(float4*)(bV + (idx>>4)*72 + (idx&15)*4) =
            *(const float4*)(g_q + base + (size_t)idx*4);
    }
    __syncthreads();
    int rr = tid>>6, d = tid&63;
    float s = 0.f;
#pragma unroll
    for (int i=rr*16;i<rr*16+16;i++) s += gp[i]*bV[i*72 + d];
    red[rr*64 + d] = s;
    __syncthreads();
    if (tid<64) qw[tid] = red[tid] + red[64+tid] + red[128+tid] + red[192+tid];
    __syncthreads();
    const float* A = pkv + (size_t)h*4096;
    float s2 = 0.f;
#pragma unroll
    for (int dd=rr*16; dd<rr*16+16; dd++) s2 += qw[dd]*A[dd*64 + d];
    red[rr*64 + d] = s2;
    __syncthreads();
    if (tid<64) g_W[(size_t)bid*64 + tid] = red[tid] + red[64+tid] + red[128+tid] + red[192+tid];
}

// ================= K3: chunk scans (4 chains/thread, 8-iter batched loads) ========
__global__ void __launch_bounds__(256) k_scan()
{
    int bh = blockIdx.x, part = blockIdx.y, tid = threadIdx.x;
    int h = bh&15;
    double gd = 1.0 - exp2(-5.0-(double)h);
    float g64 = (float)pow(gd,64.0);
    if (part < 4){
        size_t ob = (size_t)bh*NCHK*4096 + (size_t)part*1024 + tid;
        float S[4] = {0.f,0.f,0.f,0.f};
        for (int j=0;j<NCHK;j+=8){
            float u[8][4];
#pragma unroll
            for (int jj=0;jj<8;jj++)
#pragma unroll
                for (int r=0;r<4;r++)
                    u[jj][r] = g_U[ob + (size_t)(j+jj)*4096 + r*256];
#pragma unroll
            for (int jj=0;jj<8;jj++){
#pragma unroll
                for (int r=0;r<4;r++){
                    g_S[ob + (size_t)(j+jj)*4096 + r*256] = tfr(S[r]);
                    S[r] = g64*S[r] + u[jj][r];
                }
            }
        }
    } else {
        if (tid < 64){
            size_t ob2 = (size_t)bh*NCHK*64 + tid;
            float X = 0.f;
            for (int j=NCHK-8; j>=0; j-=8){
                float w[8];
#pragma unroll
                for (int jj=0;jj<8;jj++) w[jj] = g_W[ob2 + (size_t)(j+jj)*64];
#pragma unroll
                for (int jj=7;jj>=0;jj--){
                    g_Xn[ob2 + (size_t)(j+jj)*64] = X;
                    X = g64*X + w[jj];
                }
            }
        }
    }
}

// ================= K4: per-chunk finalize (tensor core, all operands pre-tf32) ======
#define P3_SMEM ((4352 + 4*4608)*4)
__global__ void __launch_bounds__(256) k_pass3()
{
    extern __shared__ float sm3[];
    float* bQ = sm3;                  // 64x68 : Q [i][d] tf32 -> P tf32
    float* bK = sm3 + 4352;           // 64x72 : K^T [d][s] tf32 -> scan buffer
    float* bS = sm3 + 4352 + 4608;    // 64x72 : S (tf32)
    float* bA = sm3 + 4352 + 2*4608;  // 64x72 : past_kv (tf32)
    float* bV = sm3 + 4352 + 3*4608;  // 64x72 : V (tf32)
    __shared__ float gp[65];
    __shared__ float Xs[64];
    __shared__ float carry[4*64];
    __shared__ float redS[8], redQ[8];
    int tid=threadIdx.x, bid=blockIdx.x;
    int j=bid&31, bh=bid>>5, h=bh&15;
    size_t base=((size_t)bh*NT+(size_t)j*NC)*ND;

    {
        const unsigned sb = (unsigned)__cvta_generic_to_shared(sm3);
        const float* Ssrc = g_S + ((size_t)bh*NCHK+j)*4096;
        const float* Asrc = g_ar + (size_t)h*4096;
        const float* Vsrc = g_v + base;
#pragma unroll
        for (int l=0;l<4;l++){
            int idx=tid+l*256;
            unsigned o = (unsigned)((idx>>4)*72 + (idx&15)*4)*4u;
            CP16(sb + (4352u+  4608u)*4u + o, Ssrc + (size_t)idx*4);
            CP16(sb + (4352u+2*4608u)*4u + o, Asrc + (size_t)idx*4);
            CP16(sb + (4352u+3*4608u)*4u + o, Vsrc + (size_t)idx*4);
        }
        asm volatile("cp.async.commit_group;" ::: "memory");
    }
    if (tid<=64){
        double gd = 1.0 - exp2(-5.0-(double)h);
        gp[tid]=(float)pow(gd,(double)tid);
    }
    if (tid<64) Xs[tid] = g_Xn[((size_t)bh*NCHK+j)*64 + tid];
#pragma unroll
    for (int l=0;l<4;l++){
        int idx=tid+l*256;
        int i=idx>>4, d4=(idx&15)*4;
        float4 q4 = *(const float4*)(g_q + base + (size_t)idx*4);
        *(float4*)(bQ + i*68 + d4) = q4;
        float4 k4 = *(const float4*)(g_k + base + (size_t)idx*4);
        bK[(d4  )*72+i]=k4.x;
        bK[(d4+1)*72+i]=k4.y;
        bK[(d4+2)*72+i]=k4.z;
        bK[(d4+3)*72+i]=k4.w;
    }
    __syncthreads();
    const int warp=tid>>5, lane=tid&31;
    const int wm=warp&3, wn=warp>>2, g=lane>>2, t4=lane&3;
    const int m0=wm*16;
    const int r0=m0+g, r1=r0+8;

    unsigned qa[8][4];
#pragma unroll
    for (int k8=0;k8<8;k8++){
        int k=k8*8;
        qa[k8][0]=__float_as_uint(bQ[(m0+g  )*68 + k+t4  ]);
        qa[k8][1]=__float_as_uint(bQ[(m0+g+8)*68 + k+t4  ]);
        qa[k8][2]=__float_as_uint(bQ[(m0+g  )*68 + k+t4+4]);
        qa[k8][3]=__float_as_uint(bQ[(m0+g+8)*68 + k+t4+4]);
    }
    float accP[4][4]={};
#pragma unroll
    for (int k8=0;k8<8;k8++){
#pragma unroll
        for (int nt=0;nt<4;nt++){
            int cb=wn*32+nt*8;
            unsigned b0=__float_as_uint(bK[(k8*8+t4  )*72 + cb+g]);
            unsigned b1=__float_as_uint(bK[(k8*8+t4+4)*72 + cb+g]);
            mma8(accP[nt], qa[k8], b0, b1);
        }
    }
    asm volatile("cp.async.wait_group 0;" ::: "memory");
    __syncthreads();
    float accQ[4][4]={}, accPP[4][4]={};
#pragma unroll
    for (int k8=0;k8<8;k8++){
#pragma unroll
        for (int nt=0;nt<4;nt++){
            int cb=wn*32+nt*8;
            unsigned b0=__float_as_uint(bS[(k8*8+t4  )*72 + cb+g]);
            unsigned b1=__float_as_uint(bS[(k8*8+t4+4)*72 + cb+g]);
            mma8(accQ[nt], qa[k8], b0, b1);
            unsigned c0=__float_as_uint(bA[(k8*8+t4  )*72 + cb+g]);
            unsigned c1=__float_as_uint(bA[(k8*8+t4+4)*72 + cb+g]);
            mma8(accPP[nt], qa[k8], c0, c1);
        }
    }
#pragma unroll
    for (int nt=0;nt<4;nt++){
        int c0=wn*32+nt*8+t4*2;
        int d00=r0-c0, d01=d00-1, d10=r1-c0, d11=d10-1;
        float p00 = (d00>=0)? accP[nt][0]*gp[d00] : 0.f;
        float p01 = (d01>=0)? accP[nt][1]*gp[d01] : 0.f;
        float p10 = (d10>=0)? accP[nt][2]*gp[d10] : 0.f;
        float p11 = (d11>=0)? accP[nt][3]*gp[d11] : 0.f;
        bQ[r0*68+c0  ]=tfr(p00);
        bQ[r0*68+c0+1]=tfr(p01);
        bQ[r1*68+c0  ]=tfr(p10);
        bQ[r1*68+c0+1]=tfr(p11);
        *(float2*)(bK + r0*72 + c0) = make_float2(accPP[nt][0],accPP[nt][1]);
        *(float2*)(bK + r1*72 + c0) = make_float2(accPP[nt][2],accPP[nt][3]);
        float gq0=gp[r0+1], gq1=gp[r1+1];
        accQ[nt][0]*=gq0; accQ[nt][1]*=gq0;
        accQ[nt][2]*=gq1; accQ[nt][3]*=gq1;
    }
    __syncthreads();
#pragma unroll
    for (int k8=0;k8<8;k8++){
        int k=k8*8;
        unsigned pa[4];
        pa[0]=__float_as_uint(bQ[(m0+g  )*68 + k+t4  ]);
        pa[1]=__float_as_uint(bQ[(m0+g+8)*68 + k+t4  ]);
        pa[2]=__float_as_uint(bQ[(m0+g  )*68 + k+t4+4]);
        pa[3]=__float_as_uint(bQ[(m0+g+8)*68 + k+t4+4]);
#pragma unroll
        for (int nt=0;nt<4;nt++){
            int cb=wn*32+nt*8;
            unsigned b0=__float_as_uint(bV[(k+t4  )*72 + cb+g]);
            unsigned b1=__float_as_uint(bV[(k+t4+4)*72 + cb+g]);
            mma8(accQ[nt], pa, b0, b1);
        }
    }
    {
        int e = tid&63, q = tid>>6;
        float g1 = gp[1];
        float loc[16];
        float c = 0.f;
#pragma unroll
        for (int i=15;i>=0;--i){
            c = bK[(q*16+i)*72 + e] + g1*c;
            loc[i] = c;
        }
        carry[q*64+e] = loc[0];
        __syncthreads();
        float F = 0.f;
        if (q<3) F  = carry[(q+1)*64+e];
        if (q<2) F += gp[16]*carry[(q+2)*64+e];
        if (q<1) F += gp[32]*carry[(q+3)*64+e];
#pragma unroll
        for (int i=0;i<16;i++){
            bK[(q*16+i)*72 + e] = loc[i] + gp[16-i]*F;
        }
    }
    __syncthreads();
    float s1=0.f, s2=0.f;
    float gx0=gp[64-r0], gx1=gp[64-r1];
#pragma unroll
    for (int nt=0;nt<4;nt++){
        int c0=wn*32+nt*8+t4*2;
        float v00 = accQ[nt][0] + bK[r0*72+c0  ] + gx0*Xs[c0  ];
        float v01 = accQ[nt][1] + bK[r0*72+c0+1] + gx0*Xs[c0+1];
        float v10 = accQ[nt][2] + bK[r1*72+c0  ] + gx1*Xs[c0  ];
        float v11 = accQ[nt][3] + bK[r1*72+c0+1] + gx1*Xs[c0+1];
        s1 += v00+v01+v10+v11;
        s2 += v00*v00+v01*v01+v10*v10+v11*v11;
        *(float2*)(g_ret + base + (size_t)r0*64 + c0) = make_float2(v00,v01);
        *(float2*)(g_ret + base + (size_t)r1*64 + c0) = make_float2(v10,v11);
    }
#pragma unroll
    for (int o=16;o>0;o>>=1){
        s1 += __shfl_down_sync(0xffffffffu, s1, o);
        s2 += __shfl_down_sync(0xffffffffu, s2, o);
    }
    if (lane==0){ redS[warp]=s1; redQ[warp]=s2; }
    __syncthreads();
    if (tid==0){
        float a=0.f,bq=0.f;
#pragma unroll
        for (int w=0;w<8;w++){ a+=redS[w]; bq+=redQ[w]; }
        g_stat[(size_t)bid*2  ]=a;
        g_stat[(size_t)bid*2+1]=bq;
    }
}

// ================= K5: per-batch GroupNorm stats =================
__global__ void __launch_bounds__(512) k_stats()
{
    __shared__ float r1[512], r2[512];
    int b=blockIdx.x, tid=threadIdx.x;
    r1[tid]=g_stat[(size_t)(b*512+tid)*2];
    r2[tid]=g_stat[(size_t)(b*512+tid)*2+1];
    __syncthreads();
    for (int o=256;o>0;o>>=1){
        if (tid<o){ r1[tid]+=r1[tid+o]; r2[tid]+=r2[tid+o]; }
        __syncthreads();
    }
    if (tid==0){
        const float N = (float)((size_t)NH*NT*ND);
        float mu = r1[0]/N;
        float var = r2[0]/N - mu*mu;
        g_norm[b*2]=mu;
        g_norm[b*2+1]=rsqrtf(var+1e-5f);
    }
}

// ================= K6: normalize + layout to [B,T,NE] =================
__global__ void __launch_bounds__(256) k_out(const float* __restrict__ gnw,
                                             const float* __restrict__ gnb,
                                             float* __restrict__ out)
{
    int bid=blockIdx.x;
    int b=bid>>11, t=bid&2047;
    int tid=threadIdx.x;
    int h=tid>>4, d4=(tid&15)*4;
    float mu=g_norm[b*2], rs=g_norm[b*2+1];
    float w = gnw[h]*rs;
    float bb = gnb[h] - mu*w;
    float4 xv = *(const float4*)(g_ret + (((size_t)(b*NH+h))*NT + t)*ND + d4);
    float4 yv = make_float4(xv.x*w+bb, xv.y*w+bb, xv.z*w+bb, xv.w*w+bb);
    *(float4*)(out + (size_t)bid*NE + h*ND + d4) = yv;
}

// ================= K7: kv reduce + decay =================
__global__ void __launch_bounds__(256) k_kvout(const float* __restrict__ pkv,
                                               float* __restrict__ out_kv)
{
    int h=blockIdx.x;
    int idx=blockIdx.y*256+threadIdx.x;
    float s=0.f;
    for (int b=0;b<NB;b++){
        size_t bh=((size_t)(b*NH+h))*NCHK;
        for (int j2=0;j2<NCHK;j2++) s += g_kvc[(bh+j2)*4096 + idx];
    }
    double gd = 1.0 - exp2(-5.0-(double)h);
    out_kv[(size_t)h*4096 + idx] = (float)gd*pkv[(size_t)h*4096 + idx] + 0.25f*s;
}

extern "C" void kernel_launch(void* const* d_in, const int* in_sizes, int n_in,
                              void* d_out, int out_size)
{
    const float* x   = (const float*)d_in[0];
    const float* pkv = (const float*)d_in[1];
    const float* Wq  = (const float*)d_in[2];
    const float* Wk  = (const float*)d_in[3];
    const float* Wv  = (const float*)d_in[4];
    const float* gnw = (const float*)d_in[5];
    const float* gnb = (const float*)d_in[6];
    float* out = (float*)d_out;

    cudaFuncSetAttribute(k_proj3, cudaFuncAttributeMaxDynamicSharedMemorySize, PROJ_SMEM);
    cudaFuncSetAttribute(k_pass1, cudaFuncAttributeMaxDynamicSharedMemorySize, P1_SMEM);
    cudaFuncSetAttribute(k_pass3, cudaFuncAttributeMaxDynamicSharedMemorySize, P3_SMEM);

    k_cvtx<<<(NX4 + NA4 + 255)/256, 256>>>(x, pkv);
    dim3 gcw(NE/64, NE/64, 3);
    k_cvtw<<<gcw, 256>>>(Wq, Wk, Wv);
    dim3 gproj(8, 64, 3);
    k_proj3<<<gproj, 256, PROJ_SMEM>>>();
    k_pass1<<<NBH*NCHK, 256, P1_SMEM>>>(pkv);
    dim3 gscan(NBH, 5);
    k_scan<<<gscan, 256>>>();
    k_pass3<<<NBH*NCHK, 256, P3_SMEM>>>();
    k_stats<<<NB, 512>>>();
    k_out<<<NB*NT, 256>>>(gnw, gnb, out);
    dim3 gkv(NH, 16);
    k_kvout<<<gkv, 256>>>(pkv, out + (size_t)NB*NT*NE);
}

// round 13
// speedup vs baseline: 1.5618x; 1.0074x over previous
#include <cuda_runtime.h>
#include <cuda_fp16.h>
#include <math.h>
#include <stdint.h>

#define NB 4
#define NT 2048
#define NH 16
#define ND 64
#define NE 1024
#define NC 64
#define NCHK 32
#define NBH (NB*NH)

// ---------------- scratch (device globals; no runtime allocation) ----------------
__device__ __half g_qh [(size_t)NB*NH*NT*ND];
__device__ __half g_kh [(size_t)NB*NH*NT*ND];
__device__ __half g_vh [(size_t)NB*NH*NT*ND];
__device__ float g_ret[(size_t)NB*NH*NT*ND];
__device__ float g_U  [(size_t)NBH*NCHK*ND*ND];
__device__ float g_S  [(size_t)NBH*NCHK*ND*ND];
__device__ float g_kvc[(size_t)NBH*NCHK*ND*ND];
__device__ float g_W  [(size_t)NBH*NCHK*ND];
__device__ float g_Xn [(size_t)NBH*NCHK*ND];
__device__ float g_stat[(size_t)NBH*NCHK*2];
__device__ float g_norm[NB*2];
__device__ __half g_xh [(size_t)NB*NT*NE];    // fp16 X
__device__ __half g_wh [(size_t)3*NE*NE];     // fp16 W^T (layout [n][k])
__device__ float  g_ar [(size_t)NH*ND*ND];    // tf32-rounded past_kv

__device__ __forceinline__ unsigned f2tf(float x){
    unsigned r;
    asm("cvt.rna.tf32.f32 %0, %1;" : "=r"(r) : "f"(x));
    return r;
}
__device__ __forceinline__ float tfr(float x){
    return __uint_as_float(f2tf(x));
}
__device__ __forceinline__ void mma8(float c[4], const unsigned a[4], unsigned b0, unsigned b1){
    asm volatile(
      "mma.sync.aligned.m16n8k8.row.col.f32.tf32.tf32.f32 "
      "{%0,%1,%2,%3},{%4,%5,%6,%7},{%8,%9},{%0,%1,%2,%3};"
      : "+f"(c[0]),"+f"(c[1]),"+f"(c[2]),"+f"(c[3])
      : "r"(a[0]),"r"(a[1]),"r"(a[2]),"r"(a[3]), "r"(b0),"r"(b1));
}
__device__ __forceinline__ void mma16(float c[4], const unsigned a[4], unsigned b0, unsigned b1){
    asm volatile(
      "mma.sync.aligned.m16n8k16.row.col.f32.f16.f16.f32 "
      "{%0,%1,%2,%3},{%4,%5,%6,%7},{%8,%9},{%0,%1,%2,%3};"
      : "+f"(c[0]),"+f"(c[1]),"+f"(c[2]),"+f"(c[3])
      : "r"(a[0]),"r"(a[1]),"r"(a[2]),"r"(a[3]), "r"(b0),"r"(b1));
}

#define CP16(dst_u32, src) \
    asm volatile("cp.async.ca.shared.global [%0], [%1], 16;" :: "r"(dst_u32), "l"(src))

// ================= K0a: X -> fp16, past_kv -> tf32 =================
#define NX4 ((NB*NT*NE)/4)       // 2097152
#define NA4 ((NH*ND*ND)/4)       // 16384
__global__ void __launch_bounds__(256) k_cvtx(const float* __restrict__ X,
                                              const float* __restrict__ pkv)
{
    int i = blockIdx.x*256 + threadIdx.x;
    if (i < NX4){
        float4 v = ((const float4*)X)[i];
        __half2 h0 = __floats2half2_rn(v.x, v.y);
        __half2 h1 = __floats2half2_rn(v.z, v.w);
        uint2 o;
        o.x = *(unsigned*)&h0;
        o.y = *(unsigned*)&h1;
        *(uint2*)&g_xh[(size_t)i*4] = o;
    } else {
        int off = i - NX4;
        if (off >= NA4) return;
        float4 v = ((const float4*)pkv)[off];
        v.x=tfr(v.x); v.y=tfr(v.y); v.z=tfr(v.z); v.w=tfr(v.w);
        ((float4*)g_ar)[off] = v;
    }
}

// ================= K0b: W -> fp16, transposed to [n][k] =================
__global__ void __launch_bounds__(256) k_cvtw(const float* __restrict__ Wq,
                                              const float* __restrict__ Wk,
                                              const float* __restrict__ Wv)
{
    __shared__ float sm[64*65];
    int sel = blockIdx.z;
    const float* W = (sel==0)?Wq:(sel==1)?Wk:Wv;
    __half* dst = g_wh + (size_t)sel*NE*NE;
    int k0 = blockIdx.x*64, n0 = blockIdx.y*64;
    int tid = threadIdx.x;
#pragma unroll
    for (int l=0;l<16;l++){
        int idx = tid + l*256;
        int r = idx>>6, c = idx&63;
        sm[c*65 + r] = W[(size_t)(k0+r)*NE + n0 + c];
    }
    __syncthreads();
#pragma unroll
    for (int l=0;l<8;l++){
        int idx = tid + l*256;
        int r = idx>>5, cp = idx&31;
        __half2 h = __floats2half2_rn(sm[r*65 + 2*cp], sm[r*65 + 2*cp + 1]);
        *(__half2*)&dst[(size_t)(n0+r)*NE + k0 + 2*cp] = h;
    }
}

// ================= K1: fused QKV projection (FP16 mma, 128x128, 3-stage) ===
#define A_STGH (128*24)
#define B_STGH (128*24)
#define PROJ_SMEM (3*(A_STGH+B_STGH)*2)
__global__ void __launch_bounds__(256) k_proj3()
{
    const int sel = blockIdx.z;
    const __half* Xh = g_xh;
    const __half* Wh = g_wh + (size_t)sel*NE*NE;
    __half* dst = (sel==0)?g_qh:(sel==1)?g_kh:g_vh;

    extern __shared__ __half hsm[];
    __half* As = hsm;
    __half* Bs = hsm + 3*A_STGH;

    const int tid = threadIdx.x;
    const int rowBase = blockIdx.y*128, colBase = blockIdx.x*128;
    const int warp = tid>>5, lane = tid&31;
    const int wm = warp&3, wn = warp>>2;
    const int g = lane>>2, t4 = lane&3;

    const int srow = tid>>1, shc = (tid&1)*8;

    const unsigned sA = (unsigned)__cvta_generic_to_shared(As);
    const unsigned sB = (unsigned)__cvta_generic_to_shared(Bs);
    const unsigned stA = (unsigned)A_STGH*2u, stB = (unsigned)B_STGH*2u;

    float acc[2][8][4];
#pragma unroll
    for (int a=0;a<2;a++)
#pragma unroll
      for (int b=0;b<8;b++)
#pragma unroll
        for (int c=0;c<4;c++) acc[a][b][c]=0.f;

    auto issue = [&](int it, int st){
        int kb = it*16;
        const __half* xs = Xh + (size_t)(rowBase+srow)*NE + kb + shc;
        CP16(sA + st*stA + (unsigned)(srow*24 + shc)*2u, xs);
        const __half* ws = Wh + (size_t)(colBase+srow)*NE + kb + shc;
        CP16(sB + st*stB + (unsigned)(srow*24 + shc)*2u, ws);
        asm volatile("cp.async.commit_group;" ::: "memory");
    };

    const int NIT = NE/16;
    issue(0,0); issue(1,1);
    for (int it=0; it<NIT; it++){
        const int st = it%3;
        if (it+1<NIT){
            asm volatile("cp.async.wait_group 1;" ::: "memory");
        } else {
            asm volatile("cp.async.wait_group 0;" ::: "memory");
        }
        __syncthreads();
        if (it+2<NIT) issue(it+2, (it+2)%3);
        const __half* Ap = As + st*A_STGH;
        const __half* Bp = Bs + st*B_STGH;
        unsigned af[2][4];
#pragma unroll
        for (int mt=0;mt<2;mt++){
            int rr = wm*32 + mt*16 + g;
            af[mt][0] = *(const unsigned*)(Ap + rr*24     + 2*t4);
            af[mt][1] = *(const unsigned*)(Ap + (rr+8)*24 + 2*t4);
            af[mt][2] = *(const unsigned*)(Ap + rr*24     + 8 + 2*t4);
            af[mt][3] = *(const unsigned*)(Ap + (rr+8)*24 + 8 + 2*t4);
        }
#pragma unroll
        for (int nt=0;nt<8;nt++){
            int nr = wn*64 + nt*8 + g;
            unsigned b0 = *(const unsigned*)(Bp + nr*24 + 2*t4);
            unsigned b1 = *(const unsigned*)(Bp + nr*24 + 8 + 2*t4);
#pragma unroll
            for (int mt=0;mt<2;mt++){
                mma16(acc[mt][nt], af[mt], b0, b1);
            }
        }
    }
    // epilogue: store q/k/v as fp16 (downstream tf32 mma sees identical mantissas)
#pragma unroll
    for (int mt=0;mt<2;mt++)
#pragma unroll
    for (int nt=0;nt<8;nt++){
        int row = rowBase + wm*32 + mt*16 + g;
        int col = colBase + wn*64 + nt*8 + t4*2;
        int b_ = row>>11, t_ = row&2047, h_ = col>>6, d_ = col&63;
        __half2 h0 = __floats2half2_rn(acc[mt][nt][0], acc[mt][nt][1]);
        *(__half2*)(dst + (((size_t)(b_*NH+h_))*NT + t_)*ND + d_) = h0;
        int t2_ = (row+8)&2047;
        __half2 h1 = __floats2half2_rn(acc[mt][nt][2], acc[mt][nt][3]);
        *(__half2*)(dst + (((size_t)(b_*NH+h_))*NT + t2_)*ND + d_) = h1;
    }
}

// ================= K2: per-chunk U_j, KV_j (tensor core, fp16-source staging) =====
#define P1_SMEM ((4352 + 2*4608)*4)
__global__ void __launch_bounds__(256) k_pass1(const float* __restrict__ pkv)
{
    extern __shared__ float sm1[];
    float* bKT = sm1;          // 64x68 : K^T [d][i]
    float* bV  = sm1 + 4352;   // 64x72 : V  [i][e] (later Q)
    float* bVw = sm1 + 4352 + 4608; // 64x72 : gamma^{63-i} V (tf32)
    __shared__ float gp[65];
    __shared__ float red[4*64];
    __shared__ float qw[64];
    int tid=threadIdx.x, bid=blockIdx.x;
    int j=bid&31, bh=bid>>5, h=bh&15;
    size_t base = ((size_t)bh*NT + (size_t)j*NC)*ND;
    if (tid<=64){
        double gd = 1.0 - exp2(-5.0-(double)h);
        gp[tid]=(float)pow(gd,(double)tid);
    }
    __syncthreads();
#pragma unroll
    for (int l=0;l<2;l++){
        int idx = tid + l*256;        // 0..511, each covers 8 elems
        int i=idx>>3, d8=(idx&7)*8;
        uint4 kk = *(const uint4*)(g_kh + base + (size_t)idx*8);
        float2 k0=__half22float2(*(__half2*)&kk.x), k1=__half22float2(*(__half2*)&kk.y);
        float2 k2=__half22float2(*(__half2*)&kk.z), k3=__half22float2(*(__half2*)&kk.w);
        bKT[(d8  )*68+i]=k0.x; bKT[(d8+1)*68+i]=k0.y;
        bKT[(d8+2)*68+i]=k1.x; bKT[(d8+3)*68+i]=k1.y;
        bKT[(d8+4)*68+i]=k2.x; bKT[(d8+5)*68+i]=k2.y;
        bKT[(d8+6)*68+i]=k3.x; bKT[(d8+7)*68+i]=k3.y;
        uint4 vv = *(const uint4*)(g_vh + base + (size_t)idx*8);
        float2 v0=__half22float2(*(__half2*)&vv.x), v1=__half22float2(*(__half2*)&vv.y);
        float2 v2=__half22float2(*(__half2*)&vv.z), v3=__half22float2(*(__half2*)&vv.w);
        *(float4*)(bV + i*72 + d8    ) = make_float4(v0.x,v0.y,v1.x,v1.y);
        *(float4*)(bV + i*72 + d8 + 4) = make_float4(v2.x,v2.y,v3.x,v3.y);
        float w = gp[63-i];
        bVw[i*72+d8  ]=tfr(v0.x*w); bVw[i*72+d8+1]=tfr(v0.y*w);
        bVw[i*72+d8+2]=tfr(v1.x*w); bVw[i*72+d8+3]=tfr(v1.y*w);
        bVw[i*72+d8+4]=tfr(v2.x*w); bVw[i*72+d8+5]=tfr(v2.y*w);
        bVw[i*72+d8+6]=tfr(v3.x*w); bVw[i*72+d8+7]=tfr(v3.y*w);
    }
    __syncthreads();
    const int warp=tid>>5, lane=tid&31;
    const int wm=warp&3, wn=warp>>2, g=lane>>2, t4=lane&3;
    const int m0=wm*16;
    const int r0=m0+g, r1=r0+8;

    unsigned ka[8][4];
#pragma unroll
    for (int k8=0;k8<8;k8++){
        int k=k8*8;
        ka[k8][0]=__float_as_uint(bKT[(m0+g  )*68 + k+t4  ]);
        ka[k8][1]=__float_as_uint(bKT[(m0+g+8)*68 + k+t4  ]);
        ka[k8][2]=__float_as_uint(bKT[(m0+g  )*68 + k+t4+4]);
        ka[k8][3]=__float_as_uint(bKT[(m0+g+8)*68 + k+t4+4]);
    }

    float accKV[4][4]={}, accU[4][4]={};
#pragma unroll
    for (int k8=0;k8<8;k8++){
#pragma unroll
        for (int nt=0;nt<4;nt++){
            int cb=wn*32+nt*8;
            unsigned b0=__float_as_uint(bV [(k8*8+t4  )*72 + cb+g]);
            unsigned b1=__float_as_uint(bV [(k8*8+t4+4)*72 + cb+g]);
            mma8(accKV[nt], ka[k8], b0, b1);
            unsigned c0=__float_as_uint(bVw[(k8*8+t4  )*72 + cb+g]);
            unsigned c1=__float_as_uint(bVw[(k8*8+t4+4)*72 + cb+g]);
            mma8(accU[nt], ka[k8], c0, c1);
        }
    }
    {
        float* Kp = g_kvc + (size_t)bid*4096;
        float* Up = g_U  + (size_t)bid*4096;
#pragma unroll
        for (int nt=0;nt<4;nt++){
            int c0=wn*32+nt*8+t4*2;
            *(float2*)(Kp + r0*64 + c0) = make_float2(accKV[nt][0],accKV[nt][1]);
            *(float2*)(Kp + r1*64 + c0) = make_float2(accKV[nt][2],accKV[nt][3]);
            *(float2*)(Up + r0*64 + c0) = make_float2(accU[nt][0],accU[nt][1]);
            *(float2*)(Up + r1*64 + c0) = make_float2(accU[nt][2],accU[nt][3]);
        }
    }
    __syncthreads();
#pragma unroll
    for (int l=0;l<2;l++){
        int idx=tid+l*256;
        int i=idx>>3, d8=(idx&7)*8;
        uint4 qq = *(const uint4*)(g_qh + base + (size_t)idx*8);
        float2 q0=__half22float2(*(__half2*)&qq.x), q1=__half22float2(*(__half2*)&qq.y);
        float2 q2=__half22float2(*(__half2*)&qq.z), q3=__half22float2(*(__half2*)&qq.w);
        *(float4*)(bV + i*72 + d8    ) = make_float4(q0.x,q0.y,q1.x,q1.y);
        *(float4*)(bV + i*72 + d8 + 4) = make_float4(q2.x,q2.y,q3.x,q3.y);
    }
    __syncthreads();
    int rr = tid>>6, d = tid&63;
    float s = 0.f;
#pragma unroll
    for (int i=rr*16;i<rr*16+16;i++) s += gp[i]*bV[i*72 + d];
    red[rr*64 + d] = s;
    __syncthreads();
    if (tid<64) qw[tid] = red[tid] + red[64+tid] + red[128+tid] + red[192+tid];
    __syncthreads();
    const float* A = pkv + (size_t)h*4096;
    float s2 = 0.f;
#pragma unroll
    for (int dd=rr*16; dd<rr*16+16; dd++) s2 += qw[dd]*A[dd*64 + d];
    red[rr*64 + d] = s2;
    __syncthreads();
    if (tid<64) g_W[(size_t)bid*64 + tid] = red[tid] + red[64+tid] + red[128+tid] + red[192+tid];
}

// ================= K3: chunk scans (4 chains/thread, 8-iter batched loads) ========
__global__ void __launch_bounds__(256) k_scan()
{
    int bh = blockIdx.x, part = blockIdx.y, tid = threadIdx.x;
    int h = bh&15;
    double gd = 1.0 - exp2(-5.0-(double)h);
    float g64 = (float)pow(gd,64.0);
    if (part < 4){
        size_t ob = (size_t)bh*NCHK*4096 + (size_t)part*1024 + tid;
        float S[4] = {0.f,0.f,0.f,0.f};
        for (int j=0;j<NCHK;j+=8){
            float u[8][4];
#pragma unroll
            for (int jj=0;jj<8;jj++)
#pragma unroll
                for (int r=0;r<4;r++)
                    u[jj][r] = g_U[ob + (size_t)(j+jj)*4096 + r*256];
#pragma unroll
            for (int jj=0;jj<8;jj++){
#pragma unroll
                for (int r=0;r<4;r++){
                    g_S[ob + (size_t)(j+jj)*4096 + r*256] = tfr(S[r]);
                    S[r] = g64*S[r] + u[jj][r];
                }
            }
        }
    } else {
        if (tid < 64){
            size_t ob2 = (size_t)bh*NCHK*64 + tid;
            float X = 0.f;
            for (int j=NCHK-8; j>=0; j-=8){
                float w[8];
#pragma unroll
                for (int jj=0;jj<8;jj++) w[jj] = g_W[ob2 + (size_t)(j+jj)*64];
#pragma unroll
                for (int jj=7;jj>=0;jj--){
                    g_Xn[ob2 + (size_t)(j+jj)*64] = X;
                    X = g64*X + w[jj];
                }
            }
        }
    }
}

// ================= K4: per-chunk finalize (tensor core, fp16-source staging) ======
#define P3_SMEM ((4352 + 4*4608)*4)
__global__ void __launch_bounds__(256) k_pass3()
{
    extern __shared__ float sm3[];
    float* bQ = sm3;                  // 64x68 : Q [i][d] -> P tf32
    float* bK = sm3 + 4352;           // 64x72 : K^T [d][s] -> scan buffer
    float* bS = sm3 + 4352 + 4608;    // 64x72 : S (tf32, cp.async)
    float* bA = sm3 + 4352 + 2*4608;  // 64x72 : past_kv (tf32, cp.async)
    float* bV = sm3 + 4352 + 3*4608;  // 64x72 : V (from fp16)
    __shared__ float gp[65];
    __shared__ float Xs[64];
    __shared__ float carry[4*64];
    __shared__ float redS[8], redQ[8];
    int tid=threadIdx.x, bid=blockIdx.x;
    int j=bid&31, bh=bid>>5, h=bh&15;
    size_t base=((size_t)bh*NT+(size_t)j*NC)*ND;

    {
        const unsigned sb = (unsigned)__cvta_generic_to_shared(sm3);
        const float* Ssrc = g_S + ((size_t)bh*NCHK+j)*4096;
        const float* Asrc = g_ar + (size_t)h*4096;
#pragma unroll
        for (int l=0;l<4;l++){
            int idx=tid+l*256;
            unsigned o = (unsigned)((idx>>4)*72 + (idx&15)*4)*4u;
            CP16(sb + (4352u+  4608u)*4u + o, Ssrc + (size_t)idx*4);
            CP16(sb + (4352u+2*4608u)*4u + o, Asrc + (size_t)idx*4);
        }
        asm volatile("cp.async.commit_group;" ::: "memory");
    }
    if (tid<=64){
        double gd = 1.0 - exp2(-5.0-(double)h);
        gp[tid]=(float)pow(gd,(double)tid);
    }
    if (tid<64) Xs[tid] = g_Xn[((size_t)bh*NCHK+j)*64 + tid];
#pragma unroll
    for (int l=0;l<2;l++){
        int idx=tid+l*256;
        int i=idx>>3, d8=(idx&7)*8;
        uint4 qq = *(const uint4*)(g_qh + base + (size_t)idx*8);
        float2 q0=__half22float2(*(__half2*)&qq.x), q1=__half22float2(*(__half2*)&qq.y);
        float2 q2=__half22float2(*(__half2*)&qq.z), q3=__half22float2(*(__half2*)&qq.w);
        *(float4*)(bQ + i*68 + d8    ) = make_float4(q0.x,q0.y,q1.x,q1.y);
        *(float4*)(bQ + i*68 + d8 + 4) = make_float4(q2.x,q2.y,q3.x,q3.y);
        uint4 kk = *(const uint4*)(g_kh + base + (size_t)idx*8);
        float2 k0=__half22float2(*(__half2*)&kk.x), k1=__half22float2(*(__half2*)&kk.y);
        float2 k2=__half22float2(*(__half2*)&kk.z), k3=__half22float2(*(__half2*)&kk.w);
        bK[(d8  )*72+i]=k0.x; bK[(d8+1)*72+i]=k0.y;
        bK[(d8+2)*72+i]=k1.x; bK[(d8+3)*72+i]=k1.y;
        bK[(d8+4)*72+i]=k2.x; bK[(d8+5)*72+i]=k2.y;
        bK[(d8+6)*72+i]=k3.x; bK[(d8+7)*72+i]=k3.y;
        uint4 vv = *(const uint4*)(g_vh + base + (size_t)idx*8);
        float2 v0=__half22float2(*(__half2*)&vv.x), v1=__half22float2(*(__half2*)&vv.y);
        float2 v2=__half22float2(*(__half2*)&vv.z), v3=__half22float2(*(__half2*)&vv.w);
        *(float4*)(bV + i*72 + d8    ) = make_float4(v0.x,v0.y,v1.x,v1.y);
        *(float4*)(bV + i*72 + d8 + 4) = make_float4(v2.x,v2.y,v3.x,v3.y);
    }
    __syncthreads();
    const int warp=tid>>5, lane=tid&31;
    const int wm=warp&3, wn=warp>>2, g=lane>>2, t4=lane&3;
    const int m0=wm*16;
    const int r0=m0+g, r1=r0+8;

    unsigned qa[8][4];
#pragma unroll
    for (int k8=0;k8<8;k8++){
        int k=k8*8;
        qa[k8][0]=__float_as_uint(bQ[(m0+g  )*68 + k+t4  ]);
        qa[k8][1]=__float_as_uint(bQ[(m0+g+8)*68 + k+t4  ]);
        qa[k8][2]=__float_as_uint(bQ[(m0+g  )*68 + k+t4+4]);
        qa[k8][3]=__float_as_uint(bQ[(m0+g+8)*68 + k+t4+4]);
    }
    float accP[4][4]={};
#pragma unroll
    for (int k8=0;k8<8;k8++){
#pragma unroll
        for (int nt=0;nt<4;nt++){
            int cb=wn*32+nt*8;
            unsigned b0=__float_as_uint(bK[(k8*8+t4  )*72 + cb+g]);
            unsigned b1=__float_as_uint(bK[(k8*8+t4+4)*72 + cb+g]);
            mma8(accP[nt], qa[k8], b0, b1);
        }
    }
    asm volatile("cp.async.wait_group 0;" ::: "memory");
    __syncthreads();
    float accQ[4][4]={}, accPP[4][4]={};
#pragma unroll
    for (int k8=0;k8<8;k8++){
#pragma unroll
        for (int nt=0;nt<4;nt++){
            int cb=wn*32+nt*8;
            unsigned b0=__float_as_uint(bS[(k8*8+t4  )*72 + cb+g]);
            unsigned b1=__float_as_uint(bS[(k8*8+t4+4)*72 + cb+g]);
            mma8(accQ[nt], qa[k8], b0, b1);
            unsigned c0=__float_as_uint(bA[(k8*8+t4  )*72 + cb+g]);
            unsigned c1=__float_as_uint(bA[(k8*8+t4+4)*72 + cb+g]);
            mma8(accPP[nt], qa[k8], c0, c1);
        }
    }
#pragma unroll
    for (int nt=0;nt<4;nt++){
        int c0=wn*32+nt*8+t4*2;
        int d00=r0-c0, d01=d00-1, d10=r1-c0, d11=d10-1;
        float p00 = (d00>=0)? accP[nt][0]*gp[d00] : 0.f;
        float p01 = (d01>=0)? accP[nt][1]*gp[d01] : 0.f;
        float p10 = (d10>=0)? accP[nt][2]*gp[d10] : 0.f;
        float p11 = (d11>=0)? accP[nt][3]*gp[d11] : 0.f;
        bQ[r0*68+c0  ]=tfr(p00);
        bQ[r0*68+c0+1]=tfr(p01);
        bQ[r1*68+c0  ]=tfr(p10);
        bQ[r1*68+c0+1]=tfr(p11);
        *(float2*)(bK + r0*72 + c0) = make_float2(accPP[nt][0],accPP[nt][1]);
        *(float2*)(bK + r1*72 + c0) = make_float2(accPP[nt][2],accPP[nt][3]);
        float gq0=gp[r0+1], gq1=gp[r1+1];
        accQ[nt][0]*=gq0; accQ[nt][1]*=gq0;
        accQ[nt][2]*=gq1; accQ[nt][3]*=gq1;
    }
    __syncthreads();
#pragma unroll
    for (int k8=0;k8<8;k8++){
        int k=k8*8;
        unsigned pa[4];
        pa[0]=__float_as_uint(bQ[(m0+g  )*68 + k+t4  ]);
        pa[1]=__float_as_uint(bQ[(m0+g+8)*68 + k+t4  ]);
        pa[2]=__float_as_uint(bQ[(m0+g  )*68 + k+t4+4]);
        pa[3]=__float_as_uint(bQ[(m0+g+8)*68 + k+t4+4]);
#pragma unroll
        for (int nt=0;nt<4;nt++){
            int cb=wn*32+nt*8;
            unsigned b0=__float_as_uint(bV[(k+t4  )*72 + cb+g]);
            unsigned b1=__float_as_uint(bV[(k+t4+4)*72 + cb+g]);
            mma8(accQ[nt], pa, b0, b1);
        }
    }
    {
        int e = tid&63, q = tid>>6;
        float g1 = gp[1];
        float loc[16];
        float c = 0.f;
#pragma unroll
        for (int i=15;i>=0;--i){
            c = bK[(q*16+i)*72 + e] + g1*c;
            loc[i] = c;
        }
        carry[q*64+e] = loc[0];
        __syncthreads();
        float F = 0.f;
        if (q<3) F  = carry[(q+1)*64+e];
        if (q<2) F += gp[16]*carry[(q+2)*64+e];
        if (q<1) F += gp[32]*carry[(q+3)*64+e];
#pragma unroll
        for (int i=0;i<16;i++){
            bK[(q*16+i)*72 + e] = loc[i] + gp[16-i]*F;
        }
    }
    __syncthreads();
    float s1=0.f, s2=0.f;
    float gx0=gp[64-r0], gx1=gp[64-r1];
#pragma unroll
    for (int nt=0;nt<4;nt++){
        int c0=wn*32+nt*8+t4*2;
        float v00 = accQ[nt][0] + bK[r0*72+c0  ] + gx0*Xs[c0  ];
        float v01 = accQ[nt][1] + bK[r0*72+c0+1] + gx0*Xs[c0+1];
        float v10 = accQ[nt][2] + bK[r1*72+c0  ] + gx1*Xs[c0  ];
        float v11 = accQ[nt][3] + bK[r1*72+c0+1] + gx1*Xs[c0+1];
        s1 += v00+v01+v10+v11;
        s2 += v00*v00+v01*v01+v10*v10+v11*v11;
        *(float2*)(g_ret + base + (size_t)r0*64 + c0) = make_float2(v00,v01);
        *(float2*)(g_ret + base + (size_t)r1*64 + c0) = make_float2(v10,v11);
    }
#pragma unroll
    for (int o=16;o>0;o>>=1){
        s1 += __shfl_down_sync(0xffffffffu, s1, o);
        s2 += __shfl_down_sync(0xffffffffu, s2, o);
    }
    if (lane==0){ redS[warp]=s1; redQ[warp]=s2; }
    __syncthreads();
    if (tid==0){
        float a=0.f,bq=0.f;
#pragma unroll
        for (int w=0;w<8;w++){ a+=redS[w]; bq+=redQ[w]; }
        g_stat[(size_t)bid*2  ]=a;
        g_stat[(size_t)bid*2+1]=bq;
    }
}

// ================= K5: per-batch GroupNorm stats =================
__global__ void __launch_bounds__(512) k_stats()
{
    __shared__ float r1[512], r2[512];
    int b=blockIdx.x, tid=threadIdx.x;
    r1[tid]=g_stat[(size_t)(b*512+tid)*2];
    r2[tid]=g_stat[(size_t)(b*512+tid)*2+1];
    __syncthreads();
    for (int o=256;o>0;o>>=1){
        if (tid<o){ r1[tid]+=r1[tid+o]; r2[tid]+=r2[tid+o]; }
        __syncthreads();
    }
    if (tid==0){
        const float N = (float)((size_t)NH*NT*ND);
        float mu = r1[0]/N;
        float var = r2[0]/N - mu*mu;
        g_norm[b*2]=mu;
        g_norm[b*2+1]=rsqrtf(var+1e-5f);
    }
}

// ================= K6: normalize + layout to [B,T,NE] =================
__global__ void __launch_bounds__(256) k_out(const float* __restrict__ gnw,
                                             const float* __restrict__ gnb,
                                             float* __restrict__ out)
{
    int bid=blockIdx.x;
    int b=bid>>11, t=bid&2047;
    int tid=threadIdx.x;
    int h=tid>>4, d4=(tid&15)*4;
    float mu=g_norm[b*2], rs=g_norm[b*2+1];
    float w = gnw[h]*rs;
    float bb = gnb[h] - mu*w;
    float4 xv = *(const float4*)(g_ret + (((size_t)(b*NH+h))*NT + t)*ND + d4);
    float4 yv = make_float4(xv.x*w+bb, xv.y*w+bb, xv.z*w+bb, xv.w*w+bb);
    *(float4*)(out + (size_t)bid*NE + h*ND + d4) = yv;
}

// ================= K7: kv reduce + decay =================
__global__ void __launch_bounds__(256) k_kvout(const float* __restrict__ pkv,
                                               float* __restrict__ out_kv)
{
    int h=blockIdx.x;
    int idx=blockIdx.y*256+threadIdx.x;
    float s=0.f;
    for (int b=0;b<NB;b++){
        size_t bh=((size_t)(b*NH+h))*NCHK;
        for (int j2=0;j2<NCHK;j2++) s += g_kvc[(bh+j2)*4096 + idx];
    }
    double gd = 1.0 - exp2(-5.0-(double)h);
    out_kv[(size_t)h*4096 + idx] = (float)gd*pkv[(size_t)h*4096 + idx] + 0.25f*s;
}

extern "C" void kernel_launch(void* const* d_in, const int* in_sizes, int n_in,
                              void* d_out, int out_size)
{
    const float* x   = (const float*)d_in[0];
    const float* pkv = (const float*)d_in[1];
    const float* Wq  = (const float*)d_in[2];
    const float* Wk  = (const float*)d_in[3];
    const float* Wv  = (const float*)d_in[4];
    const float* gnw = (const float*)d_in[5];
    const float* gnb = (const float*)d_in[6];
    float* out = (float*)d_out;

    cudaFuncSetAttribute(k_proj3, cudaFuncAttributeMaxDynamicSharedMemorySize, PROJ_SMEM);
    cudaFuncSetAttribute(k_pass1, cudaFuncAttributeMaxDynamicSharedMemorySize, P1_SMEM);
    cudaFuncSetAttribute(k_pass3, cudaFuncAttributeMaxDynamicSharedMemorySize, P3_SMEM);

    k_cvtx<<<(NX4 + NA4 + 255)/256, 256>>>(x, pkv);
    dim3 gcw(NE/64, NE/64, 3);
    k_cvtw<<<gcw, 256>>>(Wq, Wk, Wv);
    dim3 gproj(8, 64, 3);
    k_proj3<<<gproj, 256, PROJ_SMEM>>>();
    k_pass1<<<NBH*NCHK, 256, P1_SMEM>>>(pkv);
    dim3 gscan(NBH, 5);
    k_scan<<<gscan, 256>>>();
    k_pass3<<<NBH*NCHK, 256, P3_SMEM>>>();
    k_stats<<<NB, 512>>>();
    k_out<<<NB*NT, 256>>>(gnw, gnb, out);
    dim3 gkv(NH, 16);
    k_kvout<<<gkv, 256>>>(pkv, out + (size_t)NB*NT*NE);
}

// round 14
// speedup vs baseline: 1.7233x; 1.1034x over previous
#include <cuda_runtime.h>
#include <cuda_fp16.h>
#include <math.h>
#include <stdint.h>

#define NB 4
#define NT 2048
#define NH 16
#define ND 64
#define NE 1024
#define NC 64
#define NCHK 32
#define NBH (NB*NH)

// ---------------- scratch (device globals; no runtime allocation) ----------------
__device__ __half g_qh [(size_t)NB*NH*NT*ND];
__device__ __half g_kh [(size_t)NB*NH*NT*ND];
__device__ __half g_vh [(size_t)NB*NH*NT*ND];
__device__ float g_ret[(size_t)NB*NH*NT*ND];
__device__ float g_U  [(size_t)NBH*NCHK*ND*ND];
__device__ float g_S  [(size_t)NBH*NCHK*ND*ND];
__device__ float g_kvc[(size_t)NBH*NCHK*ND*ND];
__device__ float g_W  [(size_t)NBH*NCHK*ND];
__device__ float g_Xn [(size_t)NBH*NCHK*ND];
__device__ float g_stat[(size_t)NBH*NCHK*2];
__device__ float g_norm[NB*2];
__device__ __half g_xh [(size_t)NB*NT*NE];    // fp16 X
__device__ __half g_wh [(size_t)3*NE*NE];     // fp16 W^T (layout [n][k])
__device__ float  g_ar [(size_t)NH*ND*ND];    // tf32-rounded past_kv

__device__ __forceinline__ unsigned f2tf(float x){
    unsigned r;
    asm("cvt.rna.tf32.f32 %0, %1;" : "=r"(r) : "f"(x));
    return r;
}
__device__ __forceinline__ float tfr(float x){
    return __uint_as_float(f2tf(x));
}
__device__ __forceinline__ void mma8(float c[4], const unsigned a[4], unsigned b0, unsigned b1){
    asm volatile(
      "mma.sync.aligned.m16n8k8.row.col.f32.tf32.tf32.f32 "
      "{%0,%1,%2,%3},{%4,%5,%6,%7},{%8,%9},{%0,%1,%2,%3};"
      : "+f"(c[0]),"+f"(c[1]),"+f"(c[2]),"+f"(c[3])
      : "r"(a[0]),"r"(a[1]),"r"(a[2]),"r"(a[3]), "r"(b0),"r"(b1));
}
__device__ __forceinline__ void mma16(float c[4], const unsigned a[4], unsigned b0, unsigned b1){
    asm volatile(
      "mma.sync.aligned.m16n8k16.row.col.f32.f16.f16.f32 "
      "{%0,%1,%2,%3},{%4,%5,%6,%7},{%8,%9},{%0,%1,%2,%3};"
      : "+f"(c[0]),"+f"(c[1]),"+f"(c[2]),"+f"(c[3])
      : "r"(a[0]),"r"(a[1]),"r"(a[2]),"r"(a[3]), "r"(b0),"r"(b1));
}
__device__ __forceinline__ void ldsm4(unsigned r[4], unsigned addr){
    asm volatile("ldmatrix.sync.aligned.m8n8.x4.shared.b16 {%0,%1,%2,%3}, [%4];"
      : "=r"(r[0]),"=r"(r[1]),"=r"(r[2]),"=r"(r[3]) : "r"(addr));
}

#define CP16(dst_u32, src) \
    asm volatile("cp.async.ca.shared.global [%0], [%1], 16;" :: "r"(dst_u32), "l"(src))

// ================= K0a: X -> fp16, past_kv -> tf32 =================
#define NX4 ((NB*NT*NE)/4)       // 2097152
#define NA4 ((NH*ND*ND)/4)       // 16384
__global__ void __launch_bounds__(256) k_cvtx(const float* __restrict__ X,
                                              const float* __restrict__ pkv)
{
    int i = blockIdx.x*256 + threadIdx.x;
    if (i < NX4){
        float4 v = ((const float4*)X)[i];
        __half2 h0 = __floats2half2_rn(v.x, v.y);
        __half2 h1 = __floats2half2_rn(v.z, v.w);
        uint2 o;
        o.x = *(unsigned*)&h0;
        o.y = *(unsigned*)&h1;
        *(uint2*)&g_xh[(size_t)i*4] = o;
    } else {
        int off = i - NX4;
        if (off >= NA4) return;
        float4 v = ((const float4*)pkv)[off];
        v.x=tfr(v.x); v.y=tfr(v.y); v.z=tfr(v.z); v.w=tfr(v.w);
        ((float4*)g_ar)[off] = v;
    }
}

// ================= K0b: W -> fp16, transposed to [n][k] =================
__global__ void __launch_bounds__(256) k_cvtw(const float* __restrict__ Wq,
                                              const float* __restrict__ Wk,
                                              const float* __restrict__ Wv)
{
    __shared__ float sm[64*65];
    int sel = blockIdx.z;
    const float* W = (sel==0)?Wq:(sel==1)?Wk:Wv;
    __half* dst = g_wh + (size_t)sel*NE*NE;
    int k0 = blockIdx.x*64, n0 = blockIdx.y*64;
    int tid = threadIdx.x;
#pragma unroll
    for (int l=0;l<16;l++){
        int idx = tid + l*256;
        int r = idx>>6, c = idx&63;
        sm[c*65 + r] = W[(size_t)(k0+r)*NE + n0 + c];
    }
    __syncthreads();
#pragma unroll
    for (int l=0;l<8;l++){
        int idx = tid + l*256;
        int r = idx>>5, cp = idx&31;
        __half2 h = __floats2half2_rn(sm[r*65 + 2*cp], sm[r*65 + 2*cp + 1]);
        *(__half2*)&dst[(size_t)(n0+r)*NE + k0 + 2*cp] = h;
    }
}

// ================= K1: fused QKV projection (FP16 mma + ldmatrix, 3-stage) ===
#define A_STGH (128*24)
#define B_STGH (128*24)
#define PROJ_SMEM (3*(A_STGH+B_STGH)*2)
__global__ void __launch_bounds__(256) k_proj3()
{
    const int sel = blockIdx.z;
    const __half* Xh = g_xh;
    const __half* Wh = g_wh + (size_t)sel*NE*NE;
    __half* dst = (sel==0)?g_qh:(sel==1)?g_kh:g_vh;

    extern __shared__ __half hsm[];
    __half* As = hsm;
    __half* Bs = hsm + 3*A_STGH;

    const int tid = threadIdx.x;
    const int rowBase = blockIdx.y*128, colBase = blockIdx.x*128;
    const int warp = tid>>5, lane = tid&31;
    const int wm = warp&3, wn = warp>>2;
    const int g = lane>>2, t4 = lane&3;

    const int srow = tid>>1, shc = (tid&1)*8;

    const unsigned sA = (unsigned)__cvta_generic_to_shared(As);
    const unsigned sB = (unsigned)__cvta_generic_to_shared(Bs);
    const unsigned stA = (unsigned)A_STGH*2u, stB = (unsigned)B_STGH*2u;

    // ldmatrix lane offsets (bytes, stage-0 relative)
    const int l7 = lane&7;
    unsigned aoff[2], boff[4];
#pragma unroll
    for (int mt=0;mt<2;mt++){
        int row = wm*32 + mt*16 + l7 + ((lane&8)?8:0);
        int col = (lane&16)?8:0;
        aoff[mt] = sA + (unsigned)(row*24 + col)*2u;
    }
#pragma unroll
    for (int np=0;np<4;np++){
        int row = wn*64 + np*16 + l7 + ((lane&16)?8:0);
        int col = (lane&8)?8:0;
        boff[np] = sB + (unsigned)(row*24 + col)*2u;
    }

    float acc[2][8][4];
#pragma unroll
    for (int a=0;a<2;a++)
#pragma unroll
      for (int b=0;b<8;b++)
#pragma unroll
        for (int c=0;c<4;c++) acc[a][b][c]=0.f;

    auto issue = [&](int it, int st){
        int kb = it*16;
        const __half* xs = Xh + (size_t)(rowBase+srow)*NE + kb + shc;
        CP16(sA + st*stA + (unsigned)(srow*24 + shc)*2u, xs);
        const __half* ws = Wh + (size_t)(colBase+srow)*NE + kb + shc;
        CP16(sB + st*stB + (unsigned)(srow*24 + shc)*2u, ws);
        asm volatile("cp.async.commit_group;" ::: "memory");
    };

    const int NIT = NE/16;
    issue(0,0); issue(1,1);
    for (int it=0; it<NIT; it++){
        const int st = it%3;
        if (it+1<NIT){
            asm volatile("cp.async.wait_group 1;" ::: "memory");
        } else {
            asm volatile("cp.async.wait_group 0;" ::: "memory");
        }
        __syncthreads();
        if (it+2<NIT) issue(it+2, (it+2)%3);
        const unsigned oA = (unsigned)st*stA;
        const unsigned oB = (unsigned)st*stB;
        unsigned af[2][4];
        ldsm4(af[0], aoff[0] + oA);
        ldsm4(af[1], aoff[1] + oA);
#pragma unroll
        for (int np=0;np<4;np++){
            unsigned bf[4];
            ldsm4(bf, boff[np] + oB);
            mma16(acc[0][2*np  ], af[0], bf[0], bf[1]);
            mma16(acc[1][2*np  ], af[1], bf[0], bf[1]);
            mma16(acc[0][2*np+1], af[0], bf[2], bf[3]);
            mma16(acc[1][2*np+1], af[1], bf[2], bf[3]);
        }
    }
    // epilogue: store q/k/v as fp16
#pragma unroll
    for (int mt=0;mt<2;mt++)
#pragma unroll
    for (int nt=0;nt<8;nt++){
        int row = rowBase + wm*32 + mt*16 + g;
        int col = colBase + wn*64 + nt*8 + t4*2;
        int b_ = row>>11, t_ = row&2047, h_ = col>>6, d_ = col&63;
        __half2 h0 = __floats2half2_rn(acc[mt][nt][0], acc[mt][nt][1]);
        *(__half2*)(dst + (((size_t)(b_*NH+h_))*NT + t_)*ND + d_) = h0;
        int t2_ = (row+8)&2047;
        __half2 h1 = __floats2half2_rn(acc[mt][nt][2], acc[mt][nt][3]);
        *(__half2*)(dst + (((size_t)(b_*NH+h_))*NT + t2_)*ND + d_) = h1;
    }
}

// ================= K2: per-chunk U_j, KV_j (tensor core, fp16-source staging) =====
#define P1_SMEM ((4352 + 2*4608)*4)
__global__ void __launch_bounds__(256) k_pass1(const float* __restrict__ pkv)
{
    extern __shared__ float sm1[];
    float* bKT = sm1;          // 64x68 : K^T [d][i]
    float* bV  = sm1 + 4352;   // 64x72 : V  [i][e] (later Q)
    float* bVw = sm1 + 4352 + 4608; // 64x72 : gamma^{63-i} V (tf32)
    __shared__ float gp[65];
    __shared__ float red[4*64];
    __shared__ float qw[64];
    int tid=threadIdx.x, bid=blockIdx.x;
    int j=bid&31, bh=bid>>5, h=bh&15;
    size_t base = ((size_t)bh*NT + (size_t)j*NC)*ND;
    if (tid<=64){
        double gd = 1.0 - exp2(-5.0-(double)h);
        gp[tid]=(float)pow(gd,(double)tid);
    }
    __syncthreads();
#pragma unroll
    for (int l=0;l<2;l++){
        int idx = tid + l*256;
        int i=idx>>3, d8=(idx&7)*8;
        uint4 kk = *(const uint4*)(g_kh + base + (size_t)idx*8);
        float2 k0=__half22float2(*(__half2*)&kk.x), k1=__half22float2(*(__half2*)&kk.y);
        float2 k2=__half22float2(*(__half2*)&kk.z), k3=__half22float2(*(__half2*)&kk.w);
        bKT[(d8  )*68+i]=k0.x; bKT[(d8+1)*68+i]=k0.y;
        bKT[(d8+2)*68+i]=k1.x; bKT[(d8+3)*68+i]=k1.y;
        bKT[(d8+4)*68+i]=k2.x; bKT[(d8+5)*68+i]=k2.y;
        bKT[(d8+6)*68+i]=k3.x; bKT[(d8+7)*68+i]=k3.y;
        uint4 vv = *(const uint4*)(g_vh + base + (size_t)idx*8);
        float2 v0=__half22float2(*(__half2*)&vv.x), v1=__half22float2(*(__half2*)&vv.y);
        float2 v2=__half22float2(*(__half2*)&vv.z), v3=__half22float2(*(__half2*)&vv.w);
        *(float4*)(bV + i*72 + d8    ) = make_float4(v0.x,v0.y,v1.x,v1.y);
        *(float4*)(bV + i*72 + d8 + 4) = make_float4(v2.x,v2.y,v3.x,v3.y);
        float w = gp[63-i];
        bVw[i*72+d8  ]=tfr(v0.x*w); bVw[i*72+d8+1]=tfr(v0.y*w);
        bVw[i*72+d8+2]=tfr(v1.x*w); bVw[i*72+d8+3]=tfr(v1.y*w);
        bVw[i*72+d8+4]=tfr(v2.x*w); bVw[i*72+d8+5]=tfr(v2.y*w);
        bVw[i*72+d8+6]=tfr(v3.x*w); bVw[i*72+d8+7]=tfr(v3.y*w);
    }
    __syncthreads();
    const int warp=tid>>5, lane=tid&31;
    const int wm=warp&3, wn=warp>>2, g=lane>>2, t4=lane&3;
    const int m0=wm*16;
    const int r0=m0+g, r1=r0+8;

    unsigned ka[8][4];
#pragma unroll
    for (int k8=0;k8<8;k8++){
        int k=k8*8;
        ka[k8][0]=__float_as_uint(bKT[(m0+g  )*68 + k+t4  ]);
        ka[k8][1]=__float_as_uint(bKT[(m0+g+8)*68 + k+t4  ]);
        ka[k8][2]=__float_as_uint(bKT[(m0+g  )*68 + k+t4+4]);
        ka[k8][3]=__float_as_uint(bKT[(m0+g+8)*68 + k+t4+4]);
    }

    float accKV[4][4]={}, accU[4][4]={};
#pragma unroll
    for (int k8=0;k8<8;k8++){
#pragma unroll
        for (int nt=0;nt<4;nt++){
            int cb=wn*32+nt*8;
            unsigned b0=__float_as_uint(bV [(k8*8+t4  )*72 + cb+g]);
            unsigned b1=__float_as_uint(bV [(k8*8+t4+4)*72 + cb+g]);
            mma8(accKV[nt], ka[k8], b0, b1);
            unsigned c0=__float_as_uint(bVw[(k8*8+t4  )*72 + cb+g]);
            unsigned c1=__float_as_uint(bVw[(k8*8+t4+4)*72 + cb+g]);
            mma8(accU[nt], ka[k8], c0, c1);
        }
    }
    {
        float* Kp = g_kvc + (size_t)bid*4096;
        float* Up = g_U  + (size_t)bid*4096;
#pragma unroll
        for (int nt=0;nt<4;nt++){
            int c0=wn*32+nt*8+t4*2;
            *(float2*)(Kp + r0*64 + c0) = make_float2(accKV[nt][0],accKV[nt][1]);
            *(float2*)(Kp + r1*64 + c0) = make_float2(accKV[nt][2],accKV[nt][3]);
            *(float2*)(Up + r0*64 + c0) = make_float2(accU[nt][0],accU[nt][1]);
            *(float2*)(Up + r1*64 + c0) = make_float2(accU[nt][2],accU[nt][3]);
        }
    }
    __syncthreads();
#pragma unroll
    for (int l=0;l<2;l++){
        int idx=tid+l*256;
        int i=idx>>3, d8=(idx&7)*8;
        uint4 qq = *(const uint4*)(g_qh + base + (size_t)idx*8);
        float2 q0=__half22float2(*(__half2*)&qq.x), q1=__half22float2(*(__half2*)&qq.y);
        float2 q2=__half22float2(*(__half2*)&qq.z), q3=__half22float2(*(__half2*)&qq.w);
        *(float4*)(bV + i*72 + d8    ) = make_float4(q0.x,q0.y,q1.x,q1.y);
        *(float4*)(bV + i*72 + d8 + 4) = make_float4(q2.x,q2.y,q3.x,q3.y);
    }
    __syncthreads();
    int rr = tid>>6, d = tid&63;
    float s = 0.f;
#pragma unroll
    for (int i=rr*16;i<rr*16+16;i++) s += gp[i]*bV[i*72 + d];
    red[rr*64 + d] = s;
    __syncthreads();
    if (tid<64) qw[tid] = red[tid] + red[64+tid] + red[128+tid] + red[192+tid];
    __syncthreads();
    const float* A = pkv + (size_t)h*4096;
    float s2 = 0.f;
#pragma unroll
    for (int dd=rr*16; dd<rr*16+16; dd++) s2 += qw[dd]*A[dd*64 + d];
    red[rr*64 + d] = s2;
    __syncthreads();
    if (tid<64) g_W[(size_t)bid*64 + tid] = red[tid] + red[64+tid] + red[128+tid] + red[192+tid];
}

// ================= K3: chunk scans (4 chains/thread, 8-iter batched loads) ========
__global__ void __launch_bounds__(256) k_scan()
{
    int bh = blockIdx.x, part = blockIdx.y, tid = threadIdx.x;
    int h = bh&15;
    double gd = 1.0 - exp2(-5.0-(double)h);
    float g64 = (float)pow(gd,64.0);
    if (part < 4){
        size_t ob = (size_t)bh*NCHK*4096 + (size_t)part*1024 + tid;
        float S[4] = {0.f,0.f,0.f,0.f};
        for (int j=0;j<NCHK;j+=8){
            float u[8][4];
#pragma unroll
            for (int jj=0;jj<8;jj++)
#pragma unroll
                for (int r=0;r<4;r++)
                    u[jj][r] = g_U[ob + (size_t)(j+jj)*4096 + r*256];
#pragma unroll
            for (int jj=0;jj<8;jj++){
#pragma unroll
                for (int r=0;r<4;r++){
                    g_S[ob + (size_t)(j+jj)*4096 + r*256] = tfr(S[r]);
                    S[r] = g64*S[r] + u[jj][r];
                }
            }
        }
    } else {
        if (tid < 64){
            size_t ob2 = (size_t)bh*NCHK*64 + tid;
            float X = 0.f;
            for (int j=NCHK-8; j>=0; j-=8){
                float w[8];
#pragma unroll
                for (int jj=0;jj<8;jj++) w[jj] = g_W[ob2 + (size_t)(j+jj)*64];
#pragma unroll
                for (int jj=7;jj>=0;jj--){
                    g_Xn[ob2 + (size_t)(j+jj)*64] = X;
                    X = g64*X + w[jj];
                }
            }
        }
    }
}

// ================= K4: per-chunk finalize (tensor core, fp16-source staging) ======
#define P3_SMEM ((4352 + 4*4608)*4)
__global__ void __launch_bounds__(256) k_pass3()
{
    extern __shared__ float sm3[];
    float* bQ = sm3;                  // 64x68 : Q [i][d] -> P tf32
    float* bK = sm3 + 4352;           // 64x72 : K^T [d][s] -> scan buffer
    float* bS = sm3 + 4352 + 4608;    // 64x72 : S (tf32, cp.async)
    float* bA = sm3 + 4352 + 2*4608;  // 64x72 : past_kv (tf32, cp.async)
    float* bV = sm3 + 4352 + 3*4608;  // 64x72 : V (from fp16)
    __shared__ float gp[65];
    __shared__ float Xs[64];
    __shared__ float carry[4*64];
    __shared__ float redS[8], redQ[8];
    int tid=threadIdx.x, bid=blockIdx.x;
    int j=bid&31, bh=bid>>5, h=bh&15;
    size_t base=((size_t)bh*NT+(size_t)j*NC)*ND;

    {
        const unsigned sb = (unsigned)__cvta_generic_to_shared(sm3);
        const float* Ssrc = g_S + ((size_t)bh*NCHK+j)*4096;
        const float* Asrc = g_ar + (size_t)h*4096;
#pragma unroll
        for (int l=0;l<4;l++){
            int idx=tid+l*256;
            unsigned o = (unsigned)((idx>>4)*72 + (idx&15)*4)*4u;
            CP16(sb + (4352u+  4608u)*4u + o, Ssrc + (size_t)idx*4);
            CP16(sb + (4352u+2*4608u)*4u + o, Asrc + (size_t)idx*4);
        }
        asm volatile("cp.async.commit_group;" ::: "memory");
    }
    if (tid<=64){
        double gd = 1.0 - exp2(-5.0-(double)h);
        gp[tid]=(float)pow(gd,(double)tid);
    }
    if (tid<64) Xs[tid] = g_Xn[((size_t)bh*NCHK+j)*64 + tid];
#pragma unroll
    for (int l=0;l<2;l++){
        int idx=tid+l*256;
        int i=idx>>3, d8=(idx&7)*8;
        uint4 qq = *(const uint4*)(g_qh + base + (size_t)idx*8);
        float2 q0=__half22float2(*(__half2*)&qq.x), q1=__half22float2(*(__half2*)&qq.y);
        float2 q2=__half22float2(*(__half2*)&qq.z), q3=__half22float2(*(__half2*)&qq.w);
        *(float4*)(bQ + i*68 + d8    ) = make_float4(q0.x,q0.y,q1.x,q1.y);
        *(float4*)(bQ + i*68 + d8 + 4) = make_float4(q2.x,q2.y,q3.x,q3.y);
        uint4 kk = *(const uint4*)(g_kh + base + (size_t)idx*8);
        float2 k0=__half22float2(*(__half2*)&kk.x), k1=__half22float2(*(__half2*)&kk.y);
        float2 k2=__half22float2(*(__half2*)&kk.z), k3=__half22float2(*(__half2*)&kk.w);
        bK[(d8  )*72+i]=k0.x; bK[(d8+1)*72+i]=k0.y;
        bK[(d8+2)*72+i]=k1.x; bK[(d8+3)*72+i]=k1.y;
        bK[(d8+4)*72+i]=k2.x; bK[(d8+5)*72+i]=k2.y;
        bK[(d8+6)*72+i]=k3.x; bK[(d8+7)*72+i]=k3.y;
        uint4 vv = *(const uint4*)(g_vh + base + (size_t)idx*8);
        float2 v0=__half22float2(*(__half2*)&vv.x), v1=__half22float2(*(__half2*)&vv.y);
        float2 v2=__half22float2(*(__half2*)&vv.z), v3=__half22float2(*(__half2*)&vv.w);
        *(float4*)(bV + i*72 + d8    ) = make_float4(v0.x,v0.y,v1.x,v1.y);
        *(float4*)(bV + i*72 + d8 + 4) = make_float4(v2.x,v2.y,v3.x,v3.y);
    }
    __syncthreads();
    const int warp=tid>>5, lane=tid&31;
    const int wm=warp&3, wn=warp>>2, g=lane>>2, t4=lane&3;
    const int m0=wm*16;
    const int r0=m0+g, r1=r0+8;

    unsigned qa[8][4];
#pragma unroll
    for (int k8=0;k8<8;k8++){
        int k=k8*8;
        qa[k8][0]=__float_as_uint(bQ[(m0+g  )*68 + k+t4  ]);
        qa[k8][1]=__float_as_uint(bQ[(m0+g+8)*68 + k+t4  ]);
        qa[k8][2]=__float_as_uint(bQ[(m0+g  )*68 + k+t4+4]);
        qa[k8][3]=__float_as_uint(bQ[(m0+g+8)*68 + k+t4+4]);
    }
    float accP[4][4]={};
#pragma unroll
    for (int k8=0;k8<8;k8++){
#pragma unroll
        for (int nt=0;nt<4;nt++){
            int cb=wn*32+nt*8;
            unsigned b0=__float_as_uint(bK[(k8*8+t4  )*72 + cb+g]);
            unsigned b1=__float_as_uint(bK[(k8*8+t4+4)*72 + cb+g]);
            mma8(accP[nt], qa[k8], b0, b1);
        }
    }
    asm volatile("cp.async.wait_group 0;" ::: "memory");
    __syncthreads();
    float accQ[4][4]={}, accPP[4][4]={};
#pragma unroll
    for (int k8=0;k8<8;k8++){
#pragma unroll
        for (int nt=0;nt<4;nt++){
            int cb=wn*32+nt*8;
            unsigned b0=__float_as_uint(bS[(k8*8+t4  )*72 + cb+g]);
            unsigned b1=__float_as_uint(bS[(k8*8+t4+4)*72 + cb+g]);
            mma8(accQ[nt], qa[k8], b0, b1);
            unsigned c0=__float_as_uint(bA[(k8*8+t4  )*72 + cb+g]);
            unsigned c1=__float_as_uint(bA[(k8*8+t4+4)*72 + cb+g]);
            mma8(accPP[nt], qa[k8], c0, c1);
        }
    }
#pragma unroll
    for (int nt=0;nt<4;nt++){
        int c0=wn*32+nt*8+t4*2;
        int d00=r0-c0, d01=d00-1, d10=r1-c0, d11=d10-1;
        float p00 = (d00>=0)? accP[nt][0]*gp[d00] : 0.f;
        float p01 = (d01>=0)? accP[nt][1]*gp[d01] : 0.f;
        float p10 = (d10>=0)? accP[nt][2]*gp[d10] : 0.f;
        float p11 = (d11>=0)? accP[nt][3]*gp[d11] : 0.f;
        bQ[r0*68+c0  ]=tfr(p00);
        bQ[r0*68+c0+1]=tfr(p01);
        bQ[r1*68+c0  ]=tfr(p10);
        bQ[r1*68+c0+1]=tfr(p11);
        *(float2*)(bK + r0*72 + c0) = make_float2(accPP[nt][0],accPP[nt][1]);
        *(float2*)(bK + r1*72 + c0) = make_float2(accPP[nt][2],accPP[nt][3]);
        float gq0=gp[r0+1], gq1=gp[r1+1];
        accQ[nt][0]*=gq0; accQ[nt][1]*=gq0;
        accQ[nt][2]*=gq1; accQ[nt][3]*=gq1;
    }
    __syncthreads();
#pragma unroll
    for (int k8=0;k8<8;k8++){
        int k=k8*8;
        unsigned pa[4];
        pa[0]=__float_as_uint(bQ[(m0+g  )*68 + k+t4  ]);
        pa[1]=__float_as_uint(bQ[(m0+g+8)*68 + k+t4  ]);
        pa[2]=__float_as_uint(bQ[(m0+g  )*68 + k+t4+4]);
        pa[3]=__float_as_uint(bQ[(m0+g+8)*68 + k+t4+4]);
#pragma unroll
        for (int nt=0;nt<4;nt++){
            int cb=wn*32+nt*8;
            unsigned b0=__float_as_uint(bV[(k+t4  )*72 + cb+g]);
            unsigned b1=__float_as_uint(bV[(k+t4+4)*72 + cb+g]);
            mma8(accQ[nt], pa, b0, b1);
        }
    }
    {
        int e = tid&63, q = tid>>6;
        float g1 = gp[1];
        float loc[16];
        float c = 0.f;
#pragma unroll
        for (int i=15;i>=0;--i){
            c = bK[(q*16+i)*72 + e] + g1*c;
            loc[i] = c;
        }
        carry[q*64+e] = loc[0];
        __syncthreads();
        float F = 0.f;
        if (q<3) F  = carry[(q+1)*64+e];
        if (q<2) F += gp[16]*carry[(q+2)*64+e];
        if (q<1) F += gp[32]*carry[(q+3)*64+e];
#pragma unroll
        for (int i=0;i<16;i++){
            bK[(q*16+i)*72 + e] = loc[i] + gp[16-i]*F;
        }
    }
    __syncthreads();
    float s1=0.f, s2=0.f;
    float gx0=gp[64-r0], gx1=gp[64-r1];
#pragma unroll
    for (int nt=0;nt<4;nt++){
        int c0=wn*32+nt*8+t4*2;
        float v00 = accQ[nt][0] + bK[r0*72+c0  ] + gx0*Xs[c0  ];
        float v01 = accQ[nt][1] + bK[r0*72+c0+1] + gx0*Xs[c0+1];
        float v10 = accQ[nt][2] + bK[r1*72+c0  ] + gx1*Xs[c0  ];
        float v11 = accQ[nt][3] + bK[r1*72+c0+1] + gx1*Xs[c0+1];
        s1 += v00+v01+v10+v11;
        s2 += v00*v00+v01*v01+v10*v10+v11*v11;
        *(float2*)(g_ret + base + (size_t)r0*64 + c0) = make_float2(v00,v01);
        *(float2*)(g_ret + base + (size_t)r1*64 + c0) = make_float2(v10,v11);
    }
#pragma unroll
    for (int o=16;o>0;o>>=1){
        s1 += __shfl_down_sync(0xffffffffu, s1, o);
        s2 += __shfl_down_sync(0xffffffffu, s2, o);
    }
    if (lane==0){ redS[warp]=s1; redQ[warp]=s2; }
    __syncthreads();
    if (tid==0){
        float a=0.f,bq=0.f;
#pragma unroll
        for (int w=0;w<8;w++){ a+=redS[w]; bq+=redQ[w]; }
        g_stat[(size_t)bid*2  ]=a;
        g_stat[(size_t)bid*2+1]=bq;
    }
}

// ================= K5: per-batch GroupNorm stats =================
__global__ void __launch_bounds__(512) k_stats()
{
    __shared__ float r1[512], r2[512];
    int b=blockIdx.x, tid=threadIdx.x;
    r1[tid]=g_stat[(size_t)(b*512+tid)*2];
    r2[tid]=g_stat[(size_t)(b*512+tid)*2+1];
    __syncthreads();
    for (int o=256;o>0;o>>=1){
        if (tid<o){ r1[tid]+=r1[tid+o]; r2[tid]+=r2[tid+o]; }
        __syncthreads();
    }
    if (tid==0){
        const float N = (float)((size_t)NH*NT*ND);
        float mu = r1[0]/N;
        float var = r2[0]/N - mu*mu;
        g_norm[b*2]=mu;
        g_norm[b*2+1]=rsqrtf(var+1e-5f);
    }
}

// ================= K6: normalize + layout to [B,T,NE] =================
__global__ void __launch_bounds__(256) k_out(const float* __restrict__ gnw,
                                             const float* __restrict__ gnb,
                                             float* __restrict__ out)
{
    int bid=blockIdx.x;
    int b=bid>>11, t=bid&2047;
    int tid=threadIdx.x;
    int h=tid>>4, d4=(tid&15)*4;
    float mu=g_norm[b*2], rs=g_norm[b*2+1];
    float w = gnw[h]*rs;
    float bb = gnb[h] - mu*w;
    float4 xv = *(const float4*)(g_ret + (((size_t)(b*NH+h))*NT + t)*ND + d4);
    float4 yv = make_float4(xv.x*w+bb, xv.y*w+bb, xv.z*w+bb, xv.w*w+bb);
    *(float4*)(out + (size_t)bid*NE + h*ND + d4) = yv;
}

// ================= K7: kv reduce + decay (batched loads) =================
__global__ void __launch_bounds__(256) k_kvout(const float* __restrict__ pkv,
                                               float* __restrict__ out_kv)
{
    int h=blockIdx.x;
    int idx=blockIdx.y*256+threadIdx.x;
    float s=0.f;
    for (int b=0;b<NB;b++){
        size_t bh=((size_t)(b*NH+h))*NCHK;
        for (int j2=0;j2<NCHK;j2+=8){
            float t[8];
#pragma unroll
            for (int jj=0;jj<8;jj++) t[jj] = g_kvc[(bh+j2+jj)*4096 + idx];
#pragma unroll
            for (int jj=0;jj<8;jj++) s += t[jj];
        }
    }
    double gd = 1.0 - exp2(-5.0-(double)h);
    out_kv[(size_t)h*4096 + idx] = (float)gd*pkv[(size_t)h*4096 + idx] + 0.25f*s;
}

extern "C" void kernel_launch(void* const* d_in, const int* in_sizes, int n_in,
                              void* d_out, int out_size)
{
    const float* x   = (const float*)d_in[0];
    const float* pkv = (const float*)d_in[1];
    const float* Wq  = (const float*)d_in[2];
    const float* Wk  = (const float*)d_in[3];
    const float* Wv  = (const float*)d_in[4];
    const float* gnw = (const float*)d_in[5];
    const float* gnb = (const float*)d_in[6];
    float* out = (float*)d_out;

    cudaFuncSetAttribute(k_proj3, cudaFuncAttributeMaxDynamicSharedMemorySize, PROJ_SMEM);
    cudaFuncSetAttribute(k_pass1, cudaFuncAttributeMaxDynamicSharedMemorySize, P1_SMEM);
    cudaFuncSetAttribute(k_pass3, cudaFuncAttributeMaxDynamicSharedMemorySize, P3_SMEM);

    k_cvtx<<<(NX4 + NA4 + 255)/256, 256>>>(x, pkv);
    dim3 gcw(NE/64, NE/64, 3);
    k_cvtw<<<gcw, 256>>>(Wq, Wk, Wv);
    dim3 gproj(8, 64, 3);
    k_proj3<<<gproj, 256, PROJ_SMEM>>>();
    k_pass1<<<NBH*NCHK, 256, P1_SMEM>>>(pkv);
    dim3 gscan(NBH, 5);
    k_scan<<<gscan, 256>>>();
    k_pass3<<<NBH*NCHK, 256, P3_SMEM>>>();
    k_stats<<<NB, 512>>>();
    k_out<<<NB*NT, 256>>>(gnw, gnb, out);
    dim3 gkv(NH, 16);
    k_kvout<<<gkv, 256>>>(pkv, out + (size_t)NB*NT*NE);
}

// round 15
// speedup vs baseline: 1.8393x; 1.0673x over previous
#include <cuda_runtime.h>
#include <cuda_fp16.h>
#include <math.h>
#include <stdint.h>

#define NB 4
#define NT 2048
#define NH 16
#define ND 64
#define NE 1024
#define NC 64
#define NCHK 32
#define NBH (NB*NH)

// ---------------- scratch (device globals; no runtime allocation) ----------------
__device__ __half g_qh [(size_t)NB*NH*NT*ND];
__device__ __half g_kh [(size_t)NB*NH*NT*ND];
__device__ __half g_vh [(size_t)NB*NH*NT*ND];
__device__ float g_ret[(size_t)NB*NH*NT*ND];
__device__ float g_U  [(size_t)NBH*NCHK*ND*ND];
__device__ __half g_S [(size_t)NBH*NCHK*ND*ND];
__device__ float g_kvc[(size_t)NBH*NCHK*ND*ND];
__device__ float g_W  [(size_t)NBH*NCHK*ND];
__device__ float g_Xn [(size_t)NBH*NCHK*ND];
__device__ float g_stat[(size_t)NBH*NCHK*2];
__device__ float g_norm[NB*2];
__device__ __half g_xh [(size_t)NB*NT*NE];    // fp16 X
__device__ __half g_wh [(size_t)3*NE*NE];     // fp16 W^T (layout [n][k])
__device__ __half g_ar [(size_t)NH*ND*ND];    // fp16 past_kv

__device__ __forceinline__ void mma16(float c[4], const unsigned a[4], unsigned b0, unsigned b1){
    asm volatile(
      "mma.sync.aligned.m16n8k16.row.col.f32.f16.f16.f32 "
      "{%0,%1,%2,%3},{%4,%5,%6,%7},{%8,%9},{%0,%1,%2,%3};"
      : "+f"(c[0]),"+f"(c[1]),"+f"(c[2]),"+f"(c[3])
      : "r"(a[0]),"r"(a[1]),"r"(a[2]),"r"(a[3]), "r"(b0),"r"(b1));
}
__device__ __forceinline__ void ldsm4(unsigned r[4], unsigned addr){
    asm volatile("ldmatrix.sync.aligned.m8n8.x4.shared.b16 {%0,%1,%2,%3}, [%4];"
      : "=r"(r[0]),"=r"(r[1]),"=r"(r[2]),"=r"(r[3]) : "r"(addr));
}
__device__ __forceinline__ void ldsm4t(unsigned r[4], unsigned addr){
    asm volatile("ldmatrix.sync.aligned.m8n8.x4.trans.shared.b16 {%0,%1,%2,%3}, [%4];"
      : "=r"(r[0]),"=r"(r[1]),"=r"(r[2]),"=r"(r[3]) : "r"(addr));
}

#define CP16(dst_u32, src) \
    asm volatile("cp.async.ca.shared.global [%0], [%1], 16;" :: "r"(dst_u32), "l"(src))

// ================= K0a: X -> fp16, past_kv -> fp16 =================
#define NX4 ((NB*NT*NE)/4)       // 2097152
#define NA4 ((NH*ND*ND)/4)       // 16384
__global__ void __launch_bounds__(256) k_cvtx(const float* __restrict__ X,
                                              const float* __restrict__ pkv)
{
    int i = blockIdx.x*256 + threadIdx.x;
    if (i < NX4){
        float4 v = ((const float4*)X)[i];
        __half2 h0 = __floats2half2_rn(v.x, v.y);
        __half2 h1 = __floats2half2_rn(v.z, v.w);
        uint2 o;
        o.x = *(unsigned*)&h0;
        o.y = *(unsigned*)&h1;
        *(uint2*)&g_xh[(size_t)i*4] = o;
    } else {
        int off = i - NX4;
        if (off >= NA4) return;
        float4 v = ((const float4*)pkv)[off];
        __half2 h0 = __floats2half2_rn(v.x, v.y);
        __half2 h1 = __floats2half2_rn(v.z, v.w);
        uint2 o;
        o.x = *(unsigned*)&h0;
        o.y = *(unsigned*)&h1;
        *(uint2*)&g_ar[(size_t)off*4] = o;
    }
}

// ================= K0b: W -> fp16, transposed to [n][k] =================
__global__ void __launch_bounds__(256) k_cvtw(const float* __restrict__ Wq,
                                              const float* __restrict__ Wk,
                                              const float* __restrict__ Wv)
{
    __shared__ float sm[64*65];
    int sel = blockIdx.z;
    const float* W = (sel==0)?Wq:(sel==1)?Wk:Wv;
    __half* dst = g_wh + (size_t)sel*NE*NE;
    int k0 = blockIdx.x*64, n0 = blockIdx.y*64;
    int tid = threadIdx.x;
#pragma unroll
    for (int l=0;l<16;l++){
        int idx = tid + l*256;
        int r = idx>>6, c = idx&63;
        sm[c*65 + r] = W[(size_t)(k0+r)*NE + n0 + c];
    }
    __syncthreads();
#pragma unroll
    for (int l=0;l<8;l++){
        int idx = tid + l*256;
        int r = idx>>5, cp = idx&31;
        __half2 h = __floats2half2_rn(sm[r*65 + 2*cp], sm[r*65 + 2*cp + 1]);
        *(__half2*)&dst[(size_t)(n0+r)*NE + k0 + 2*cp] = h;
    }
}

// ================= K1: fused QKV projection (FP16 mma + ldmatrix, 3-stage) ===
#define A_STGH (128*24)
#define B_STGH (128*24)
#define PROJ_SMEM (3*(A_STGH+B_STGH)*2)
__global__ void __launch_bounds__(256) k_proj3()
{
    const int sel = blockIdx.z;
    const __half* Xh = g_xh;
    const __half* Wh = g_wh + (size_t)sel*NE*NE;
    __half* dst = (sel==0)?g_qh:(sel==1)?g_kh:g_vh;

    extern __shared__ __half hsm[];
    __half* As = hsm;
    __half* Bs = hsm + 3*A_STGH;

    const int tid = threadIdx.x;
    const int rowBase = blockIdx.y*128, colBase = blockIdx.x*128;
    const int warp = tid>>5, lane = tid&31;
    const int wm = warp&3, wn = warp>>2;
    const int g = lane>>2, t4 = lane&3;

    const int srow = tid>>1, shc = (tid&1)*8;

    const unsigned sA = (unsigned)__cvta_generic_to_shared(As);
    const unsigned sB = (unsigned)__cvta_generic_to_shared(Bs);
    const unsigned stA = (unsigned)A_STGH*2u, stB = (unsigned)B_STGH*2u;

    const int l7 = lane&7;
    unsigned aoff[2], boff[4];
#pragma unroll
    for (int mt=0;mt<2;mt++){
        int row = wm*32 + mt*16 + l7 + ((lane&8)?8:0);
        int col = (lane&16)?8:0;
        aoff[mt] = sA + (unsigned)(row*24 + col)*2u;
    }
#pragma unroll
    for (int np=0;np<4;np++){
        int row = wn*64 + np*16 + l7 + ((lane&16)?8:0);
        int col = (lane&8)?8:0;
        boff[np] = sB + (unsigned)(row*24 + col)*2u;
    }

    float acc[2][8][4];
#pragma unroll
    for (int a=0;a<2;a++)
#pragma unroll
      for (int b=0;b<8;b++)
#pragma unroll
        for (int c=0;c<4;c++) acc[a][b][c]=0.f;

    auto issue = [&](int it, int st){
        int kb = it*16;
        const __half* xs = Xh + (size_t)(rowBase+srow)*NE + kb + shc;
        CP16(sA + st*stA + (unsigned)(srow*24 + shc)*2u, xs);
        const __half* ws = Wh + (size_t)(colBase+srow)*NE + kb + shc;
        CP16(sB + st*stB + (unsigned)(srow*24 + shc)*2u, ws);
        asm volatile("cp.async.commit_group;" ::: "memory");
    };

    const int NIT = NE/16;
    issue(0,0); issue(1,1);
    for (int it=0; it<NIT; it++){
        const int st = it%3;
        if (it+1<NIT){
            asm volatile("cp.async.wait_group 1;" ::: "memory");
        } else {
            asm volatile("cp.async.wait_group 0;" ::: "memory");
        }
        __syncthreads();
        if (it+2<NIT) issue(it+2, (it+2)%3);
        const unsigned oA = (unsigned)st*stA;
        const unsigned oB = (unsigned)st*stB;
        unsigned af[2][4];
        ldsm4(af[0], aoff[0] + oA);
        ldsm4(af[1], aoff[1] + oA);
#pragma unroll
        for (int np=0;np<4;np++){
            unsigned bf[4];
            ldsm4(bf, boff[np] + oB);
            mma16(acc[0][2*np  ], af[0], bf[0], bf[1]);
            mma16(acc[1][2*np  ], af[1], bf[0], bf[1]);
            mma16(acc[0][2*np+1], af[0], bf[2], bf[3]);
            mma16(acc[1][2*np+1], af[1], bf[2], bf[3]);
        }
    }
#pragma unroll
    for (int mt=0;mt<2;mt++)
#pragma unroll
    for (int nt=0;nt<8;nt++){
        int row = rowBase + wm*32 + mt*16 + g;
        int col = colBase + wn*64 + nt*8 + t4*2;
        int b_ = row>>11, t_ = row&2047, h_ = col>>6, d_ = col&63;
        __half2 h0 = __floats2half2_rn(acc[mt][nt][0], acc[mt][nt][1]);
        *(__half2*)(dst + (((size_t)(b_*NH+h_))*NT + t_)*ND + d_) = h0;
        int t2_ = (row+8)&2047;
        __half2 h1 = __floats2half2_rn(acc[mt][nt][2], acc[mt][nt][3]);
        *(__half2*)(dst + (((size_t)(b_*NH+h_))*NT + t2_)*ND + d_) = h1;
    }
}

// ================= K2: per-chunk U_j, KV_j (fp16 mma + ldmatrix) ==================
#define P1_SMEM (3*4608*2)
__global__ void __launch_bounds__(256) k_pass1(const float* __restrict__ pkv)
{
    extern __shared__ __half hs1[];
    __half* bK  = hs1;            // [i][72] fp16
    __half* bV  = hs1 + 4608;     // [i][72] fp16 (later Q fp16)
    __half* bVw = hs1 + 2*4608;   // gamma^{63-i} V fp16
    __shared__ float gp[65];
    __shared__ float red[4*64];
    __shared__ float qw[64];
    int tid=threadIdx.x, bid=blockIdx.x;
    int j=bid&31, bh=bid>>5, h=bh&15;
    size_t base = ((size_t)bh*NT + (size_t)j*NC)*ND;
    if (tid<=64){
        double gd = 1.0 - exp2(-5.0-(double)h);
        gp[tid]=(float)pow(gd,(double)tid);
    }
    __syncthreads();
#pragma unroll
    for (int l=0;l<2;l++){
        int idx = tid + l*256;
        int i=idx>>3, d8=(idx&7)*8;
        uint4 kk = *(const uint4*)(g_kh + base + (size_t)idx*8);
        *(uint4*)(bK + i*72 + d8) = kk;
        uint4 vv = *(const uint4*)(g_vh + base + (size_t)idx*8);
        *(uint4*)(bV + i*72 + d8) = vv;
        __half2 ws = __float2half2_rn(gp[63-i]);
        __half2 w0 = __hmul2(*(__half2*)&vv.x, ws);
        __half2 w1 = __hmul2(*(__half2*)&vv.y, ws);
        __half2 w2 = __hmul2(*(__half2*)&vv.z, ws);
        __half2 w3 = __hmul2(*(__half2*)&vv.w, ws);
        uint4 wo;
        wo.x=*(unsigned*)&w0; wo.y=*(unsigned*)&w1;
        wo.z=*(unsigned*)&w2; wo.w=*(unsigned*)&w3;
        *(uint4*)(bVw + i*72 + d8) = wo;
    }
    __syncthreads();
    const int warp=tid>>5, lane=tid&31;
    const int wm=warp&3, wn=warp>>2, g=lane>>2, t4=lane&3;
    const int m0=wm*16, cb=wn*32;
    const int r0=m0+g, r1=r0+8;
    const int l7=lane&7, x8=(lane&8)?8:0, x16=(lane&16)?8:0;

    const unsigned sK  = (unsigned)__cvta_generic_to_shared(bK);
    const unsigned sV  = (unsigned)__cvta_generic_to_shared(bV);
    const unsigned sVw = (unsigned)__cvta_generic_to_shared(bVw);

    float accKV[4][4]={}, accU[4][4]={};
#pragma unroll
    for (int ks=0;ks<4;ks++){
        // A = K^T (trans ldmatrix on K stored [i][d])
        unsigned a[4];
        ldsm4t(a, sK + (unsigned)((16*ks + l7 + x16)*72 + m0 + x8)*2u);
#pragma unroll
        for (int np=0;np<2;np++){
            unsigned tb = (unsigned)((16*ks + l7 + x8)*72 + cb + np*16 + x16)*2u;
            unsigned bf[4];
            ldsm4t(bf, sV + tb);
            mma16(accKV[np*2  ], a, bf[0], bf[1]);
            mma16(accKV[np*2+1], a, bf[2], bf[3]);
            unsigned cf[4];
            ldsm4t(cf, sVw + tb);
            mma16(accU[np*2  ], a, cf[0], cf[1]);
            mma16(accU[np*2+1], a, cf[2], cf[3]);
        }
    }
    {
        float* Kp = g_kvc + (size_t)bid*4096;
        float* Up = g_U  + (size_t)bid*4096;
#pragma unroll
        for (int nt=0;nt<4;nt++){
            int c0=cb+nt*8+t4*2;
            *(float2*)(Kp + r0*64 + c0) = make_float2(accKV[nt][0],accKV[nt][1]);
            *(float2*)(Kp + r1*64 + c0) = make_float2(accKV[nt][2],accKV[nt][3]);
            *(float2*)(Up + r0*64 + c0) = make_float2(accU[nt][0],accU[nt][1]);
            *(float2*)(Up + r1*64 + c0) = make_float2(accU[nt][2],accU[nt][3]);
        }
    }
    __syncthreads();
    // Q fp16 into bVw (free now)
#pragma unroll
    for (int l=0;l<2;l++){
        int idx=tid+l*256;
        int i=idx>>3, d8=(idx&7)*8;
        *(uint4*)(bVw + i*72 + d8) = *(const uint4*)(g_qh + base + (size_t)idx*8);
    }
    __syncthreads();
    int rr = tid>>6, d = tid&63;
    float s = 0.f;
#pragma unroll
    for (int i=rr*16;i<rr*16+16;i++) s += gp[i]*__half2float(bVw[i*72 + d]);
    red[rr*64 + d] = s;
    __syncthreads();
    if (tid<64) qw[tid] = red[tid] + red[64+tid] + red[128+tid] + red[192+tid];
    __syncthreads();
    const float* A = pkv + (size_t)h*4096;
    float s2 = 0.f;
#pragma unroll
    for (int dd=rr*16; dd<rr*16+16; dd++) s2 += qw[dd]*A[dd*64 + d];
    red[rr*64 + d] = s2;
    __syncthreads();
    if (tid<64) g_W[(size_t)bid*64 + tid] = red[tid] + red[64+tid] + red[128+tid] + red[192+tid];
}

// ================= K3: chunk scans (S stored fp16) ========
__global__ void __launch_bounds__(256) k_scan()
{
    int bh = blockIdx.x, part = blockIdx.y, tid = threadIdx.x;
    int h = bh&15;
    double gd = 1.0 - exp2(-5.0-(double)h);
    float g64 = (float)pow(gd,64.0);
    if (part < 4){
        size_t ob = (size_t)bh*NCHK*4096 + (size_t)part*1024 + tid;
        float S[4] = {0.f,0.f,0.f,0.f};
        for (int j=0;j<NCHK;j+=8){
            float u[8][4];
#pragma unroll
            for (int jj=0;jj<8;jj++)
#pragma unroll
                for (int r=0;r<4;r++)
                    u[jj][r] = g_U[ob + (size_t)(j+jj)*4096 + r*256];
#pragma unroll
            for (int jj=0;jj<8;jj++){
#pragma unroll
                for (int r=0;r<4;r++){
                    g_S[ob + (size_t)(j+jj)*4096 + r*256] = __float2half(S[r]);
                    S[r] = g64*S[r] + u[jj][r];
                }
            }
        }
    } else {
        if (tid < 64){
            size_t ob2 = (size_t)bh*NCHK*64 + tid;
            float X = 0.f;
            for (int j=NCHK-8; j>=0; j-=8){
                float w[8];
#pragma unroll
                for (int jj=0;jj<8;jj++) w[jj] = g_W[ob2 + (size_t)(j+jj)*64];
#pragma unroll
                for (int jj=7;jj>=0;jj--){
                    g_Xn[ob2 + (size_t)(j+jj)*64] = X;
                    X = g64*X + w[jj];
                }
            }
        }
    }
}

// ================= K4: per-chunk finalize (fp16 mma + ldmatrix) ====================
#define P3_SMEM (5*4608*2)
__global__ void __launch_bounds__(256) k_pass3()
{
    extern __shared__ __half hs3[];
    __half* bQ = hs3;             // Q [i][72] -> P fp16
    __half* bK = hs3 + 4608;      // K [s][72]
    __half* bS = hs3 + 2*4608;    // S [d][72]
    __half* bA = hs3 + 3*4608;    // past_kv [d][72]
    __half* bV = hs3 + 4*4608;    // V [s][72]
    float* scanbuf = (float*)(hs3 + 2*4608);   // overlays bS+bA: 64x72 fp32
    __shared__ float gp[65];
    __shared__ float Xs[64];
    __shared__ float carry[4*64];
    __shared__ float redS[8], redQ[8];
    int tid=threadIdx.x, bid=blockIdx.x;
    int j=bid&31, bh=bid>>5, h=bh&15;
    size_t base=((size_t)bh*NT+(size_t)j*NC)*ND;

    {
        const unsigned sb = (unsigned)__cvta_generic_to_shared(hs3);
        const __half* Qsrc = g_qh + base;
        const __half* Ksrc = g_kh + base;
        const __half* Ssrc = g_S + ((size_t)bh*NCHK+j)*4096;
        const __half* Asrc = g_ar + (size_t)h*4096;
        const __half* Vsrc = g_vh + base;
#pragma unroll
        for (int l=0;l<2;l++){
            int idx=tid+l*256;
            int i=idx>>3, d8=(idx&7)*8;
            unsigned o = (unsigned)(i*72 + d8)*2u;
            CP16(sb            + o, Qsrc + (size_t)idx*8);
            CP16(sb +   9216u  + o, Ksrc + (size_t)idx*8);
            CP16(sb + 2*9216u  + o, Ssrc + (size_t)idx*8);
            CP16(sb + 3*9216u  + o, Asrc + (size_t)idx*8);
            CP16(sb + 4*9216u  + o, Vsrc + (size_t)idx*8);
        }
        asm volatile("cp.async.commit_group;" ::: "memory");
    }
    if (tid<=64){
        double gd = 1.0 - exp2(-5.0-(double)h);
        gp[tid]=(float)pow(gd,(double)tid);
    }
    if (tid<64) Xs[tid] = g_Xn[((size_t)bh*NCHK+j)*64 + tid];
    asm volatile("cp.async.wait_group 0;" ::: "memory");
    __syncthreads();
    const int warp=tid>>5, lane=tid&31;
    const int wm=warp&3, wn=warp>>2, g=lane>>2, t4=lane&3;
    const int m0=wm*16, cb=wn*32;
    const int r0=m0+g, r1=r0+8;
    const int l7=lane&7, x8=(lane&8)?8:0, x16=(lane&16)?8:0;

    const unsigned sQ = (unsigned)__cvta_generic_to_shared(bQ);
    const unsigned sK = (unsigned)__cvta_generic_to_shared(bK);
    const unsigned sS = (unsigned)__cvta_generic_to_shared(bS);
    const unsigned sA = (unsigned)__cvta_generic_to_shared(bA);
    const unsigned sV = (unsigned)__cvta_generic_to_shared(bV);

    // offsets
    unsigned aOff[4], nOff[4][2], tOff[4][2];
#pragma unroll
    for (int ks=0;ks<4;ks++){
        aOff[ks] = (unsigned)((m0 + l7 + x8)*72 + 16*ks + x16)*2u;
#pragma unroll
        for (int np=0;np<2;np++){
            nOff[ks][np] = (unsigned)((cb + np*16 + l7 + x16)*72 + 16*ks + x8)*2u;
            tOff[ks][np] = (unsigned)((16*ks + l7 + x8)*72 + cb + np*16 + x16)*2u;
        }
    }

    // Q fragments (all 4 k-steps), reused across products 1-3
    unsigned qa[4][4];
#pragma unroll
    for (int ks=0;ks<4;ks++) ldsm4(qa[ks], sQ + aOff[ks]);

    float accP[4][4]={}, accQ[4][4]={}, accPP[4][4]={};
#pragma unroll
    for (int ks=0;ks<4;ks++){
#pragma unroll
        for (int np=0;np<2;np++){
            unsigned bf[4];
            ldsm4(bf, sK + nOff[ks][np]);           // K rows [s][d], non-trans
            mma16(accP[np*2  ], qa[ks], bf[0], bf[1]);
            mma16(accP[np*2+1], qa[ks], bf[2], bf[3]);
            unsigned sf[4];
            ldsm4t(sf, sS + tOff[ks][np]);          // S [d][e], trans
            mma16(accQ[np*2  ], qa[ks], sf[0], sf[1]);
            mma16(accQ[np*2+1], qa[ks], sf[2], sf[3]);
            unsigned af[4];
            ldsm4t(af, sA + tOff[ks][np]);          // past_kv [d][e], trans
            mma16(accPP[np*2  ], qa[ks], af[0], af[1]);
            mma16(accPP[np*2+1], qa[ks], af[2], af[3]);
        }
    }
    __syncthreads();   // all reads of bQ/bK/bS/bA done
    // decay P -> bQ (fp16); PP -> scanbuf (fp32); scale accQ by gamma^{row+1}
#pragma unroll
    for (int nt=0;nt<4;nt++){
        int c0=cb+nt*8+t4*2;
        int d00=r0-c0, d01=d00-1, d10=r1-c0, d11=d10-1;
        float p00 = (d00>=0)? accP[nt][0]*gp[d00] : 0.f;
        float p01 = (d01>=0)? accP[nt][1]*gp[d01] : 0.f;
        float p10 = (d10>=0)? accP[nt][2]*gp[d10] : 0.f;
        float p11 = (d11>=0)? accP[nt][3]*gp[d11] : 0.f;
        *(__half2*)(bQ + r0*72 + c0) = __floats2half2_rn(p00,p01);
        *(__half2*)(bQ + r1*72 + c0) = __floats2half2_rn(p10,p11);
        *(float2*)(scanbuf + r0*72 + c0) = make_float2(accPP[nt][0],accPP[nt][1]);
        *(float2*)(scanbuf + r1*72 + c0) = make_float2(accPP[nt][2],accPP[nt][3]);
        float gq0=gp[r0+1], gq1=gp[r1+1];
        accQ[nt][0]*=gq0; accQ[nt][1]*=gq0;
        accQ[nt][2]*=gq1; accQ[nt][3]*=gq1;
    }
    __syncthreads();
    // R += P V : P from bQ (non-trans), V^T from bV (trans)
#pragma unroll
    for (int ks=0;ks<4;ks++){
        unsigned pa[4];
        ldsm4(pa, sQ + aOff[ks]);
#pragma unroll
        for (int np=0;np<2;np++){
            unsigned bf[4];
            ldsm4t(bf, sV + tOff[ks][np]);
            mma16(accQ[np*2  ], pa, bf[0], bf[1]);
            mma16(accQ[np*2+1], pa, bf[2], bf[3]);
        }
    }
    // suffix scan of PP (scanbuf, stride 72)
    {
        int e = tid&63, q = tid>>6;
        float g1 = gp[1];
        float loc[16];
        float c = 0.f;
#pragma unroll
        for (int i=15;i>=0;--i){
            c = scanbuf[(q*16+i)*72 + e] + g1*c;
            loc[i] = c;
        }
        carry[q*64+e] = loc[0];
        __syncthreads();
        float F = 0.f;
        if (q<3) F  = carry[(q+1)*64+e];
        if (q<2) F += gp[16]*carry[(q+2)*64+e];
        if (q<1) F += gp[32]*carry[(q+3)*64+e];
#pragma unroll
        for (int i=0;i<16;i++){
            scanbuf[(q*16+i)*72 + e] = loc[i] + gp[16-i]*F;
        }
    }
    __syncthreads();
    float s1=0.f, s2=0.f;
    float gx0=gp[64-r0], gx1=gp[64-r1];
#pragma unroll
    for (int nt=0;nt<4;nt++){
        int c0=cb+nt*8+t4*2;
        float v00 = accQ[nt][0] + scanbuf[r0*72+c0  ] + gx0*Xs[c0  ];
        float v01 = accQ[nt][1] + scanbuf[r0*72+c0+1] + gx0*Xs[c0+1];
        float v10 = accQ[nt][2] + scanbuf[r1*72+c0  ] + gx1*Xs[c0  ];
        float v11 = accQ[nt][3] + scanbuf[r1*72+c0+1] + gx1*Xs[c0+1];
        s1 += v00+v01+v10+v11;
        s2 += v00*v00+v01*v01+v10*v10+v11*v11;
        *(float2*)(g_ret + base + (size_t)r0*64 + c0) = make_float2(v00,v01);
        *(float2*)(g_ret + base + (size_t)r1*64 + c0) = make_float2(v10,v11);
    }
#pragma unroll
    for (int o=16;o>0;o>>=1){
        s1 += __shfl_down_sync(0xffffffffu, s1, o);
        s2 += __shfl_down_sync(0xffffffffu, s2, o);
    }
    if (lane==0){ redS[warp]=s1; redQ[warp]=s2; }
    __syncthreads();
    if (tid==0){
        float a=0.f,bq=0.f;
#pragma unroll
        for (int w=0;w<8;w++){ a+=redS[w]; bq+=redQ[w]; }
        g_stat[(size_t)bid*2  ]=a;
        g_stat[(size_t)bid*2+1]=bq;
    }
}

// ================= K5: per-batch GroupNorm stats =================
__global__ void __launch_bounds__(512) k_stats()
{
    __shared__ float r1[512], r2[512];
    int b=blockIdx.x, tid=threadIdx.x;
    r1[tid]=g_stat[(size_t)(b*512+tid)*2];
    r2[tid]=g_stat[(size_t)(b*512+tid)*2+1];
    __syncthreads();
    for (int o=256;o>0;o>>=1){
        if (tid<o){ r1[tid]+=r1[tid+o]; r2[tid]+=r2[tid+o]; }
        __syncthreads();
    }
    if (tid==0){
        const float N = (float)((size_t)NH*NT*ND);
        float mu = r1[0]/N;
        float var = r2[0]/N - mu*mu;
        g_norm[b*2]=mu;
        g_norm[b*2+1]=rsqrtf(var+1e-5f);
    }
}

// ================= K6: normalize + layout to [B,T,NE] =================
__global__ void __launch_bounds__(256) k_out(const float* __restrict__ gnw,
                                             const float* __restrict__ gnb,
                                             float* __restrict__ out)
{
    int bid=blockIdx.x;
    int b=bid>>11, t=bid&2047;
    int tid=threadIdx.x;
    int h=tid>>4, d4=(tid&15)*4;
    float mu=g_norm[b*2], rs=g_norm[b*2+1];
    float w = gnw[h]*rs;
    float bb = gnb[h] - mu*w;
    float4 xv = *(const float4*)(g_ret + (((size_t)(b*NH+h))*NT + t)*ND + d4);
    float4 yv = make_float4(xv.x*w+bb, xv.y*w+bb, xv.z*w+bb, xv.w*w+bb);
    *(float4*)(out + (size_t)bid*NE + h*ND + d4) = yv;
}

// ================= K7: kv reduce + decay (batched loads) =================
__global__ void __launch_bounds__(256) k_kvout(const float* __restrict__ pkv,
                                               float* __restrict__ out_kv)
{
    int h=blockIdx.x;
    int idx=blockIdx.y*256+threadIdx.x;
    float s=0.f;
    for (int b=0;b<NB;b++){
        size_t bh=((size_t)(b*NH+h))*NCHK;
        for (int j2=0;j2<NCHK;j2+=8){
            float t[8];
#pragma unroll
            for (int jj=0;jj<8;jj++) t[jj] = g_kvc[(bh+j2+jj)*4096 + idx];
#pragma unroll
            for (int jj=0;jj<8;jj++) s += t[jj];
        }
    }
    double gd = 1.0 - exp2(-5.0-(double)h);
    out_kv[(size_t)h*4096 + idx] = (float)gd*pkv[(size_t)h*4096 + idx] + 0.25f*s;
}

extern "C" void kernel_launch(void* const* d_in, const int* in_sizes, int n_in,
                              void* d_out, int out_size)
{
    const float* x   = (const float*)d_in[0];
    const float* pkv = (const float*)d_in[1];
    const float* Wq  = (const float*)d_in[2];
    const float* Wk  = (const float*)d_in[3];
    const float* Wv  = (const float*)d_in[4];
    const float* gnw = (const float*)d_in[5];
    const float* gnb = (const float*)d_in[6];
    float* out = (float*)d_out;

    cudaFuncSetAttribute(k_proj3, cudaFuncAttributeMaxDynamicSharedMemorySize, PROJ_SMEM);
    cudaFuncSetAttribute(k_pass1, cudaFuncAttributeMaxDynamicSharedMemorySize, P1_SMEM);
    cudaFuncSetAttribute(k_pass3, cudaFuncAttributeMaxDynamicSharedMemorySize, P3_SMEM);

    k_cvtx<<<(NX4 + NA4 + 255)/256, 256>>>(x, pkv);
    dim3 gcw(NE/64, NE/64, 3);
    k_cvtw<<<gcw, 256>>>(Wq, Wk, Wv);
    dim3 gproj(8, 64, 3);
    k_proj3<<<gproj, 256, PROJ_SMEM>>>();
    k_pass1<<<NBH*NCHK, 256, P1_SMEM>>>(pkv);
    dim3 gscan(NBH, 5);
    k_scan<<<gscan, 256>>>();
    k_pass3<<<NBH*NCHK, 256, P3_SMEM>>>();
    k_stats<<<NB, 512>>>();
    k_out<<<NB*NT, 256>>>(gnw, gnb, out);
    dim3 gkv(NH, 16);
    k_kvout<<<gkv, 256>>>(pkv, out + (size_t)NB*NT*NE);
}

// round 16
// speedup vs baseline: 1.8532x; 1.0076x over previous
#include <cuda_runtime.h>
#include <cuda_fp16.h>
#include <math.h>
#include <stdint.h>

#define NB 4
#define NT 2048
#define NH 16
#define ND 64
#define NE 1024
#define NC 64
#define NCHK 32
#define NBH (NB*NH)

// ---------------- scratch (device globals; no runtime allocation) ----------------
__device__ __half g_qh [(size_t)NB*NH*NT*ND];
__device__ __half g_kh [(size_t)NB*NH*NT*ND];
__device__ __half g_vh [(size_t)NB*NH*NT*ND];
__device__ float g_ret[(size_t)NB*NH*NT*ND];
__device__ float g_U  [(size_t)NBH*NCHK*ND*ND];
__device__ __half g_S [(size_t)NBH*NCHK*ND*ND];
__device__ float g_kvp[(size_t)NBH*8*ND*ND];
__device__ float g_W  [(size_t)NBH*NCHK*ND];
__device__ float g_Xn [(size_t)NBH*NCHK*ND];
__device__ float g_stat[(size_t)NBH*NCHK*2];
__device__ float g_norm[NB*2];
__device__ __half g_xh [(size_t)NB*NT*NE];    // fp16 X
__device__ __half g_wh [(size_t)3*NE*NE];     // fp16 W^T (layout [n][k])
__device__ __half g_ar [(size_t)NH*ND*ND];    // fp16 past_kv

__device__ __forceinline__ void mma16(float c[4], const unsigned a[4], unsigned b0, unsigned b1){
    asm volatile(
      "mma.sync.aligned.m16n8k16.row.col.f32.f16.f16.f32 "
      "{%0,%1,%2,%3},{%4,%5,%6,%7},{%8,%9},{%0,%1,%2,%3};"
      : "+f"(c[0]),"+f"(c[1]),"+f"(c[2]),"+f"(c[3])
      : "r"(a[0]),"r"(a[1]),"r"(a[2]),"r"(a[3]), "r"(b0),"r"(b1));
}
__device__ __forceinline__ void ldsm4(unsigned r[4], unsigned addr){
    asm volatile("ldmatrix.sync.aligned.m8n8.x4.shared.b16 {%0,%1,%2,%3}, [%4];"
      : "=r"(r[0]),"=r"(r[1]),"=r"(r[2]),"=r"(r[3]) : "r"(addr));
}
__device__ __forceinline__ void ldsm4t(unsigned r[4], unsigned addr){
    asm volatile("ldmatrix.sync.aligned.m8n8.x4.trans.shared.b16 {%0,%1,%2,%3}, [%4];"
      : "=r"(r[0]),"=r"(r[1]),"=r"(r[2]),"=r"(r[3]) : "r"(addr));
}

#define CP16(dst_u32, src) \
    asm volatile("cp.async.ca.shared.global [%0], [%1], 16;" :: "r"(dst_u32), "l"(src))

// ================= K0a: X -> fp16, past_kv -> fp16 =================
#define NX4 ((NB*NT*NE)/4)       // 2097152
#define NA4 ((NH*ND*ND)/4)       // 16384
__global__ void __launch_bounds__(256) k_cvtx(const float* __restrict__ X,
                                              const float* __restrict__ pkv)
{
    int i = blockIdx.x*256 + threadIdx.x;
    if (i < NX4){
        float4 v = ((const float4*)X)[i];
        __half2 h0 = __floats2half2_rn(v.x, v.y);
        __half2 h1 = __floats2half2_rn(v.z, v.w);
        uint2 o;
        o.x = *(unsigned*)&h0;
        o.y = *(unsigned*)&h1;
        *(uint2*)&g_xh[(size_t)i*4] = o;
    } else {
        int off = i - NX4;
        if (off >= NA4) return;
        float4 v = ((const float4*)pkv)[off];
        __half2 h0 = __floats2half2_rn(v.x, v.y);
        __half2 h1 = __floats2half2_rn(v.z, v.w);
        uint2 o;
        o.x = *(unsigned*)&h0;
        o.y = *(unsigned*)&h1;
        *(uint2*)&g_ar[(size_t)off*4] = o;
    }
}

// ================= K0b: W -> fp16, transposed to [n][k] =================
__global__ void __launch_bounds__(256) k_cvtw(const float* __restrict__ Wq,
                                              const float* __restrict__ Wk,
                                              const float* __restrict__ Wv)
{
    __shared__ float sm[64*65];
    int sel = blockIdx.z;
    const float* W = (sel==0)?Wq:(sel==1)?Wk:Wv;
    __half* dst = g_wh + (size_t)sel*NE*NE;
    int k0 = blockIdx.x*64, n0 = blockIdx.y*64;
    int tid = threadIdx.x;
#pragma unroll
    for (int l=0;l<16;l++){
        int idx = tid + l*256;
        int r = idx>>6, c = idx&63;
        sm[c*65 + r] = W[(size_t)(k0+r)*NE + n0 + c];
    }
    __syncthreads();
#pragma unroll
    for (int l=0;l<8;l++){
        int idx = tid + l*256;
        int r = idx>>5, cp = idx&31;
        __half2 h = __floats2half2_rn(sm[r*65 + 2*cp], sm[r*65 + 2*cp + 1]);
        *(__half2*)&dst[(size_t)(n0+r)*NE + k0 + 2*cp] = h;
    }
}

// ================= K1: fused QKV projection (FP16 mma + ldmatrix, 3-stage) ===
#define A_STGH (128*24)
#define B_STGH (128*24)
#define PROJ_SMEM (3*(A_STGH+B_STGH)*2)
__global__ void __launch_bounds__(256) k_proj3()
{
    const int sel = blockIdx.z;
    const __half* Xh = g_xh;
    const __half* Wh = g_wh + (size_t)sel*NE*NE;
    __half* dst = (sel==0)?g_qh:(sel==1)?g_kh:g_vh;

    extern __shared__ __half hsm[];
    __half* As = hsm;
    __half* Bs = hsm + 3*A_STGH;

    const int tid = threadIdx.x;
    const int rowBase = blockIdx.y*128, colBase = blockIdx.x*128;
    const int warp = tid>>5, lane = tid&31;
    const int wm = warp&3, wn = warp>>2;
    const int g = lane>>2, t4 = lane&3;

    const int srow = tid>>1, shc = (tid&1)*8;

    const unsigned sA = (unsigned)__cvta_generic_to_shared(As);
    const unsigned sB = (unsigned)__cvta_generic_to_shared(Bs);
    const unsigned stA = (unsigned)A_STGH*2u, stB = (unsigned)B_STGH*2u;

    const int l7 = lane&7;
    unsigned aoff[2], boff[4];
#pragma unroll
    for (int mt=0;mt<2;mt++){
        int row = wm*32 + mt*16 + l7 + ((lane&8)?8:0);
        int col = (lane&16)?8:0;
        aoff[mt] = sA + (unsigned)(row*24 + col)*2u;
    }
#pragma unroll
    for (int np=0;np<4;np++){
        int row = wn*64 + np*16 + l7 + ((lane&16)?8:0);
        int col = (lane&8)?8:0;
        boff[np] = sB + (unsigned)(row*24 + col)*2u;
    }

    float acc[2][8][4];
#pragma unroll
    for (int a=0;a<2;a++)
#pragma unroll
      for (int b=0;b<8;b++)
#pragma unroll
        for (int c=0;c<4;c++) acc[a][b][c]=0.f;

    auto issue = [&](int it, int st){
        int kb = it*16;
        const __half* xs = Xh + (size_t)(rowBase+srow)*NE + kb + shc;
        CP16(sA + st*stA + (unsigned)(srow*24 + shc)*2u, xs);
        const __half* ws = Wh + (size_t)(colBase+srow)*NE + kb + shc;
        CP16(sB + st*stB + (unsigned)(srow*24 + shc)*2u, ws);
        asm volatile("cp.async.commit_group;" ::: "memory");
    };

    const int NIT = NE/16;
    issue(0,0); issue(1,1);
    for (int it=0; it<NIT; it++){
        const int st = it%3;
        if (it+1<NIT){
            asm volatile("cp.async.wait_group 1;" ::: "memory");
        } else {
            asm volatile("cp.async.wait_group 0;" ::: "memory");
        }
        __syncthreads();
        if (it+2<NIT) issue(it+2, (it+2)%3);
        const unsigned oA = (unsigned)st*stA;
        const unsigned oB = (unsigned)st*stB;
        unsigned af[2][4];
        ldsm4(af[0], aoff[0] + oA);
        ldsm4(af[1], aoff[1] + oA);
#pragma unroll
        for (int np=0;np<4;np++){
            unsigned bf[4];
            ldsm4(bf, boff[np] + oB);
            mma16(acc[0][2*np  ], af[0], bf[0], bf[1]);
            mma16(acc[1][2*np  ], af[1], bf[0], bf[1]);
            mma16(acc[0][2*np+1], af[0], bf[2], bf[3]);
            mma16(acc[1][2*np+1], af[1], bf[2], bf[3]);
        }
    }
#pragma unroll
    for (int mt=0;mt<2;mt++)
#pragma unroll
    for (int nt=0;nt<8;nt++){
        int row = rowBase + wm*32 + mt*16 + g;
        int col = colBase + wn*64 + nt*8 + t4*2;
        int b_ = row>>11, t_ = row&2047, h_ = col>>6, d_ = col&63;
        __half2 h0 = __floats2half2_rn(acc[mt][nt][0], acc[mt][nt][1]);
        *(__half2*)(dst + (((size_t)(b_*NH+h_))*NT + t_)*ND + d_) = h0;
        int t2_ = (row+8)&2047;
        __half2 h1 = __floats2half2_rn(acc[mt][nt][2], acc[mt][nt][3]);
        *(__half2*)(dst + (((size_t)(b_*NH+h_))*NT + t2_)*ND + d_) = h1;
    }
}

// ================= K2: per-chunk U_j (fp16 mma + ldmatrix), W_j ==================
#define P1_SMEM (2*4608*2)
__global__ void __launch_bounds__(256) k_pass1(const float* __restrict__ pkv)
{
    extern __shared__ __half hs1[];
    __half* bK  = hs1;            // K [i][72] fp16 (later Q)
    __half* bVw = hs1 + 4608;     // gamma^{63-i} V fp16
    __shared__ float gp[65];
    __shared__ float red[4*64];
    __shared__ float qw[64];
    int tid=threadIdx.x, bid=blockIdx.x;
    int j=bid&31, bh=bid>>5, h=bh&15;
    size_t base = ((size_t)bh*NT + (size_t)j*NC)*ND;
    if (tid<=64){
        double gd = 1.0 - exp2(-5.0-(double)h);
        gp[tid]=(float)pow(gd,(double)tid);
    }
    __syncthreads();
#pragma unroll
    for (int l=0;l<2;l++){
        int idx = tid + l*256;
        int i=idx>>3, d8=(idx&7)*8;
        *(uint4*)(bK + i*72 + d8) = *(const uint4*)(g_kh + base + (size_t)idx*8);
        uint4 vv = *(const uint4*)(g_vh + base + (size_t)idx*8);
        __half2 ws = __float2half2_rn(gp[63-i]);
        __half2 w0 = __hmul2(*(__half2*)&vv.x, ws);
        __half2 w1 = __hmul2(*(__half2*)&vv.y, ws);
        __half2 w2 = __hmul2(*(__half2*)&vv.z, ws);
        __half2 w3 = __hmul2(*(__half2*)&vv.w, ws);
        uint4 wo;
        wo.x=*(unsigned*)&w0; wo.y=*(unsigned*)&w1;
        wo.z=*(unsigned*)&w2; wo.w=*(unsigned*)&w3;
        *(uint4*)(bVw + i*72 + d8) = wo;
    }
    __syncthreads();
    const int warp=tid>>5, lane=tid&31;
    const int wm=warp&3, wn=warp>>2, g=lane>>2, t4=lane&3;
    const int m0=wm*16, cb=wn*32;
    const int r0=m0+g, r1=r0+8;
    const int l7=lane&7, x8=(lane&8)?8:0, x16=(lane&16)?8:0;

    const unsigned sK  = (unsigned)__cvta_generic_to_shared(bK);
    const unsigned sVw = (unsigned)__cvta_generic_to_shared(bVw);

    float accU[4][4]={};
#pragma unroll
    for (int ks=0;ks<4;ks++){
        unsigned a[4];
        ldsm4t(a, sK + (unsigned)((16*ks + l7 + x16)*72 + m0 + x8)*2u);
#pragma unroll
        for (int np=0;np<2;np++){
            unsigned tb = (unsigned)((16*ks + l7 + x8)*72 + cb + np*16 + x16)*2u;
            unsigned cf[4];
            ldsm4t(cf, sVw + tb);
            mma16(accU[np*2  ], a, cf[0], cf[1]);
            mma16(accU[np*2+1], a, cf[2], cf[3]);
        }
    }
    {
        float* Up = g_U + (size_t)bid*4096;
#pragma unroll
        for (int nt=0;nt<4;nt++){
            int c0=cb+nt*8+t4*2;
            *(float2*)(Up + r0*64 + c0) = make_float2(accU[nt][0],accU[nt][1]);
            *(float2*)(Up + r1*64 + c0) = make_float2(accU[nt][2],accU[nt][3]);
        }
    }
    __syncthreads();
    // Q fp16 into bK (free now)
#pragma unroll
    for (int l=0;l<2;l++){
        int idx=tid+l*256;
        int i=idx>>3, d8=(idx&7)*8;
        *(uint4*)(bK + i*72 + d8) = *(const uint4*)(g_qh + base + (size_t)idx*8);
    }
    __syncthreads();
    int rr = tid>>6, d = tid&63;
    float s = 0.f;
#pragma unroll
    for (int i=rr*16;i<rr*16+16;i++) s += gp[i]*__half2float(bK[i*72 + d]);
    red[rr*64 + d] = s;
    __syncthreads();
    if (tid<64) qw[tid] = red[tid] + red[64+tid] + red[128+tid] + red[192+tid];
    __syncthreads();
    const float* A = pkv + (size_t)h*4096;
    float s2 = 0.f;
#pragma unroll
    for (int dd=rr*16; dd<rr*16+16; dd++) s2 += qw[dd]*A[dd*64 + d];
    red[rr*64 + d] = s2;
    __syncthreads();
    if (tid<64) g_W[(size_t)bid*64 + tid] = red[tid] + red[64+tid] + red[128+tid] + red[192+tid];
}

// ================= K2b: KV partials = K^T V over 256-token slabs (fp16 mma) =======
#define KV_SMEM (2*4608*2)
__global__ void __launch_bounds__(256) k_kv()
{
    extern __shared__ __half hkv[];
    __half* bK = hkv;
    __half* bV = hkv + 4608;
    int bh = blockIdx.x, part = blockIdx.y;
    int tid = threadIdx.x;
    size_t base = ((size_t)bh*NT + (size_t)part*256)*ND;

    const int warp=tid>>5, lane=tid&31;
    const int wm=warp&3, wn=warp>>2, g=lane>>2, t4=lane&3;
    const int m0=wm*16, cb=wn*32;
    const int r0=m0+g, r1=r0+8;
    const int l7=lane&7, x8=(lane&8)?8:0, x16=(lane&16)?8:0;
    const unsigned sK = (unsigned)__cvta_generic_to_shared(bK);
    const unsigned sV = (unsigned)__cvta_generic_to_shared(bV);

    float acc[4][4]={};
    for (int tile=0; tile<4; tile++){
        size_t tb = base + (size_t)tile*64*ND;
#pragma unroll
        for (int l=0;l<2;l++){
            int idx = tid + l*256;
            int i=idx>>3, d8=(idx&7)*8;
            *(uint4*)(bK + i*72 + d8) = *(const uint4*)(g_kh + tb + (size_t)idx*8);
            *(uint4*)(bV + i*72 + d8) = *(const uint4*)(g_vh + tb + (size_t)idx*8);
        }
        __syncthreads();
#pragma unroll
        for (int ks=0;ks<4;ks++){
            unsigned a[4];
            ldsm4t(a, sK + (unsigned)((16*ks + l7 + x16)*72 + m0 + x8)*2u);
#pragma unroll
            for (int np=0;np<2;np++){
                unsigned to = (unsigned)((16*ks + l7 + x8)*72 + cb + np*16 + x16)*2u;
                unsigned bf[4];
                ldsm4t(bf, sV + to);
                mma16(acc[np*2  ], a, bf[0], bf[1]);
                mma16(acc[np*2+1], a, bf[2], bf[3]);
            }
        }
        __syncthreads();
    }
    float* Kp = g_kvp + ((size_t)bh*8 + part)*4096;
#pragma unroll
    for (int nt=0;nt<4;nt++){
        int c0=cb+nt*8+t4*2;
        *(float2*)(Kp + r0*64 + c0) = make_float2(acc[nt][0],acc[nt][1]);
        *(float2*)(Kp + r1*64 + c0) = make_float2(acc[nt][2],acc[nt][3]);
    }
}

// ================= K3: chunk scans (S stored fp16) ========
__global__ void __launch_bounds__(256) k_scan()
{
    int bh = blockIdx.x, part = blockIdx.y, tid = threadIdx.x;
    int h = bh&15;
    double gd = 1.0 - exp2(-5.0-(double)h);
    float g64 = (float)pow(gd,64.0);
    if (part < 4){
        size_t ob = (size_t)bh*NCHK*4096 + (size_t)part*1024 + tid;
        float S[4] = {0.f,0.f,0.f,0.f};
        for (int j=0;j<NCHK;j+=8){
            float u[8][4];
#pragma unroll
            for (int jj=0;jj<8;jj++)
#pragma unroll
                for (int r=0;r<4;r++)
                    u[jj][r] = g_U[ob + (size_t)(j+jj)*4096 + r*256];
#pragma unroll
            for (int jj=0;jj<8;jj++){
#pragma unroll
                for (int r=0;r<4;r++){
                    g_S[ob + (size_t)(j+jj)*4096 + r*256] = __float2half(S[r]);
                    S[r] = g64*S[r] + u[jj][r];
                }
            }
        }
    } else {
        if (tid < 64){
            size_t ob2 = (size_t)bh*NCHK*64 + tid;
            float X = 0.f;
            for (int j=NCHK-8; j>=0; j-=8){
                float w[8];
#pragma unroll
                for (int jj=0;jj<8;jj++) w[jj] = g_W[ob2 + (size_t)(j+jj)*64];
#pragma unroll
                for (int jj=7;jj>=0;jj--){
                    g_Xn[ob2 + (size_t)(j+jj)*64] = X;
                    X = g64*X + w[jj];
                }
            }
        }
    }
}

// ================= K4: per-chunk finalize (fp16 mma + ldmatrix) ====================
#define P3_SMEM (5*4608*2)
__global__ void __launch_bounds__(256) k_pass3()
{
    extern __shared__ __half hs3[];
    __half* bQ = hs3;             // Q [i][72] -> P fp16
    __half* bK = hs3 + 4608;      // K [s][72]
    __half* bS = hs3 + 2*4608;    // S [d][72]
    __half* bA = hs3 + 3*4608;    // past_kv [d][72]
    __half* bV = hs3 + 4*4608;    // V [s][72]
    float* scanbuf = (float*)(hs3 + 2*4608);   // overlays bS+bA: 64x72 fp32
    __shared__ float gp[65];
    __shared__ float Xs[64];
    __shared__ float carry[4*64];
    __shared__ float redS[8], redQ[8];
    int tid=threadIdx.x, bid=blockIdx.x;
    int j=bid&31, bh=bid>>5, h=bh&15;
    size_t base=((size_t)bh*NT+(size_t)j*NC)*ND;

    {
        const unsigned sb = (unsigned)__cvta_generic_to_shared(hs3);
        const __half* Qsrc = g_qh + base;
        const __half* Ksrc = g_kh + base;
        const __half* Ssrc = g_S + ((size_t)bh*NCHK+j)*4096;
        const __half* Asrc = g_ar + (size_t)h*4096;
        const __half* Vsrc = g_vh + base;
#pragma unroll
        for (int l=0;l<2;l++){
            int idx=tid+l*256;
            int i=idx>>3, d8=(idx&7)*8;
            unsigned o = (unsigned)(i*72 + d8)*2u;
            CP16(sb            + o, Qsrc + (size_t)idx*8);
            CP16(sb +   9216u  + o, Ksrc + (size_t)idx*8);
            CP16(sb + 2*9216u  + o, Ssrc + (size_t)idx*8);
            CP16(sb + 3*9216u  + o, Asrc + (size_t)idx*8);
            CP16(sb + 4*9216u  + o, Vsrc + (size_t)idx*8);
        }
        asm volatile("cp.async.commit_group;" ::: "memory");
    }
    if (tid<=64){
        double gd = 1.0 - exp2(-5.0-(double)h);
        gp[tid]=(float)pow(gd,(double)tid);
    }
    if (tid<64) Xs[tid] = g_Xn[((size_t)bh*NCHK+j)*64 + tid];
    asm volatile("cp.async.wait_group 0;" ::: "memory");
    __syncthreads();
    const int warp=tid>>5, lane=tid&31;
    const int wm=warp&3, wn=warp>>2, g=lane>>2, t4=lane&3;
    const int m0=wm*16, cb=wn*32;
    const int r0=m0+g, r1=r0+8;
    const int l7=lane&7, x8=(lane&8)?8:0, x16=(lane&16)?8:0;

    const unsigned sQ = (unsigned)__cvta_generic_to_shared(bQ);
    const unsigned sK = (unsigned)__cvta_generic_to_shared(bK);
    const unsigned sS = (unsigned)__cvta_generic_to_shared(bS);
    const unsigned sA = (unsigned)__cvta_generic_to_shared(bA);
    const unsigned sV = (unsigned)__cvta_generic_to_shared(bV);

    unsigned aOff[4], nOff[4][2], tOff[4][2];
#pragma unroll
    for (int ks=0;ks<4;ks++){
        aOff[ks] = (unsigned)((m0 + l7 + x8)*72 + 16*ks + x16)*2u;
#pragma unroll
        for (int np=0;np<2;np++){
            nOff[ks][np] = (unsigned)((cb + np*16 + l7 + x16)*72 + 16*ks + x8)*2u;
            tOff[ks][np] = (unsigned)((16*ks + l7 + x8)*72 + cb + np*16 + x16)*2u;
        }
    }

    unsigned qa[4][4];
#pragma unroll
    for (int ks=0;ks<4;ks++) ldsm4(qa[ks], sQ + aOff[ks]);

    float accP[4][4]={}, accQ[4][4]={}, accPP[4][4]={};
#pragma unroll
    for (int ks=0;ks<4;ks++){
#pragma unroll
        for (int np=0;np<2;np++){
            unsigned bf[4];
            ldsm4(bf, sK + nOff[ks][np]);
            mma16(accP[np*2  ], qa[ks], bf[0], bf[1]);
            mma16(accP[np*2+1], qa[ks], bf[2], bf[3]);
            unsigned sf[4];
            ldsm4t(sf, sS + tOff[ks][np]);
            mma16(accQ[np*2  ], qa[ks], sf[0], sf[1]);
            mma16(accQ[np*2+1], qa[ks], sf[2], sf[3]);
            unsigned af[4];
            ldsm4t(af, sA + tOff[ks][np]);
            mma16(accPP[np*2  ], qa[ks], af[0], af[1]);
            mma16(accPP[np*2+1], qa[ks], af[2], af[3]);
        }
    }
    __syncthreads();
#pragma unroll
    for (int nt=0;nt<4;nt++){
        int c0=cb+nt*8+t4*2;
        int d00=r0-c0, d01=d00-1, d10=r1-c0, d11=d10-1;
        float p00 = (d00>=0)? accP[nt][0]*gp[d00] : 0.f;
        float p01 = (d01>=0)? accP[nt][1]*gp[d01] : 0.f;
        float p10 = (d10>=0)? accP[nt][2]*gp[d10] : 0.f;
        float p11 = (d11>=0)? accP[nt][3]*gp[d11] : 0.f;
        *(__half2*)(bQ + r0*72 + c0) = __floats2half2_rn(p00,p01);
        *(__half2*)(bQ + r1*72 + c0) = __floats2half2_rn(p10,p11);
        *(float2*)(scanbuf + r0*72 + c0) = make_float2(accPP[nt][0],accPP[nt][1]);
        *(float2*)(scanbuf + r1*72 + c0) = make_float2(accPP[nt][2],accPP[nt][3]);
        float gq0=gp[r0+1], gq1=gp[r1+1];
        accQ[nt][0]*=gq0; accQ[nt][1]*=gq0;
        accQ[nt][2]*=gq1; accQ[nt][3]*=gq1;
    }
    __syncthreads();
#pragma unroll
    for (int ks=0;ks<4;ks++){
        unsigned pa[4];
        ldsm4(pa, sQ + aOff[ks]);
#pragma unroll
        for (int np=0;np<2;np++){
            unsigned bf[4];
            ldsm4t(bf, sV + tOff[ks][np]);
            mma16(accQ[np*2  ], pa, bf[0], bf[1]);
            mma16(accQ[np*2+1], pa, bf[2], bf[3]);
        }
    }
    {
        int e = tid&63, q = tid>>6;
        float g1 = gp[1];
        float loc[16];
        float c = 0.f;
#pragma unroll
        for (int i=15;i>=0;--i){
            c = scanbuf[(q*16+i)*72 + e] + g1*c;
            loc[i] = c;
        }
        carry[q*64+e] = loc[0];
        __syncthreads();
        float F = 0.f;
        if (q<3) F  = carry[(q+1)*64+e];
        if (q<2) F += gp[16]*carry[(q+2)*64+e];
        if (q<1) F += gp[32]*carry[(q+3)*64+e];
#pragma unroll
        for (int i=0;i<16;i++){
            scanbuf[(q*16+i)*72 + e] = loc[i] + gp[16-i]*F;
        }
    }
    __syncthreads();
    float s1=0.f, s2=0.f;
    float gx0=gp[64-r0], gx1=gp[64-r1];
#pragma unroll
    for (int nt=0;nt<4;nt++){
        int c0=cb+nt*8+t4*2;
        float v00 = accQ[nt][0] + scanbuf[r0*72+c0  ] + gx0*Xs[c0  ];
        float v01 = accQ[nt][1] + scanbuf[r0*72+c0+1] + gx0*Xs[c0+1];
        float v10 = accQ[nt][2] + scanbuf[r1*72+c0  ] + gx1*Xs[c0  ];
        float v11 = accQ[nt][3] + scanbuf[r1*72+c0+1] + gx1*Xs[c0+1];
        s1 += v00+v01+v10+v11;
        s2 += v00*v00+v01*v01+v10*v10+v11*v11;
        *(float2*)(g_ret + base + (size_t)r0*64 + c0) = make_float2(v00,v01);
        *(float2*)(g_ret + base + (size_t)r1*64 + c0) = make_float2(v10,v11);
    }
#pragma unroll
    for (int o=16;o>0;o>>=1){
        s1 += __shfl_down_sync(0xffffffffu, s1, o);
        s2 += __shfl_down_sync(0xffffffffu, s2, o);
    }
    if (lane==0){ redS[warp]=s1; redQ[warp]=s2; }
    __syncthreads();
    if (tid==0){
        float a=0.f,bq=0.f;
#pragma unroll
        for (int w=0;w<8;w++){ a+=redS[w]; bq+=redQ[w]; }
        g_stat[(size_t)bid*2  ]=a;
        g_stat[(size_t)bid*2+1]=bq;
    }
}

// ================= K5: per-batch GroupNorm stats =================
__global__ void __launch_bounds__(512) k_stats()
{
    __shared__ float r1[512], r2[512];
    int b=blockIdx.x, tid=threadIdx.x;
    r1[tid]=g_stat[(size_t)(b*512+tid)*2];
    r2[tid]=g_stat[(size_t)(b*512+tid)*2+1];
    __syncthreads();
    for (int o=256;o>0;o>>=1){
        if (tid<o){ r1[tid]+=r1[tid+o]; r2[tid]+=r2[tid+o]; }
        __syncthreads();
    }
    if (tid==0){
        const float N = (float)((size_t)NH*NT*ND);
        float mu = r1[0]/N;
        float var = r2[0]/N - mu*mu;
        g_norm[b*2]=mu;
        g_norm[b*2+1]=rsqrtf(var+1e-5f);
    }
}

// ================= K6: normalize + layout to [B,T,NE] =================
__global__ void __launch_bounds__(256) k_out(const float* __restrict__ gnw,
                                             const float* __restrict__ gnb,
                                             float* __restrict__ out)
{
    int bid=blockIdx.x;
    int b=bid>>11, t=bid&2047;
    int tid=threadIdx.x;
    int h=tid>>4, d4=(tid&15)*4;
    float mu=g_norm[b*2], rs=g_norm[b*2+1];
    float w = gnw[h]*rs;
    float bb = gnb[h] - mu*w;
    float4 xv = *(const float4*)(g_ret + (((size_t)(b*NH+h))*NT + t)*ND + d4);
    float4 yv = make_float4(xv.x*w+bb, xv.y*w+bb, xv.z*w+bb, xv.w*w+bb);
    *(float4*)(out + (size_t)bid*NE + h*ND + d4) = yv;
}

// ================= K7: kv reduce + decay =================
__global__ void __launch_bounds__(256) k_kvout(const float* __restrict__ pkv,
                                               float* __restrict__ out_kv)
{
    int h=blockIdx.x;
    int idx=blockIdx.y*256+threadIdx.x;
    float s=0.f;
    for (int b=0;b<NB;b++){
        size_t o = ((size_t)(b*NH+h)*8)*4096 + idx;
        float t[8];
#pragma unroll
        for (int p=0;p<8;p++) t[p] = g_kvp[o + (size_t)p*4096];
#pragma unroll
        for (int p=0;p<8;p++) s += t[p];
    }
    double gd = 1.0 - exp2(-5.0-(double)h);
    out_kv[(size_t)h*4096 + idx] = (float)gd*pkv[(size_t)h*4096 + idx] + 0.25f*s;
}

extern "C" void kernel_launch(void* const* d_in, const int* in_sizes, int n_in,
                              void* d_out, int out_size)
{
    const float* x   = (const float*)d_in[0];
    const float* pkv = (const float*)d_in[1];
    const float* Wq  = (const float*)d_in[2];
    const float* Wk  = (const float*)d_in[3];
    const float* Wv  = (const float*)d_in[4];
    const float* gnw = (const float*)d_in[5];
    const float* gnb = (const float*)d_in[6];
    float* out = (float*)d_out;

    cudaFuncSetAttribute(k_proj3, cudaFuncAttributeMaxDynamicSharedMemorySize, PROJ_SMEM);
    cudaFuncSetAttribute(k_pass1, cudaFuncAttributeMaxDynamicSharedMemorySize, P1_SMEM);
    cudaFuncSetAttribute(k_kv,    cudaFuncAttributeMaxDynamicSharedMemorySize, KV_SMEM);
    cudaFuncSetAttribute(k_pass3, cudaFuncAttributeMaxDynamicSharedMemorySize, P3_SMEM);

    k_cvtx<<<(NX4 + NA4 + 255)/256, 256>>>(x, pkv);
    dim3 gcw(NE/64, NE/64, 3);
    k_cvtw<<<gcw, 256>>>(Wq, Wk, Wv);
    dim3 gproj(8, 64, 3);
    k_proj3<<<gproj, 256, PROJ_SMEM>>>();
    k_pass1<<<NBH*NCHK, 256, P1_SMEM>>>(pkv);
    dim3 gscan(NBH, 5);
    k_scan<<<gscan, 256>>>();
    k_pass3<<<NBH*NCHK, 256, P3_SMEM>>>();
    dim3 gkv2(NBH, 8);
    k_kv<<<gkv2, 256, KV_SMEM>>>();
    k_stats<<<NB, 512>>>();
    k_out<<<NB*NT, 256>>>(gnw, gnb, out);
    dim3 gkv(NH, 16);
    k_kvout<<<gkv, 256>>>(pkv, out + (size_t)NB*NT*NE);
}

// round 17
// speedup vs baseline: 1.9369x; 1.0452x over previous
#include <cuda_runtime.h>
#include <cuda_fp16.h>
#include <math.h>
#include <stdint.h>

#define NB 4
#define NT 2048
#define NH 16
#define ND 64
#define NE 1024
#define NC 64
#define NCHK 32
#define NBH (NB*NH)

// ---------------- scratch (device globals; no runtime allocation) ----------------
__device__ __half g_qh [(size_t)NB*NH*NT*ND];
__device__ __half g_kh [(size_t)NB*NH*NT*ND];
__device__ __half g_vh [(size_t)NB*NH*NT*ND];
__device__ float g_ret[(size_t)NB*NH*NT*ND];
__device__ float g_U  [(size_t)NBH*NCHK*ND*ND];
__device__ __half g_S [(size_t)NBH*NCHK*ND*ND];
__device__ float g_kvp[(size_t)NBH*8*ND*ND];
__device__ float g_W  [(size_t)NBH*NCHK*ND];
__device__ float g_Xn [(size_t)NBH*NCHK*ND];
__device__ float g_stat[(size_t)NBH*NCHK*2];
__device__ float g_norm[NB*2];
__device__ __half g_xh [(size_t)NB*NT*NE];    // fp16 X
__device__ __half g_wh [(size_t)3*NE*NE];     // fp16 W^T (layout [n][k])
__device__ __half g_ar [(size_t)NH*ND*ND];    // fp16 past_kv

__device__ __forceinline__ void mma16(float c[4], const unsigned a[4], unsigned b0, unsigned b1){
    asm volatile(
      "mma.sync.aligned.m16n8k16.row.col.f32.f16.f16.f32 "
      "{%0,%1,%2,%3},{%4,%5,%6,%7},{%8,%9},{%0,%1,%2,%3};"
      : "+f"(c[0]),"+f"(c[1]),"+f"(c[2]),"+f"(c[3])
      : "r"(a[0]),"r"(a[1]),"r"(a[2]),"r"(a[3]), "r"(b0),"r"(b1));
}
__device__ __forceinline__ void ldsm4(unsigned r[4], unsigned addr){
    asm volatile("ldmatrix.sync.aligned.m8n8.x4.shared.b16 {%0,%1,%2,%3}, [%4];"
      : "=r"(r[0]),"=r"(r[1]),"=r"(r[2]),"=r"(r[3]) : "r"(addr));
}
__device__ __forceinline__ void ldsm4t(unsigned r[4], unsigned addr){
    asm volatile("ldmatrix.sync.aligned.m8n8.x4.trans.shared.b16 {%0,%1,%2,%3}, [%4];"
      : "=r"(r[0]),"=r"(r[1]),"=r"(r[2]),"=r"(r[3]) : "r"(addr));
}

#define CP16(dst_u32, src) \
    asm volatile("cp.async.ca.shared.global [%0], [%1], 16;" :: "r"(dst_u32), "l"(src))

// ================= K0a: X -> fp16, past_kv -> fp16 =================
#define NX4 ((NB*NT*NE)/4)       // 2097152
#define NA4 ((NH*ND*ND)/4)       // 16384
__global__ void __launch_bounds__(256) k_cvtx(const float* __restrict__ X,
                                              const float* __restrict__ pkv)
{
    int i = blockIdx.x*256 + threadIdx.x;
    if (i < NX4){
        float4 v = ((const float4*)X)[i];
        __half2 h0 = __floats2half2_rn(v.x, v.y);
        __half2 h1 = __floats2half2_rn(v.z, v.w);
        uint2 o;
        o.x = *(unsigned*)&h0;
        o.y = *(unsigned*)&h1;
        *(uint2*)&g_xh[(size_t)i*4] = o;
    } else {
        int off = i - NX4;
        if (off >= NA4) return;
        float4 v = ((const float4*)pkv)[off];
        __half2 h0 = __floats2half2_rn(v.x, v.y);
        __half2 h1 = __floats2half2_rn(v.z, v.w);
        uint2 o;
        o.x = *(unsigned*)&h0;
        o.y = *(unsigned*)&h1;
        *(uint2*)&g_ar[(size_t)off*4] = o;
    }
}

// ================= K0b: W -> fp16, transposed to [n][k] =================
__global__ void __launch_bounds__(256) k_cvtw(const float* __restrict__ Wq,
                                              const float* __restrict__ Wk,
                                              const float* __restrict__ Wv)
{
    __shared__ float sm[64*65];
    int sel = blockIdx.z;
    const float* W = (sel==0)?Wq:(sel==1)?Wk:Wv;
    __half* dst = g_wh + (size_t)sel*NE*NE;
    int k0 = blockIdx.x*64, n0 = blockIdx.y*64;
    int tid = threadIdx.x;
#pragma unroll
    for (int l=0;l<16;l++){
        int idx = tid + l*256;
        int r = idx>>6, c = idx&63;
        sm[c*65 + r] = W[(size_t)(k0+r)*NE + n0 + c];
    }
    __syncthreads();
#pragma unroll
    for (int l=0;l<8;l++){
        int idx = tid + l*256;
        int r = idx>>5, cp = idx&31;
        __half2 h = __floats2half2_rn(sm[r*65 + 2*cp], sm[r*65 + 2*cp + 1]);
        *(__half2*)&dst[(size_t)(n0+r)*NE + k0 + 2*cp] = h;
    }
}

// ================= K1: fused QKV projection (FP16 mma + ldmatrix, 3-stage) ===
#define A_STGH (128*24)
#define B_STGH (128*24)
#define PROJ_SMEM (3*(A_STGH+B_STGH)*2)
__global__ void __launch_bounds__(256) k_proj3()
{
    const int sel = blockIdx.z;
    const __half* Xh = g_xh;
    const __half* Wh = g_wh + (size_t)sel*NE*NE;
    __half* dst = (sel==0)?g_qh:(sel==1)?g_kh:g_vh;

    extern __shared__ __half hsm[];
    __half* As = hsm;
    __half* Bs = hsm + 3*A_STGH;

    const int tid = threadIdx.x;
    const int rowBase = blockIdx.y*128, colBase = blockIdx.x*128;
    const int warp = tid>>5, lane = tid&31;
    const int wm = warp&3, wn = warp>>2;
    const int g = lane>>2, t4 = lane&3;

    const int srow = tid>>1, shc = (tid&1)*8;

    const unsigned sA = (unsigned)__cvta_generic_to_shared(As);
    const unsigned sB = (unsigned)__cvta_generic_to_shared(Bs);
    const unsigned stA = (unsigned)A_STGH*2u, stB = (unsigned)B_STGH*2u;

    const int l7 = lane&7;
    unsigned aoff[2], boff[4];
#pragma unroll
    for (int mt=0;mt<2;mt++){
        int row = wm*32 + mt*16 + l7 + ((lane&8)?8:0);
        int col = (lane&16)?8:0;
        aoff[mt] = sA + (unsigned)(row*24 + col)*2u;
    }
#pragma unroll
    for (int np=0;np<4;np++){
        int row = wn*64 + np*16 + l7 + ((lane&16)?8:0);
        int col = (lane&8)?8:0;
        boff[np] = sB + (unsigned)(row*24 + col)*2u;
    }

    float acc[2][8][4];
#pragma unroll
    for (int a=0;a<2;a++)
#pragma unroll
      for (int b=0;b<8;b++)
#pragma unroll
        for (int c=0;c<4;c++) acc[a][b][c]=0.f;

    auto issue = [&](int it, int st){
        int kb = it*16;
        const __half* xs = Xh + (size_t)(rowBase+srow)*NE + kb + shc;
        CP16(sA + st*stA + (unsigned)(srow*24 + shc)*2u, xs);
        const __half* ws = Wh + (size_t)(colBase+srow)*NE + kb + shc;
        CP16(sB + st*stB + (unsigned)(srow*24 + shc)*2u, ws);
        asm volatile("cp.async.commit_group;" ::: "memory");
    };

    const int NIT = NE/16;
    issue(0,0); issue(1,1);
    for (int it=0; it<NIT; it++){
        const int st = it%3;
        if (it+1<NIT){
            asm volatile("cp.async.wait_group 1;" ::: "memory");
        } else {
            asm volatile("cp.async.wait_group 0;" ::: "memory");
        }
        __syncthreads();
        if (it+2<NIT) issue(it+2, (it+2)%3);
        const unsigned oA = (unsigned)st*stA;
        const unsigned oB = (unsigned)st*stB;
        unsigned af[2][4];
        ldsm4(af[0], aoff[0] + oA);
        ldsm4(af[1], aoff[1] + oA);
#pragma unroll
        for (int np=0;np<4;np++){
            unsigned bf[4];
            ldsm4(bf, boff[np] + oB);
            mma16(acc[0][2*np  ], af[0], bf[0], bf[1]);
            mma16(acc[1][2*np  ], af[1], bf[0], bf[1]);
            mma16(acc[0][2*np+1], af[0], bf[2], bf[3]);
            mma16(acc[1][2*np+1], af[1], bf[2], bf[3]);
        }
    }
#pragma unroll
    for (int mt=0;mt<2;mt++)
#pragma unroll
    for (int nt=0;nt<8;nt++){
        int row = rowBase + wm*32 + mt*16 + g;
        int col = colBase + wn*64 + nt*8 + t4*2;
        int b_ = row>>11, t_ = row&2047, h_ = col>>6, d_ = col&63;
        __half2 h0 = __floats2half2_rn(acc[mt][nt][0], acc[mt][nt][1]);
        *(__half2*)(dst + (((size_t)(b_*NH+h_))*NT + t_)*ND + d_) = h0;
        int t2_ = (row+8)&2047;
        __half2 h1 = __floats2half2_rn(acc[mt][nt][2], acc[mt][nt][3]);
        *(__half2*)(dst + (((size_t)(b_*NH+h_))*NT + t2_)*ND + d_) = h1;
    }
}

// ========== K2: fused per-chunk U_j + W_j + 256-token KV partial (fp16 mma) =======
#define P1_SMEM (3*4608*2)
__global__ void __launch_bounds__(256) k_pass1(const float* __restrict__ pkv)
{
    extern __shared__ __half hs1[];
    __half* bK  = hs1;            // K [i][72] fp16
    __half* bV  = hs1 + 4608;     // V [i][72] fp16
    __half* bVw = hs1 + 2*4608;   // gamma^{63-i} V fp16 (then Q)
    __shared__ float gp[65];
    __shared__ float red[4*64];
    __shared__ float qw[64];
    int tid=threadIdx.x;
    int bh=blockIdx.x, part=blockIdx.y, h=bh&15;
    if (tid<=64){
        double gd = 1.0 - exp2(-5.0-(double)h);
        gp[tid]=(float)pow(gd,(double)tid);
    }
    __syncthreads();
    const int warp=tid>>5, lane=tid&31;
    const int wm=warp&3, wn=warp>>2, g=lane>>2, t4=lane&3;
    const int m0=wm*16, cb=wn*32;
    const int r0=m0+g, r1=r0+8;
    const int l7=lane&7, x8=(lane&8)?8:0, x16=(lane&16)?8:0;
    const unsigned sK  = (unsigned)__cvta_generic_to_shared(bK);
    const unsigned sV  = (unsigned)__cvta_generic_to_shared(bV);
    const unsigned sVw = (unsigned)__cvta_generic_to_shared(bVw);
    const float* A = pkv + (size_t)h*4096;
    const int rr = tid>>6, d = tid&63;

    float accKV[4][4]={};
    for (int tile=0; tile<4; tile++){
        int j = part*4 + tile;
        size_t base = ((size_t)bh*NT + (size_t)j*NC)*ND;
        // stage K, V, gammaV
#pragma unroll
        for (int l=0;l<2;l++){
            int idx = tid + l*256;
            int i=idx>>3, d8=(idx&7)*8;
            *(uint4*)(bK + i*72 + d8) = *(const uint4*)(g_kh + base + (size_t)idx*8);
            uint4 vv = *(const uint4*)(g_vh + base + (size_t)idx*8);
            *(uint4*)(bV + i*72 + d8) = vv;
            __half2 ws = __float2half2_rn(gp[63-i]);
            __half2 w0 = __hmul2(*(__half2*)&vv.x, ws);
            __half2 w1 = __hmul2(*(__half2*)&vv.y, ws);
            __half2 w2 = __hmul2(*(__half2*)&vv.z, ws);
            __half2 w3 = __hmul2(*(__half2*)&vv.w, ws);
            uint4 wo;
            wo.x=*(unsigned*)&w0; wo.y=*(unsigned*)&w1;
            wo.z=*(unsigned*)&w2; wo.w=*(unsigned*)&w3;
            *(uint4*)(bVw + i*72 + d8) = wo;
        }
        __syncthreads();
        float accU[4][4]={};
#pragma unroll
        for (int ks=0;ks<4;ks++){
            unsigned a[4];
            ldsm4t(a, sK + (unsigned)((16*ks + l7 + x16)*72 + m0 + x8)*2u);
#pragma unroll
            for (int np=0;np<2;np++){
                unsigned tb = (unsigned)((16*ks + l7 + x8)*72 + cb + np*16 + x16)*2u;
                unsigned cf[4];
                ldsm4t(cf, sVw + tb);
                mma16(accU[np*2  ], a, cf[0], cf[1]);
                mma16(accU[np*2+1], a, cf[2], cf[3]);
                unsigned bf[4];
                ldsm4t(bf, sV + tb);
                mma16(accKV[np*2  ], a, bf[0], bf[1]);
                mma16(accKV[np*2+1], a, bf[2], bf[3]);
            }
        }
        {
            float* Up = g_U + ((size_t)bh*NCHK + j)*4096;
#pragma unroll
            for (int nt=0;nt<4;nt++){
                int c0=cb+nt*8+t4*2;
                *(float2*)(Up + r0*64 + c0) = make_float2(accU[nt][0],accU[nt][1]);
                *(float2*)(Up + r1*64 + c0) = make_float2(accU[nt][2],accU[nt][3]);
            }
        }
        __syncthreads();
        // Q into bVw (mma reads done)
#pragma unroll
        for (int l=0;l<2;l++){
            int idx=tid+l*256;
            int i=idx>>3, d8=(idx&7)*8;
            *(uint4*)(bVw + i*72 + d8) = *(const uint4*)(g_qh + base + (size_t)idx*8);
        }
        __syncthreads();
        float s = 0.f;
#pragma unroll
        for (int i=rr*16;i<rr*16+16;i++) s += gp[i]*__half2float(bVw[i*72 + d]);
        red[rr*64 + d] = s;
        __syncthreads();
        if (tid<64) qw[tid] = red[tid] + red[64+tid] + red[128+tid] + red[192+tid];
        __syncthreads();
        float s2 = 0.f;
#pragma unroll
        for (int dd=rr*16; dd<rr*16+16; dd++) s2 += qw[dd]*A[dd*64 + d];
        red[rr*64 + d] = s2;
        __syncthreads();
        if (tid<64) g_W[((size_t)bh*NCHK + j)*64 + tid] =
            red[tid] + red[64+tid] + red[128+tid] + red[192+tid];
        __syncthreads();
    }
    // store KV partial for this 256-token slab
    float* Kp = g_kvp + ((size_t)bh*8 + part)*4096;
#pragma unroll
    for (int nt=0;nt<4;nt++){
        int c0=cb+nt*8+t4*2;
        *(float2*)(Kp + r0*64 + c0) = make_float2(accKV[nt][0],accKV[nt][1]);
        *(float2*)(Kp + r1*64 + c0) = make_float2(accKV[nt][2],accKV[nt][3]);
    }
}

// ================= K3: chunk scans (S stored fp16) ========
__global__ void __launch_bounds__(256) k_scan()
{
    int bh = blockIdx.x, part = blockIdx.y, tid = threadIdx.x;
    int h = bh&15;
    double gd = 1.0 - exp2(-5.0-(double)h);
    float g64 = (float)pow(gd,64.0);
    if (part < 4){
        size_t ob = (size_t)bh*NCHK*4096 + (size_t)part*1024 + tid;
        float S[4] = {0.f,0.f,0.f,0.f};
        for (int j=0;j<NCHK;j+=8){
            float u[8][4];
#pragma unroll
            for (int jj=0;jj<8;jj++)
#pragma unroll
                for (int r=0;r<4;r++)
                    u[jj][r] = g_U[ob + (size_t)(j+jj)*4096 + r*256];
#pragma unroll
            for (int jj=0;jj<8;jj++){
#pragma unroll
                for (int r=0;r<4;r++){
                    g_S[ob + (size_t)(j+jj)*4096 + r*256] = __float2half(S[r]);
                    S[r] = g64*S[r] + u[jj][r];
                }
            }
        }
    } else {
        if (tid < 64){
            size_t ob2 = (size_t)bh*NCHK*64 + tid;
            float X = 0.f;
            for (int j=NCHK-8; j>=0; j-=8){
                float w[8];
#pragma unroll
                for (int jj=0;jj<8;jj++) w[jj] = g_W[ob2 + (size_t)(j+jj)*64];
#pragma unroll
                for (int jj=7;jj>=0;jj--){
                    g_Xn[ob2 + (size_t)(j+jj)*64] = X;
                    X = g64*X + w[jj];
                }
            }
        }
    }
}

// ================= K4: per-chunk finalize (fp16 mma + ldmatrix) ====================
#define P3_SMEM (5*4608*2)
__global__ void __launch_bounds__(256) k_pass3()
{
    extern __shared__ __half hs3[];
    __half* bQ = hs3;             // Q [i][72] -> P fp16
    __half* bK = hs3 + 4608;      // K [s][72]
    __half* bS = hs3 + 2*4608;    // S [d][72]
    __half* bA = hs3 + 3*4608;    // past_kv [d][72]
    __half* bV = hs3 + 4*4608;    // V [s][72]
    float* scanbuf = (float*)(hs3 + 2*4608);   // overlays bS+bA: 64x72 fp32
    __shared__ float gp[65];
    __shared__ float Xs[64];
    __shared__ float carry[4*64];
    __shared__ float redS[8], redQ[8];
    int tid=threadIdx.x, bid=blockIdx.x;
    int j=bid&31, bh=bid>>5, h=bh&15;
    size_t base=((size_t)bh*NT+(size_t)j*NC)*ND;

    {
        const unsigned sb = (unsigned)__cvta_generic_to_shared(hs3);
        const __half* Qsrc = g_qh + base;
        const __half* Ksrc = g_kh + base;
        const __half* Ssrc = g_S + ((size_t)bh*NCHK+j)*4096;
        const __half* Asrc = g_ar + (size_t)h*4096;
        const __half* Vsrc = g_vh + base;
#pragma unroll
        for (int l=0;l<2;l++){
            int idx=tid+l*256;
            int i=idx>>3, d8=(idx&7)*8;
            unsigned o = (unsigned)(i*72 + d8)*2u;
            CP16(sb            + o, Qsrc + (size_t)idx*8);
            CP16(sb +   9216u  + o, Ksrc + (size_t)idx*8);
            CP16(sb + 2*9216u  + o, Ssrc + (size_t)idx*8);
            CP16(sb + 3*9216u  + o, Asrc + (size_t)idx*8);
            CP16(sb + 4*9216u  + o, Vsrc + (size_t)idx*8);
        }
        asm volatile("cp.async.commit_group;" ::: "memory");
    }
    if (tid<=64){
        double gd = 1.0 - exp2(-5.0-(double)h);
        gp[tid]=(float)pow(gd,(double)tid);
    }
    if (tid<64) Xs[tid] = g_Xn[((size_t)bh*NCHK+j)*64 + tid];
    asm volatile("cp.async.wait_group 0;" ::: "memory");
    __syncthreads();
    const int warp=tid>>5, lane=tid&31;
    const int wm=warp&3, wn=warp>>2, g=lane>>2, t4=lane&3;
    const int m0=wm*16, cb=wn*32;
    const int r0=m0+g, r1=r0+8;
    const int l7=lane&7, x8=(lane&8)?8:0, x16=(lane&16)?8:0;

    const unsigned sQ = (unsigned)__cvta_generic_to_shared(bQ);
    const unsigned sK = (unsigned)__cvta_generic_to_shared(bK);
    const unsigned sS = (unsigned)__cvta_generic_to_shared(bS);
    const unsigned sA = (unsigned)__cvta_generic_to_shared(bA);
    const unsigned sV = (unsigned)__cvta_generic_to_shared(bV);

    unsigned aOff[4], nOff[4][2], tOff[4][2];
#pragma unroll
    for (int ks=0;ks<4;ks++){
        aOff[ks] = (unsigned)((m0 + l7 + x8)*72 + 16*ks + x16)*2u;
#pragma unroll
        for (int np=0;np<2;np++){
            nOff[ks][np] = (unsigned)((cb + np*16 + l7 + x16)*72 + 16*ks + x8)*2u;
            tOff[ks][np] = (unsigned)((16*ks + l7 + x8)*72 + cb + np*16 + x16)*2u;
        }
    }

    unsigned qa[4][4];
#pragma unroll
    for (int ks=0;ks<4;ks++) ldsm4(qa[ks], sQ + aOff[ks]);

    float accP[4][4]={}, accQ[4][4]={}, accPP[4][4]={};
#pragma unroll
    for (int ks=0;ks<4;ks++){
#pragma unroll
        for (int np=0;np<2;np++){
            unsigned bf[4];
            ldsm4(bf, sK + nOff[ks][np]);
            mma16(accP[np*2  ], qa[ks], bf[0], bf[1]);
            mma16(accP[np*2+1], qa[ks], bf[2], bf[3]);
            unsigned sf[4];
            ldsm4t(sf, sS + tOff[ks][np]);
            mma16(accQ[np*2  ], qa[ks], sf[0], sf[1]);
            mma16(accQ[np*2+1], qa[ks], sf[2], sf[3]);
            unsigned af[4];
            ldsm4t(af, sA + tOff[ks][np]);
            mma16(accPP[np*2  ], qa[ks], af[0], af[1]);
            mma16(accPP[np*2+1], qa[ks], af[2], af[3]);
        }
    }
    __syncthreads();
#pragma unroll
    for (int nt=0;nt<4;nt++){
        int c0=cb+nt*8+t4*2;
        int d00=r0-c0, d01=d00-1, d10=r1-c0, d11=d10-1;
        float p00 = (d00>=0)? accP[nt][0]*gp[d00] : 0.f;
        float p01 = (d01>=0)? accP[nt][1]*gp[d01] : 0.f;
        float p10 = (d10>=0)? accP[nt][2]*gp[d10] : 0.f;
        float p11 = (d11>=0)? accP[nt][3]*gp[d11] : 0.f;
        *(__half2*)(bQ + r0*72 + c0) = __floats2half2_rn(p00,p01);
        *(__half2*)(bQ + r1*72 + c0) = __floats2half2_rn(p10,p11);
        *(float2*)(scanbuf + r0*72 + c0) = make_float2(accPP[nt][0],accPP[nt][1]);
        *(float2*)(scanbuf + r1*72 + c0) = make_float2(accPP[nt][2],accPP[nt][3]);
        float gq0=gp[r0+1], gq1=gp[r1+1];
        accQ[nt][0]*=gq0; accQ[nt][1]*=gq0;
        accQ[nt][2]*=gq1; accQ[nt][3]*=gq1;
    }
    __syncthreads();
#pragma unroll
    for (int ks=0;ks<4;ks++){
        unsigned pa[4];
        ldsm4(pa, sQ + aOff[ks]);
#pragma unroll
        for (int np=0;np<2;np++){
            unsigned bf[4];
            ldsm4t(bf, sV + tOff[ks][np]);
            mma16(accQ[np*2  ], pa, bf[0], bf[1]);
            mma16(accQ[np*2+1], pa, bf[2], bf[3]);
        }
    }
    {
        int e = tid&63, q = tid>>6;
        float g1 = gp[1];
        float loc[16];
        float c = 0.f;
#pragma unroll
        for (int i=15;i>=0;--i){
            c = scanbuf[(q*16+i)*72 + e] + g1*c;
            loc[i] = c;
        }
        carry[q*64+e] = loc[0];
        __syncthreads();
        float F = 0.f;
        if (q<3) F  = carry[(q+1)*64+e];
        if (q<2) F += gp[16]*carry[(q+2)*64+e];
        if (q<1) F += gp[32]*carry[(q+3)*64+e];
#pragma unroll
        for (int i=0;i<16;i++){
            scanbuf[(q*16+i)*72 + e] = loc[i] + gp[16-i]*F;
        }
    }
    __syncthreads();
    float s1=0.f, s2=0.f;
    float gx0=gp[64-r0], gx1=gp[64-r1];
#pragma unroll
    for (int nt=0;nt<4;nt++){
        int c0=cb+nt*8+t4*2;
        float v00 = accQ[nt][0] + scanbuf[r0*72+c0  ] + gx0*Xs[c0  ];
        float v01 = accQ[nt][1] + scanbuf[r0*72+c0+1] + gx0*Xs[c0+1];
        float v10 = accQ[nt][2] + scanbuf[r1*72+c0  ] + gx1*Xs[c0  ];
        float v11 = accQ[nt][3] + scanbuf[r1*72+c0+1] + gx1*Xs[c0+1];
        s1 += v00+v01+v10+v11;
        s2 += v00*v00+v01*v01+v10*v10+v11*v11;
        *(float2*)(g_ret + base + (size_t)r0*64 + c0) = make_float2(v00,v01);
        *(float2*)(g_ret + base + (size_t)r1*64 + c0) = make_float2(v10,v11);
    }
#pragma unroll
    for (int o=16;o>0;o>>=1){
        s1 += __shfl_down_sync(0xffffffffu, s1, o);
        s2 += __shfl_down_sync(0xffffffffu, s2, o);
    }
    if (lane==0){ redS[warp]=s1; redQ[warp]=s2; }
    __syncthreads();
    if (tid==0){
        float a=0.f,bq=0.f;
#pragma unroll
        for (int w=0;w<8;w++){ a+=redS[w]; bq+=redQ[w]; }
        g_stat[(size_t)bid*2  ]=a;
        g_stat[(size_t)bid*2+1]=bq;
    }
}

// ================= K5: per-batch GroupNorm stats =================
__global__ void __launch_bounds__(512) k_stats()
{
    __shared__ float r1[512], r2[512];
    int b=blockIdx.x, tid=threadIdx.x;
    r1[tid]=g_stat[(size_t)(b*512+tid)*2];
    r2[tid]=g_stat[(size_t)(b*512+tid)*2+1];
    __syncthreads();
    for (int o=256;o>0;o>>=1){
        if (tid<o){ r1[tid]+=r1[tid+o]; r2[tid]+=r2[tid+o]; }
        __syncthreads();
    }
    if (tid==0){
        const float N = (float)((size_t)NH*NT*ND);
        float mu = r1[0]/N;
        float var = r2[0]/N - mu*mu;
        g_norm[b*2]=mu;
        g_norm[b*2+1]=rsqrtf(var+1e-5f);
    }
}

// ================= K6: normalize + layout to [B,T,NE] =================
__global__ void __launch_bounds__(256) k_out(const float* __restrict__ gnw,
                                             const float* __restrict__ gnb,
                                             float* __restrict__ out)
{
    int bid=blockIdx.x;
    int b=bid>>11, t=bid&2047;
    int tid=threadIdx.x;
    int h=tid>>4, d4=(tid&15)*4;
    float mu=g_norm[b*2], rs=g_norm[b*2+1];
    float w = gnw[h]*rs;
    float bb = gnb[h] - mu*w;
    float4 xv = *(const float4*)(g_ret + (((size_t)(b*NH+h))*NT + t)*ND + d4);
    float4 yv = make_float4(xv.x*w+bb, xv.y*w+bb, xv.z*w+bb, xv.w*w+bb);
    *(float4*)(out + (size_t)bid*NE + h*ND + d4) = yv;
}

// ================= K7: kv reduce + decay =================
__global__ void __launch_bounds__(256) k_kvout(const float* __restrict__ pkv,
                                               float* __restrict__ out_kv)
{
    int h=blockIdx.x;
    int idx=blockIdx.y*256+threadIdx.x;
    float s=0.f;
    for (int b=0;b<NB;b++){
        size_t o = ((size_t)(b*NH+h)*8)*4096 + idx;
        float t[8];
#pragma unroll
        for (int p=0;p<8;p++) t[p] = g_kvp[o + (size_t)p*4096];
#pragma unroll
        for (int p=0;p<8;p++) s += t[p];
    }
    double gd = 1.0 - exp2(-5.0-(double)h);
    out_kv[(size_t)h*4096 + idx] = (float)gd*pkv[(size_t)h*4096 + idx] + 0.25f*s;
}

extern "C" void kernel_launch(void* const* d_in, const int* in_sizes, int n_in,
                              void* d_out, int out_size)
{
    const float* x   = (const float*)d_in[0];
    const float* pkv = (const float*)d_in[1];
    const float* Wq  = (const float*)d_in[2];
    const float* Wk  = (const float*)d_in[3];
    const float* Wv  = (const float*)d_in[4];
    const float* gnw = (const float*)d_in[5];
    const float* gnb = (const float*)d_in[6];
    float* out = (float*)d_out;

    cudaFuncSetAttribute(k_proj3, cudaFuncAttributeMaxDynamicSharedMemorySize, PROJ_SMEM);
    cudaFuncSetAttribute(k_pass1, cudaFuncAttributeMaxDynamicSharedMemorySize, P1_SMEM);
    cudaFuncSetAttribute(k_pass3, cudaFuncAttributeMaxDynamicSharedMemorySize, P3_SMEM);

    k_cvtx<<<(NX4 + NA4 + 255)/256, 256>>>(x, pkv);
    dim3 gcw(NE/64, NE/64, 3);
    k_cvtw<<<gcw, 256>>>(Wq, Wk, Wv);
    dim3 gproj(8, 64, 3);
    k_proj3<<<gproj, 256, PROJ_SMEM>>>();
    dim3 gp1(NBH, 8);
    k_pass1<<<gp1, 256, P1_SMEM>>>(pkv);
    dim3 gscan(NBH, 5);
    k_scan<<<gscan, 256>>>();
    k_pass3<<<NBH*NCHK, 256, P3_SMEM>>>();
    k_stats<<<NB, 512>>>();
    k_out<<<NB*NT, 256>>>(gnw, gnb, out);
    dim3 gkv(NH, 16);
    k_kvout<<<gkv, 256>>>(pkv, out + (size_t)NB*NT*NE);
}